// round 7
// baseline (speedup 1.0000x reference)
#include <cuda_runtime.h>
#include <cuda_bf16.h>
#include <math.h>
#include <stdint.h>

typedef unsigned long long u64;

// ---------------------------------------------------------------------------
// Output layout (tuple flattened in order)
// ---------------------------------------------------------------------------
#define OFF_OFFSETS 0
#define OFF_SIZES   524288
#define OFF_WEIGHTS 1048576
#define OFF_PREDCLS 1310720
#define OFF_SEG     1310732
#define OFF_SCORE   1572876

// Scratch (device globals; no allocation allowed)
__device__ char  g_f1qh[33554432], g_f1ql[33554432];   // feat1 int8 limbs
__device__ float g_x1f[67108864];                      // conv1 out fp32
__device__ char  g_x1qh[67108864], g_x1ql[67108864];   // conv1 out int8 limbs
__device__ float g_x2[67108864];                       // conv2 out fp32
__device__ __nv_bfloat16 g_cph[16777216], g_cpl[16777216];  // crops bf16 limbs
__device__ __nv_bfloat16 g_s1h[25165824], g_s1l[25165824];  // sc1 out bf16 limbs
__device__ float g_s2[25165824];                       // sc2 out fp32
// int8 transposed weights [cout][k9]
__device__ char g_wq1h[294912], g_wq1l[294912];
__device__ char g_wq2h[589824], g_wq2l[589824];
// bf16 transposed weights for crop convs
__device__ __nv_bfloat16 g_wsc1h[55296], g_wsc1l[55296];
__device__ __nv_bfloat16 g_wsc2h[82944], g_wsc2l[82944];
__device__ unsigned g_amax[4];   // 0:feat1 1:x1 2:wcb1 3:wcb2
__device__ int g_cls[4];

// ---------------------------------------------------------------------------
// PTX helpers (arch-generic sm_80+)
// ---------------------------------------------------------------------------
__device__ __forceinline__ uint32_t smem_u32(const void* p) {
    uint32_t a;
    asm("{ .reg .u64 t; cvta.to.shared.u64 t, %1; cvt.u32.u64 %0, t; }"
        : "=r"(a) : "l"(p));
    return a;
}
__device__ __forceinline__ void ldsm_x4(uint32_t* r, uint32_t a) {
    asm volatile("ldmatrix.sync.aligned.m8n8.x4.shared.b16 {%0,%1,%2,%3}, [%4];"
                 : "=r"(r[0]), "=r"(r[1]), "=r"(r[2]), "=r"(r[3]) : "r"(a));
}
__device__ __forceinline__ void mma_bf16(float* d, const uint32_t* a, const uint32_t* b) {
    asm volatile("mma.sync.aligned.m16n8k16.row.col.f32.bf16.bf16.f32 "
                 "{%0,%1,%2,%3}, {%4,%5,%6,%7}, {%8,%9}, {%0,%1,%2,%3};"
                 : "+f"(d[0]), "+f"(d[1]), "+f"(d[2]), "+f"(d[3])
                 : "r"(a[0]), "r"(a[1]), "r"(a[2]), "r"(a[3]),
                   "r"(b[0]), "r"(b[1]));
}
__device__ __forceinline__ void mma_s8(int* d, const uint32_t* a, const uint32_t* b) {
    asm volatile("mma.sync.aligned.m16n8k32.row.col.s32.s8.s8.s32 "
                 "{%0,%1,%2,%3}, {%4,%5,%6,%7}, {%8,%9}, {%0,%1,%2,%3};"
                 : "+r"(d[0]), "+r"(d[1]), "+r"(d[2]), "+r"(d[3])
                 : "r"(a[0]), "r"(a[1]), "r"(a[2]), "r"(a[3]),
                   "r"(b[0]), "r"(b[1]));
}
__device__ __forceinline__ void cpa16(uint32_t dst, const void* src, bool ok) {
    int sz = ok ? 16 : 0;
    asm volatile("cp.async.cg.shared.global [%0], [%1], 16, %2;"
                 :: "r"(dst), "l"(src), "r"(sz) : "memory");
}
__device__ __forceinline__ void cp_commit() {
    asm volatile("cp.async.commit_group;" ::: "memory");
}
template <int N>
__device__ __forceinline__ void cp_wait() {
    asm volatile("cp.async.wait_group %0;" :: "n"(N) : "memory");
}

__device__ __forceinline__ void bsplit(float v, __nv_bfloat16& h, __nv_bfloat16& l) {
    h = __float2bfloat16_rn(v);
    l = __float2bfloat16_rn(v - __bfloat162float(h));
}

// 15-bit two-limb int8 quantization
__device__ __forceinline__ void q15(float x, float inv, char& h, char& l) {
    int q = __float2int_rn(x * inv);
    q = max(-16383, min(16383, q));
    int hh = (q >= 0) ? ((q + 64) >> 7) : -(((-q) + 64) >> 7);
    hh = max(-127, min(127, hh));
    h = (char)hh;
    l = (char)(q - (hh << 7));
}

// ---------------------------------------------------------------------------
// Init / reduction / quantization kernels
// ---------------------------------------------------------------------------
__global__ void init_kernel(unsigned* amax) {
    if (threadIdx.x < 4) amax[threadIdx.x] = 0u;
}

__global__ void amax_kernel(const float* __restrict__ x, int n, unsigned* slot) {
    __shared__ float red[8];
    int gid = blockIdx.x * blockDim.x + threadIdx.x;
    int stride = gridDim.x * blockDim.x;
    float m = 0.f;
    for (int i = gid; i < n; i += stride) m = fmaxf(m, fabsf(x[i]));
    #pragma unroll
    for (int o = 16; o > 0; o >>= 1) m = fmaxf(m, __shfl_xor_sync(0xffffffff, m, o));
    if ((threadIdx.x & 31) == 0) red[threadIdx.x >> 5] = m;
    __syncthreads();
    if (threadIdx.x < 8) {
        m = red[threadIdx.x];
        #pragma unroll
        for (int o = 4; o > 0; o >>= 1) m = fmaxf(m, __shfl_xor_sync(0xff, m, o));
        if (threadIdx.x == 0) atomicMax(slot, __float_as_uint(m));
    }
}

// fp32 -> int8 limbs (elementwise, 4-wide)
__global__ void fquant_kernel(const float* __restrict__ src, int n,
                              const unsigned* slot,
                              char* __restrict__ h, char* __restrict__ l) {
    int i = blockIdx.x * blockDim.x + threadIdx.x;
    if (i * 4 >= n) return;
    float amax = __uint_as_float(slot[0]);
    float inv = amax > 0.f ? 16383.f / amax : 0.f;
    float4 v = *(const float4*)(src + i * 4);
    char h0, h1, h2, h3, l0, l1, l2, l3;
    q15(v.x, inv, h0, l0); q15(v.y, inv, h1, l1);
    q15(v.z, inv, h2, l2); q15(v.w, inv, h3, l3);
    *(char4*)(h + i * 4) = make_char4(h0, h1, h2, h3);
    *(char4*)(l + i * 4) = make_char4(l0, l1, l2, l3);
}

// weights [K9][COUT] fp32 -> [cout][k9] int8 limbs
__global__ void wquant_kernel(const float* __restrict__ w, int K9, int COUT,
                              const unsigned* slot,
                              char* __restrict__ h, char* __restrict__ l) {
    int i = blockIdx.x * blockDim.x + threadIdx.x;
    if (i >= K9 * COUT) return;
    float amax = __uint_as_float(slot[0]);
    float inv = amax > 0.f ? 16383.f / amax : 0.f;
    int k = i / COUT, c = i % COUT;
    char hb, lb;
    q15(w[i], inv, hb, lb);
    h[(size_t)c * K9 + k] = hb;
    l[(size_t)c * K9 + k] = lb;
}

// weights [K9][COUT] fp32 -> [cout][k9] bf16 limbs (crop convs)
__global__ void wprep_kernel(const float* __restrict__ w,
                             __nv_bfloat16* __restrict__ h,
                             __nv_bfloat16* __restrict__ l, int K9, int COUT) {
    int i = blockIdx.x * blockDim.x + threadIdx.x;
    if (i >= K9 * COUT) return;
    int k = i / COUT, c = i % COUT;
    __nv_bfloat16 hb, lb;
    bsplit(w[i], hb, lb);
    h[(size_t)c * K9 + k] = hb;
    l[(size_t)c * K9 + k] = lb;
}

// ---------------------------------------------------------------------------
// INT8 tensor-core 3x3 conv (2-limb, 3 terms). CTA: 128 thr (2M x 2N warps).
// Tile M=128px (8y x 16x) x N=64 couts. K chunks of 32 ch (one k32 MMA step).
// smem pitch 48B (conflict-free ldmatrix). Double buffered cp.async.
// grid: (W/16, H/8, nimg * NT)
// ---------------------------------------------------------------------------
#define ASZ8 6144     // 128 * 48
#define BSZ8 3072     // 64 * 48
#define BUF8 18432    // 2*ASZ8 + 2*BSZ8

template <int CIN, bool DO_AMAX>
__global__ __launch_bounds__(128, 2)
void conv3x3_s8(const char* __restrict__ inh, const char* __restrict__ inl,
                const char* __restrict__ wth, const char* __restrict__ wtl,
                const float* __restrict__ bias,
                const unsigned* __restrict__ sA, const unsigned* __restrict__ sB,
                float* __restrict__ outf, unsigned* amax_out,
                int H, int W, int COUT, int NT) {
    constexpr int K9 = 9 * CIN;
    __shared__ __align__(16) char smbuf[2 * BUF8];
    __shared__ float sbias[64];
    const uint32_t sb = smem_u32(smbuf);

    int t = threadIdx.x, warp = t >> 5, lane = t & 31;
    int img = blockIdx.z / NT, ntile = blockIdx.z % NT;
    int cobase = ntile * 64;
    int x0 = blockIdx.x * 16, y0 = blockIdx.y * 8;

    if (t < 64) sbias[t] = bias[cobase + t];
    float sAB = (__uint_as_float(sA[0]) / 16383.f) * (__uint_as_float(sB[0]) / 16383.f);

    int lpy = t >> 4, lpx = t & 15;
    bool bok = t < 64;
    int wm = warp & 1, nw = warp >> 1;
    int nbase = nw * 32;

    int acc2[4][4][4], acc1[4][4][4];
    #pragma unroll
    for (int i = 0; i < 4; i++)
        #pragma unroll
        for (int j = 0; j < 4; j++)
            #pragma unroll
            for (int q = 0; q < 4; q++) { acc2[i][j][q] = 0; acc1[i][j][q] = 0; }

    const char* imgh = inh + (size_t)img * H * W * CIN;
    const char* imgl = inl + (size_t)img * H * W * CIN;
    const int KCH = K9 / 32;

    auto issue = [&](int kc, int buf) {
        int kbase = kc * 32;
        int tap = kbase / CIN;
        int dy = tap / 3 - 1, dx = tap % 3 - 1;
        int gy = y0 + lpy + dy, gx = x0 + lpx + dx;
        bool aok = (gy >= 0 && gy < H && gx >= 0 && gx < W);
        int cy = min(max(gy, 0), H - 1), cx = min(max(gx, 0), W - 1);
        size_t ab = ((size_t)cy * W + cx) * CIN + (kbase % CIN);
        uint32_t AhiO = sb + buf * BUF8;
        uint32_t AloO = AhiO + ASZ8;
        uint32_t BhiO = AhiO + 2 * ASZ8;
        uint32_t BloO = BhiO + BSZ8;
        uint32_t arow = t * 48;
        cpa16(AhiO + arow,      imgh + ab,      aok);
        cpa16(AhiO + arow + 16, imgh + ab + 16, aok);
        cpa16(AloO + arow,      imgl + ab,      aok);
        cpa16(AloO + arow + 16, imgl + ab + 16, aok);
        if (bok) {
            size_t bb = (size_t)(cobase + t) * K9 + kbase;
            cpa16(BhiO + arow,      wth + bb,      true);
            cpa16(BhiO + arow + 16, wth + bb + 16, true);
            cpa16(BloO + arow,      wtl + bb,      true);
            cpa16(BloO + arow + 16, wtl + bb + 16, true);
        }
        cp_commit();
    };

    issue(0, 0);

    for (int kc = 0; kc < KCH; kc++) {
        int buf = kc & 1;
        if (kc + 1 < KCH) { issue(kc + 1, buf ^ 1); cp_wait<1>(); }
        else              { cp_wait<0>(); }
        __syncthreads();

        uint32_t AhiO = sb + buf * BUF8;
        uint32_t AloO = AhiO + ASZ8;
        uint32_t BhiO = AhiO + 2 * ASZ8;
        uint32_t BloO = BhiO + BSZ8;

        uint32_t ah[4][4], al[4][4];
        #pragma unroll
        for (int mi = 0; mi < 4; mi++) {
            uint32_t rowb = (uint32_t)((wm * 64 + mi * 16 + (lane & 15)) * 48
                                       + (lane >> 4) * 16);
            ldsm_x4(ah[mi], AhiO + rowb);
            ldsm_x4(al[mi], AloO + rowb);
        }
        uint32_t bh[4][2], bl[4][2];
        #pragma unroll
        for (int p = 0; p < 2; p++) {
            uint32_t addr = (uint32_t)((nbase + p * 16 + ((lane >> 4) << 3) + (lane & 7)) * 48
                                       + ((lane >> 3) & 1) * 16);
            uint32_t r4[4];
            ldsm_x4(r4, BhiO + addr);
            bh[2 * p][0] = r4[0]; bh[2 * p][1] = r4[1];
            bh[2 * p + 1][0] = r4[2]; bh[2 * p + 1][1] = r4[3];
            ldsm_x4(r4, BloO + addr);
            bl[2 * p][0] = r4[0]; bl[2 * p][1] = r4[1];
            bl[2 * p + 1][0] = r4[2]; bl[2 * p + 1][1] = r4[3];
        }
        #pragma unroll
        for (int mi = 0; mi < 4; mi++)
            #pragma unroll
            for (int ni = 0; ni < 4; ni++) {
                mma_s8(acc2[mi][ni], ah[mi], bh[ni]);
                mma_s8(acc1[mi][ni], ah[mi], bl[ni]);
                mma_s8(acc1[mi][ni], al[mi], bh[ni]);
            }
        __syncthreads();
    }

    // ---- epilogue: combine limbs, bias, relu, write fp32, optional amax ----
    float lmax = 0.f;
    #pragma unroll
    for (int mi = 0; mi < 4; mi++) {
        int p0 = wm * 64 + mi * 16 + (lane >> 2);
        #pragma unroll
        for (int half = 0; half < 2; half++) {
            int p = p0 + half * 8;
            int gy = y0 + (p >> 4), gx = x0 + (p & 15);
            size_t pixoff = ((size_t)img * H * W + (size_t)gy * W + gx) * COUT + cobase;
            #pragma unroll
            for (int ni = 0; ni < 4; ni++) {
                int cl = nbase + ni * 8 + (lane & 3) * 2;
                float r0 = ((float)acc2[mi][ni][half * 2 + 0] * 16384.f
                            + (float)acc1[mi][ni][half * 2 + 0] * 128.f) * sAB + sbias[cl];
                float r1 = ((float)acc2[mi][ni][half * 2 + 1] * 16384.f
                            + (float)acc1[mi][ni][half * 2 + 1] * 128.f) * sAB + sbias[cl + 1];
                r0 = fmaxf(r0, 0.f); r1 = fmaxf(r1, 0.f);
                *(float2*)(outf + pixoff + cl) = make_float2(r0, r1);
                if (DO_AMAX) lmax = fmaxf(lmax, fmaxf(r0, r1));
            }
        }
    }
    if (DO_AMAX) {
        #pragma unroll
        for (int o = 16; o > 0; o >>= 1)
            lmax = fmaxf(lmax, __shfl_xor_sync(0xffffffff, lmax, o));
        if (lane == 0) atomicMax(amax_out, __float_as_uint(lmax));
    }
}

// ---------------------------------------------------------------------------
// bf16 tensor-core conv (crop convs) — proven R6 path
// ---------------------------------------------------------------------------
#define CONV_ASZ 10240

template <int CIN, int COUT_TILE, bool RELU, bool OUT_SPLIT, int MAXB>
__global__ __launch_bounds__(128, MAXB)
void conv3x3_cp(const __nv_bfloat16* __restrict__ inh,
                const __nv_bfloat16* __restrict__ inl,
                const __nv_bfloat16* __restrict__ wth,
                const __nv_bfloat16* __restrict__ wtl,
                const float* __restrict__ bias,
                float* __restrict__ outf,
                __nv_bfloat16* __restrict__ outh,
                __nv_bfloat16* __restrict__ outl,
                int H, int W, int COUT, int NT) {
    constexpr int K9 = 9 * CIN;
    constexpr int BSZ = COUT_TILE * 80;
    constexpr int BUFSZ = 2 * CONV_ASZ + 2 * BSZ;
    extern __shared__ char sm[];
    const uint32_t sb = smem_u32(sm);
    __shared__ float sbias[COUT_TILE];

    int t = threadIdx.x, warp = t >> 5, lane = t & 31;
    int img = blockIdx.z / NT, ntile = blockIdx.z % NT;
    int cobase = ntile * COUT_TILE;
    int x0 = blockIdx.x * 16, y0 = blockIdx.y * 8;

    if (t < COUT_TILE) sbias[t] = bias[cobase + t];

    int lpy = t >> 4, lpx = t & 15;
    bool bok = t < COUT_TILE;

    constexpr int NF = COUT_TILE / 16;
    int wm = warp & 1, nw = warp >> 1;
    int nbase = nw * (COUT_TILE / 2);

    float acc[4][NF][4];
    #pragma unroll
    for (int i = 0; i < 4; i++)
        #pragma unroll
        for (int j = 0; j < NF; j++)
            #pragma unroll
            for (int q = 0; q < 4; q++) acc[i][j][q] = 0.f;

    const __nv_bfloat16* imgh = inh + (size_t)img * H * W * CIN;
    const __nv_bfloat16* imgl = inl + (size_t)img * H * W * CIN;
    const int KCH = K9 / 32;

    auto issue = [&](int kc, int buf) {
        int kbase = kc * 32;
        int tap = kbase / CIN;
        int dy = tap / 3 - 1, dx = tap % 3 - 1;
        int gy = y0 + lpy + dy, gx = x0 + lpx + dx;
        bool aok = (gy >= 0 && gy < H && gx >= 0 && gx < W);
        int cy = min(max(gy, 0), H - 1), cx = min(max(gx, 0), W - 1);
        size_t ab = ((size_t)cy * W + cx) * CIN + (kbase % CIN);
        uint32_t AhiO = sb + buf * BUFSZ;
        uint32_t AloO = AhiO + CONV_ASZ;
        uint32_t BhiO = AhiO + 2 * CONV_ASZ;
        uint32_t BloO = BhiO + BSZ;
        uint32_t arow = t * 80;
        #pragma unroll
        for (int j = 0; j < 4; j++) {
            cpa16(AhiO + arow + j * 16, imgh + ab + j * 8, aok);
            cpa16(AloO + arow + j * 16, imgl + ab + j * 8, aok);
        }
        if (bok) {
            size_t bb = (size_t)(cobase + t) * K9 + kbase;
            #pragma unroll
            for (int j = 0; j < 4; j++) {
                cpa16(BhiO + arow + j * 16, wth + bb + j * 8, true);
                cpa16(BloO + arow + j * 16, wtl + bb + j * 8, true);
            }
        }
        cp_commit();
    };

    issue(0, 0);

    for (int kc = 0; kc < KCH; kc++) {
        int buf = kc & 1;
        if (kc + 1 < KCH) { issue(kc + 1, buf ^ 1); cp_wait<1>(); }
        else              { cp_wait<0>(); }
        __syncthreads();

        uint32_t AhiO = sb + buf * BUFSZ;
        uint32_t AloO = AhiO + CONV_ASZ;
        uint32_t BhiO = AhiO + 2 * CONV_ASZ;
        uint32_t BloO = BhiO + BSZ;

        #pragma unroll
        for (int k16 = 0; k16 < 2; k16++) {
            uint32_t ah[4][4], al[4][4];
            #pragma unroll
            for (int mi = 0; mi < 4; mi++) {
                uint32_t rowb = (uint32_t)((wm * 64 + mi * 16 + (lane & 15)) * 80
                                           + (k16 * 16 + (lane >> 4) * 8) * 2);
                ldsm_x4(ah[mi], AhiO + rowb);
                ldsm_x4(al[mi], AloO + rowb);
            }
            uint32_t bh[NF][2], bl[NF][2];
            #pragma unroll
            for (int p = 0; p < NF / 2; p++) {
                uint32_t addr = (uint32_t)((nbase + p * 16 + ((lane >> 4) << 3) + (lane & 7)) * 80
                                           + (k16 * 16 + ((lane >> 3) & 1) * 8) * 2);
                uint32_t r4[4];
                ldsm_x4(r4, BhiO + addr);
                bh[2 * p][0] = r4[0]; bh[2 * p][1] = r4[1];
                bh[2 * p + 1][0] = r4[2]; bh[2 * p + 1][1] = r4[3];
                ldsm_x4(r4, BloO + addr);
                bl[2 * p][0] = r4[0]; bl[2 * p][1] = r4[1];
                bl[2 * p + 1][0] = r4[2]; bl[2 * p + 1][1] = r4[3];
            }
            #pragma unroll
            for (int mi = 0; mi < 4; mi++)
                #pragma unroll
                for (int ni = 0; ni < NF; ni++) {
                    mma_bf16(acc[mi][ni], ah[mi], bh[ni]);
                    mma_bf16(acc[mi][ni], ah[mi], bl[ni]);
                    mma_bf16(acc[mi][ni], al[mi], bh[ni]);
                }
        }
        __syncthreads();
    }

    #pragma unroll
    for (int mi = 0; mi < 4; mi++) {
        int p0 = wm * 64 + mi * 16 + (lane >> 2);
        #pragma unroll
        for (int half = 0; half < 2; half++) {
            int p = p0 + half * 8;
            int gy = y0 + (p >> 4), gx = x0 + (p & 15);
            size_t pixoff = ((size_t)img * H * W + (size_t)gy * W + gx) * COUT + cobase;
            #pragma unroll
            for (int ni = 0; ni < NF; ni++) {
                int cl = nbase + ni * 8 + (lane & 3) * 2;
                float r0 = acc[mi][ni][half * 2 + 0] + sbias[cl];
                float r1 = acc[mi][ni][half * 2 + 1] + sbias[cl + 1];
                if (RELU) { r0 = fmaxf(r0, 0.f); r1 = fmaxf(r1, 0.f); }
                if (OUT_SPLIT) {
                    __nv_bfloat16 h0, h1, l0, l1;
                    bsplit(r0, h0, l0); bsplit(r1, h1, l1);
                    __nv_bfloat162 hh; hh.x = h0; hh.y = h1;
                    __nv_bfloat162 ll; ll.x = l0; ll.y = l1;
                    *(uint32_t*)(outh + pixoff + cl) = *(uint32_t*)&hh;
                    *(uint32_t*)(outl + pixoff + cl) = *(uint32_t*)&ll;
                } else {
                    *(float2*)(outf + pixoff + cl) = make_float2(r0, r1);
                }
            }
        }
    }
}

// ---------------------------------------------------------------------------
// Classification head
// ---------------------------------------------------------------------------
__global__ void cls_kernel(const float* __restrict__ feat5,
                           const float* __restrict__ fc1_w, const float* __restrict__ fc1_b,
                           const float* __restrict__ fc2_w, const float* __restrict__ fc2_b,
                           const float* __restrict__ fc3_w, const float* __restrict__ fc3_b,
                           float* __restrict__ out_predcls, int* __restrict__ cls) {
    int b = blockIdx.x;
    int t = threadIdx.x;
    __shared__ float g0[256], g1[256], lg[3];
    const float* f = feat5 + (size_t)b * 16 * 16 * 256;
    float s = 0.f;
    #pragma unroll 4
    for (int p = 0; p < 256; p++) s += f[p * 256 + t];
    g0[t] = s * (1.0f / 256.0f);
    __syncthreads();
    float a = fc1_b[t];
    #pragma unroll 4
    for (int k = 0; k < 256; k++) a = fmaf(g0[k], fc1_w[k * 256 + t], a);
    g1[t] = fmaxf(a, 0.f);
    __syncthreads();
    a = fc2_b[t];
    #pragma unroll 4
    for (int k = 0; k < 256; k++) a = fmaf(g1[k], fc2_w[k * 256 + t], a);
    g0[t] = fmaxf(a, 0.f);
    __syncthreads();
    if (t < 3) {
        a = fc3_b[t];
        for (int k = 0; k < 256; k++) a = fmaf(g0[k], fc3_w[k * 3 + t], a);
        lg[t] = a;
    }
    __syncthreads();
    if (t == 0) {
        float m = fmaxf(lg[0], fmaxf(lg[1], lg[2]));
        float e0 = expf(lg[0] - m), e1 = expf(lg[1] - m), e2 = expf(lg[2] - m);
        float inv = 1.f / (e0 + e1 + e2);
        out_predcls[b * 3 + 0] = e0 * inv;
        out_predcls[b * 3 + 1] = e1 * inv;
        out_predcls[b * 3 + 2] = e2 * inv;
        int c = 0;
        if (lg[1] > lg[0]) c = 1;
        if (lg[2] > lg[c]) c = 2;
        cls[b] = c;
    }
}

// ---------------------------------------------------------------------------
// Fused reg/wt conv with class selection
// ---------------------------------------------------------------------------
__global__ void regsel_kernel(const float* __restrict__ x,
                              const float* __restrict__ reg_w, const float* __restrict__ reg_b,
                              const float* __restrict__ wt_w,  const float* __restrict__ wt_b,
                              const int* __restrict__ cls, float* __restrict__ out) {
    int b = blockIdx.z;
    int c = cls[b];
    __shared__ __align__(16) float ws[9 * 256 * 5];
    int t = threadIdx.x;
    for (int i = t; i < 9 * 256; i += 256) {
        const float* rp = reg_w + (size_t)i * 12 + 4 * c;
        float* wp = ws + i * 5;
        wp[0] = rp[0]; wp[1] = rp[1]; wp[2] = rp[2]; wp[3] = rp[3];
        wp[4] = wt_w[(size_t)i * 3 + c];
    }
    __syncthreads();
    int px = blockIdx.x * 16 + (t & 15);
    int py = blockIdx.y * 16 + (t >> 4);
    float a0 = reg_b[4 * c], a1 = reg_b[4 * c + 1], a2 = reg_b[4 * c + 2],
          a3 = reg_b[4 * c + 3], a4 = wt_b[c];
    const float* xi = x + (size_t)b * 256 * 256 * 256;
    for (int tap = 0; tap < 9; tap++) {
        int yy = py + tap / 3 - 1, xx = px + tap % 3 - 1;
        if (yy < 0 || yy >= 256 || xx < 0 || xx >= 256) continue;
        const float* ip = xi + ((size_t)yy * 256 + xx) * 256;
        const float* wp = ws + tap * 256 * 5;
        #pragma unroll 2
        for (int ci = 0; ci < 256; ci += 4) {
            float4 v = *(const float4*)(ip + ci);
            float wl[20];
            const float4* w4 = (const float4*)(wp + ci * 5);
            #pragma unroll
            for (int q = 0; q < 5; q++) ((float4*)wl)[q] = w4[q];
            a0 = fmaf(v.x, wl[0], a0);  a1 = fmaf(v.x, wl[1], a1);
            a2 = fmaf(v.x, wl[2], a2);  a3 = fmaf(v.x, wl[3], a3);  a4 = fmaf(v.x, wl[4], a4);
            a0 = fmaf(v.y, wl[5], a0);  a1 = fmaf(v.y, wl[6], a1);
            a2 = fmaf(v.y, wl[7], a2);  a3 = fmaf(v.y, wl[8], a3);  a4 = fmaf(v.y, wl[9], a4);
            a0 = fmaf(v.z, wl[10], a0); a1 = fmaf(v.z, wl[11], a1);
            a2 = fmaf(v.z, wl[12], a2); a3 = fmaf(v.z, wl[13], a3); a4 = fmaf(v.z, wl[14], a4);
            a0 = fmaf(v.w, wl[15], a0); a1 = fmaf(v.w, wl[16], a1);
            a2 = fmaf(v.w, wl[17], a2); a3 = fmaf(v.w, wl[18], a3); a4 = fmaf(v.w, wl[19], a4);
        }
    }
    size_t pix = ((size_t)b * 256 + py) * 256 + px;
    out[OFF_OFFSETS + pix * 2 + 0] = a0;
    out[OFF_OFFSETS + pix * 2 + 1] = a1;
    out[OFF_SIZES   + pix * 2 + 0] = a2;
    out[OFF_SIZES   + pix * 2 + 1] = a3;
    out[OFF_WEIGHTS + pix] = a4;
}

// ---------------------------------------------------------------------------
// Bilinear crop -> bf16 limbs
// ---------------------------------------------------------------------------
__global__ void crop_kernel(const float* __restrict__ feat0,
                            const float* __restrict__ boxes,
                            __nv_bfloat16* __restrict__ ch,
                            __nv_bfloat16* __restrict__ cl) {
    int n = blockIdx.x;
    int b = n >> 6;
    const int H = 512, W = 512, C = 64;
    __shared__ int sy0[32], sx0[32];
    __shared__ float swy[32], swx[32];
    const float* bx = boxes + (size_t)n * 4;
    float y1 = bx[0], x1 = bx[1], y2 = bx[2], x2 = bx[3];
    int t = threadIdx.x;
    if (t < 32) {
        float tt = (float)t / 31.0f;
        float ys = y1 * (H - 1) + tt * (y2 - y1) * (H - 1);
        int yy0 = (int)floorf(ys);
        yy0 = min(max(yy0, 0), H - 2);
        sy0[t] = yy0; swy[t] = ys - (float)yy0;
    } else if (t < 64) {
        int i = t - 32;
        float tt = (float)i / 31.0f;
        float xs = x1 * (W - 1) + tt * (x2 - x1) * (W - 1);
        int xx0 = (int)floorf(xs);
        xx0 = min(max(xx0, 0), W - 2);
        sx0[i] = xx0; swx[i] = xs - (float)xx0;
    }
    __syncthreads();
    const float* f = feat0 + (size_t)b * H * W * C;
    size_t obase = (size_t)n * 32 * 32 * C;
    for (int idx = t; idx < 32 * 32 * C; idx += blockDim.x) {
        int c  = idx & 63;
        int ix = (idx >> 6) & 31;
        int iy = idx >> 11;
        int yy0 = sy0[iy], xx0 = sx0[ix];
        float wy = swy[iy], wx = swx[ix];
        const float* p00 = f + ((size_t)yy0 * W + xx0) * C + c;
        float v00 = p00[0], v01 = p00[C], v10 = p00[(size_t)W * C], v11 = p00[(size_t)W * C + C];
        float top = v00 * (1.f - wx) + v01 * wx;
        float bot = v10 * (1.f - wx) + v11 * wx;
        float v = top * (1.f - wy) + bot * wy;
        __nv_bfloat16 hb, lb;
        bsplit(v, hb, lb);
        ch[obase + idx] = hb;
        cl[obase + idx] = lb;
    }
}

// ---------------------------------------------------------------------------
// so conv with class selection
// ---------------------------------------------------------------------------
__global__ void sosel_kernel(const float* __restrict__ s2,
                             const float* __restrict__ so_w, const float* __restrict__ so_b,
                             const int* __restrict__ cls, float* __restrict__ out) {
    int n = blockIdx.x;
    int c = cls[n >> 6];
    __shared__ __align__(16) float ws[9 * 96];
    int t = threadIdx.x;
    for (int i = t; i < 864; i += 256) ws[i] = so_w[(size_t)i * 3 + c];
    __syncthreads();
    float bias = so_b[c];
    const float* sp = s2 + (size_t)n * 32 * 32 * 96;
    for (int pix = t; pix < 1024; pix += 256) {
        int py = pix >> 5, px = pix & 31;
        float acc = bias;
        for (int tap = 0; tap < 9; tap++) {
            int yy = py + tap / 3 - 1, xx = px + tap % 3 - 1;
            if (yy < 0 || yy >= 32 || xx < 0 || xx >= 32) continue;
            const float* ip = sp + ((size_t)yy * 32 + xx) * 96;
            const float* wp = ws + tap * 96;
            #pragma unroll 4
            for (int ci = 0; ci < 96; ci += 4) {
                float4 v = *(const float4*)(ip + ci);
                float4 w = *(const float4*)(wp + ci);
                acc = fmaf(v.x, w.x, acc);
                acc = fmaf(v.y, w.y, acc);
                acc = fmaf(v.z, w.z, acc);
                acc = fmaf(v.w, w.w, acc);
            }
        }
        out[OFF_SEG + (size_t)n * 1024 + pix] = acc;
    }
}

// ---------------------------------------------------------------------------
// Score head
// ---------------------------------------------------------------------------
__global__ void score_kernel(const float* __restrict__ s2,
                             const float* __restrict__ sd1_w, const float* __restrict__ sd1_b,
                             const float* __restrict__ sd2_w, const float* __restrict__ sd2_b,
                             const float* __restrict__ sd3_w, const float* __restrict__ sd3_b,
                             const int* __restrict__ cls, float* __restrict__ out) {
    int n = blockIdx.x;
    int t = threadIdx.x;
    __shared__ float pooled[6144];
    __shared__ float h1[256], h2[256];
    const float* sp = s2 + (size_t)n * 32 * 32 * 96;
    for (int o = t; o < 6144; o += 256) {
        int c  = o % 96;
        int px = (o / 96) & 7;
        int py = o / 768;
        float s = 0.f;
        #pragma unroll
        for (int i = 0; i < 4; i++)
            #pragma unroll
            for (int j = 0; j < 4; j++)
                s += sp[(((size_t)(py * 4 + i)) * 32 + (px * 4 + j)) * 96 + c];
        pooled[o] = s * (1.f / 16.f);
    }
    __syncthreads();
    float a = sd1_b[t];
    #pragma unroll 4
    for (int k = 0; k < 6144; k++) a = fmaf(pooled[k], sd1_w[(size_t)k * 256 + t], a);
    h1[t] = fmaxf(a, 0.f);
    __syncthreads();
    a = sd2_b[t];
    #pragma unroll 4
    for (int k = 0; k < 256; k++) a = fmaf(h1[k], sd2_w[k * 256 + t], a);
    h2[t] = fmaxf(a, 0.f);
    __syncthreads();
    if (t == 0) {
        int c = cls[n >> 6];
        float acc = sd3_b[c];
        for (int k = 0; k < 256; k++) acc = fmaf(h2[k], sd3_w[k * 3 + c], acc);
        out[OFF_SCORE + n] = acc;
    }
}

// ---------------------------------------------------------------------------
extern "C" void kernel_launch(void* const* d_in, const int* in_sizes, int n_in,
                              void* d_out, int out_size) {
    (void)in_sizes; (void)n_in; (void)out_size;
    const float* feat0 = (const float*)d_in[0];
    const float* feat1 = (const float*)d_in[1];
    const float* feat5 = (const float*)d_in[2];
    const float* boxes = (const float*)d_in[3];
    const float* cb1_w = (const float*)d_in[4];
    const float* cb1_b = (const float*)d_in[5];
    const float* cb2_w = (const float*)d_in[6];
    const float* cb2_b = (const float*)d_in[7];
    const float* reg_w = (const float*)d_in[8];
    const float* reg_b = (const float*)d_in[9];
    const float* wt_w  = (const float*)d_in[10];
    const float* wt_b  = (const float*)d_in[11];
    const float* fc1_w = (const float*)d_in[12];
    const float* fc1_b = (const float*)d_in[13];
    const float* fc2_w = (const float*)d_in[14];
    const float* fc2_b = (const float*)d_in[15];
    const float* fc3_w = (const float*)d_in[16];
    const float* fc3_b = (const float*)d_in[17];
    const float* sc1_w = (const float*)d_in[18];
    const float* sc1_b = (const float*)d_in[19];
    const float* sc2_w = (const float*)d_in[20];
    const float* sc2_b = (const float*)d_in[21];
    const float* so_w  = (const float*)d_in[22];
    const float* so_b  = (const float*)d_in[23];
    const float* sd1_w = (const float*)d_in[24];
    const float* sd1_b = (const float*)d_in[25];
    const float* sd2_w = (const float*)d_in[26];
    const float* sd2_b = (const float*)d_in[27];
    const float* sd3_w = (const float*)d_in[28];
    const float* sd3_b = (const float*)d_in[29];
    float* out = (float*)d_out;

    // resolve device globals
    void *p;
    cudaGetSymbolAddress(&p, g_f1qh);  char* f1qh = (char*)p;
    cudaGetSymbolAddress(&p, g_f1ql);  char* f1ql = (char*)p;
    cudaGetSymbolAddress(&p, g_x1f);   float* x1f = (float*)p;
    cudaGetSymbolAddress(&p, g_x1qh);  char* x1qh = (char*)p;
    cudaGetSymbolAddress(&p, g_x1ql);  char* x1ql = (char*)p;
    cudaGetSymbolAddress(&p, g_x2);    float* x2 = (float*)p;
    cudaGetSymbolAddress(&p, g_cph);   __nv_bfloat16* cph = (__nv_bfloat16*)p;
    cudaGetSymbolAddress(&p, g_cpl);   __nv_bfloat16* cpl = (__nv_bfloat16*)p;
    cudaGetSymbolAddress(&p, g_s1h);   __nv_bfloat16* s1h = (__nv_bfloat16*)p;
    cudaGetSymbolAddress(&p, g_s1l);   __nv_bfloat16* s1l = (__nv_bfloat16*)p;
    cudaGetSymbolAddress(&p, g_s2);    float* s2 = (float*)p;
    cudaGetSymbolAddress(&p, g_wq1h);  char* wq1h = (char*)p;
    cudaGetSymbolAddress(&p, g_wq1l);  char* wq1l = (char*)p;
    cudaGetSymbolAddress(&p, g_wq2h);  char* wq2h = (char*)p;
    cudaGetSymbolAddress(&p, g_wq2l);  char* wq2l = (char*)p;
    cudaGetSymbolAddress(&p, g_wsc1h); __nv_bfloat16* w3h = (__nv_bfloat16*)p;
    cudaGetSymbolAddress(&p, g_wsc1l); __nv_bfloat16* w3l = (__nv_bfloat16*)p;
    cudaGetSymbolAddress(&p, g_wsc2h); __nv_bfloat16* w4h = (__nv_bfloat16*)p;
    cudaGetSymbolAddress(&p, g_wsc2l); __nv_bfloat16* w4l = (__nv_bfloat16*)p;
    cudaGetSymbolAddress(&p, g_amax);  unsigned* amax = (unsigned*)p;
    cudaGetSymbolAddress(&p, g_cls);   int* cls = (int*)p;

    constexpr int DYN96 = 2 * (2 * CONV_ASZ + 2 * 96 * 80);
    cudaFuncSetAttribute(conv3x3_cp<64, 96, true, true, 3>,
                         cudaFuncAttributeMaxDynamicSharedMemorySize, DYN96);
    cudaFuncSetAttribute(conv3x3_cp<96, 96, true, false, 3>,
                         cudaFuncAttributeMaxDynamicSharedMemorySize, DYN96);

    // reset per-call state (graph replays)
    init_kernel<<<1, 32>>>(amax);

    // classification first (selection depends on cls)
    cls_kernel<<<4, 256>>>(feat5, fc1_w, fc1_b, fc2_w, fc2_b, fc3_w, fc3_b,
                           out + OFF_PREDCLS, cls);

    // scales + quantization for the big convs
    amax_kernel<<<1024, 256>>>(feat1, 33554432, amax + 0);
    amax_kernel<<<128, 256>>>(cb1_w, 294912, amax + 2);
    amax_kernel<<<128, 256>>>(cb2_w, 589824, amax + 3);
    wquant_kernel<<<(294912 + 255) / 256, 256>>>(cb1_w, 1152, 256, amax + 2, wq1h, wq1l);
    wquant_kernel<<<(589824 + 255) / 256, 256>>>(cb2_w, 2304, 256, amax + 3, wq2h, wq2l);
    fquant_kernel<<<(33554432 / 4 + 255) / 256, 256>>>(feat1, 33554432, amax + 0, f1qh, f1ql);

    // crop + segmentation branch (bf16 path)
    wprep_kernel<<<(576 * 96 + 255) / 256, 256>>>(sc1_w, w3h, w3l, 576, 96);
    wprep_kernel<<<(864 * 96 + 255) / 256, 256>>>(sc2_w, w4h, w4l, 864, 96);
    crop_kernel<<<256, 256>>>(feat0, boxes, cph, cpl);
    conv3x3_cp<64, 96, true, true, 3><<<dim3(2, 4, 256), 128, DYN96>>>(
        cph, cpl, w3h, w3l, sc1_b, nullptr, s1h, s1l, 32, 32, 96, 1);
    conv3x3_cp<96, 96, true, false, 3><<<dim3(2, 4, 256), 128, DYN96>>>(
        s1h, s1l, w4h, w4l, sc2_b, s2, nullptr, nullptr, 32, 32, 96, 1);
    sosel_kernel<<<256, 256>>>(s2, so_w, so_b, cls, out);
    score_kernel<<<256, 256>>>(s2, sd1_w, sd1_b, sd2_w, sd2_b, sd3_w, sd3_b, cls, out);

    // regression branch (int8 tensor path)
    conv3x3_s8<128, true><<<dim3(16, 32, 16), 128>>>(
        f1qh, f1ql, wq1h, wq1l, cb1_b, amax + 0, amax + 2,
        x1f, amax + 1, 256, 256, 256, 4);
    fquant_kernel<<<(67108864 / 4 + 255) / 256, 256>>>(x1f, 67108864, amax + 1, x1qh, x1ql);
    conv3x3_s8<256, false><<<dim3(16, 32, 16), 128>>>(
        x1qh, x1ql, wq2h, wq2l, cb2_b, amax + 1, amax + 3,
        x2, nullptr, 256, 256, 256, 4);
    regsel_kernel<<<dim3(16, 16, 4), 256>>>(x2, reg_w, reg_b, wt_w, wt_b, cls, out);
}

// round 8
// speedup vs baseline: 2.0204x; 2.0204x over previous
#include <cuda_runtime.h>
#include <cuda_fp16.h>
#include <math.h>
#include <stdint.h>

typedef unsigned long long u64;

// ---------------------------------------------------------------------------
// Output layout (tuple flattened in order)
// ---------------------------------------------------------------------------
#define OFF_OFFSETS 0
#define OFF_SIZES   524288
#define OFF_WEIGHTS 1048576
#define OFF_PREDCLS 1310720
#define OFF_SEG     1310732
#define OFF_SCORE   1572876

// Scratch (device globals; no allocation allowed)
__device__ __half g_f1h[33554432], g_f1l[33554432];   // feat1 fp16 limbs
__device__ __half g_x1h[67108864], g_x1l[67108864];   // conv1 out fp16 limbs
__device__ float  g_x2[67108864];                     // conv2 out fp32
__device__ __half g_cph[16777216], g_cpl[16777216];   // crops fp16 limbs
__device__ __half g_s1h[25165824], g_s1l[25165824];   // sc1 out fp16 limbs
__device__ float  g_s2[25165824];                     // sc2 out fp32
// transposed fp16 weights [cout][k9]
__device__ __half g_w1[294912];
__device__ __half g_w2[589824];
__device__ __half g_w3[55296];
__device__ __half g_w4[82944];
__device__ int g_cls[4];

// ---------------------------------------------------------------------------
// PTX helpers (arch-generic sm_80+)
// ---------------------------------------------------------------------------
__device__ __forceinline__ uint32_t smem_u32(const void* p) {
    uint32_t a;
    asm("{ .reg .u64 t; cvta.to.shared.u64 t, %1; cvt.u32.u64 %0, t; }"
        : "=r"(a) : "l"(p));
    return a;
}
__device__ __forceinline__ void ldsm_x4(uint32_t* r, uint32_t a) {
    asm volatile("ldmatrix.sync.aligned.m8n8.x4.shared.b16 {%0,%1,%2,%3}, [%4];"
                 : "=r"(r[0]), "=r"(r[1]), "=r"(r[2]), "=r"(r[3]) : "r"(a));
}
__device__ __forceinline__ void mma_f16(float* d, const uint32_t* a, const uint32_t* b) {
    asm volatile("mma.sync.aligned.m16n8k16.row.col.f32.f16.f16.f32 "
                 "{%0,%1,%2,%3}, {%4,%5,%6,%7}, {%8,%9}, {%0,%1,%2,%3};"
                 : "+f"(d[0]), "+f"(d[1]), "+f"(d[2]), "+f"(d[3])
                 : "r"(a[0]), "r"(a[1]), "r"(a[2]), "r"(a[3]),
                   "r"(b[0]), "r"(b[1]));
}
__device__ __forceinline__ void cpa16(uint32_t dst, const void* src, bool ok) {
    int sz = ok ? 16 : 0;
    asm volatile("cp.async.cg.shared.global [%0], [%1], 16, %2;"
                 :: "r"(dst), "l"(src), "r"(sz) : "memory");
}
__device__ __forceinline__ void cp_commit() {
    asm volatile("cp.async.commit_group;" ::: "memory");
}
template <int N>
__device__ __forceinline__ void cp_wait() {
    asm volatile("cp.async.wait_group %0;" :: "n"(N) : "memory");
}

// split fp32 -> fp16 hi + fp16 lo (residual ~2^-22)
__device__ __forceinline__ void hsplit(float v, __half& h, __half& l) {
    h = __float2half_rn(v);
    l = __float2half_rn(v - __half2float(h));
}

// ---------------------------------------------------------------------------
// Operand preparation kernels
// ---------------------------------------------------------------------------
// fp32 -> fp16 limbs (elementwise, 4-wide)
__global__ void fsplit16_kernel(const float* __restrict__ src,
                                __half* __restrict__ h, __half* __restrict__ l,
                                int n) {
    int i = blockIdx.x * blockDim.x + threadIdx.x;
    if (i * 4 >= n) return;
    float4 v = *(const float4*)(src + i * 4);
    __half h0, h1, h2, h3, l0, l1, l2, l3;
    hsplit(v.x, h0, l0); hsplit(v.y, h1, l1);
    hsplit(v.z, h2, l2); hsplit(v.w, h3, l3);
    __half2 hh0 = __halves2half2(h0, h1), hh1 = __halves2half2(h2, h3);
    __half2 ll0 = __halves2half2(l0, l1), ll1 = __halves2half2(l2, l3);
    *(uint2*)(h + i * 4) = make_uint2(*(uint32_t*)&hh0, *(uint32_t*)&hh1);
    *(uint2*)(l + i * 4) = make_uint2(*(uint32_t*)&ll0, *(uint32_t*)&ll1);
}

// weights [K9][COUT] fp32 -> [cout][k9] single fp16
__global__ void wprep16_kernel(const float* __restrict__ w,
                               __half* __restrict__ o, int K9, int COUT) {
    int i = blockIdx.x * blockDim.x + threadIdx.x;
    if (i >= K9 * COUT) return;
    int k = i / COUT, c = i % COUT;
    o[(size_t)c * K9 + k] = __float2half_rn(w[i]);
}

// ---------------------------------------------------------------------------
// FP16 tensor-core 3x3 SAME conv: A = 2 fp16 limbs (exact), W = 1 fp16 limb.
// 2 MMAs per k16 (A_hi*W + A_lo*W = A*fp16(W), fp32 accumulate).
// CTA: 128 thr (2M x 2N warps). Tile M=128px (8y x 16x) x N=COUT_TILE.
// Warp tile 64 x COUT_TILE/2. K chunks of 32 channels. Double-buffered cp.async.
// grid: (W/16, H/8, nimg * NT)
// ---------------------------------------------------------------------------
#define CONV_ASZ 10240   // 128 rows * 80B per A limb

template <int CIN, int COUT_TILE, bool OUT_SPLIT, int MAXB>
__global__ __launch_bounds__(128, MAXB)
void conv3x3_h(const __half* __restrict__ inh, const __half* __restrict__ inl,
               const __half* __restrict__ wt,
               const float* __restrict__ bias,
               float* __restrict__ outf,
               __half* __restrict__ outh, __half* __restrict__ outl,
               int H, int W, int COUT, int NT) {
    constexpr int K9 = 9 * CIN;
    constexpr int BSZ = COUT_TILE * 80;
    constexpr int BUFSZ = 2 * CONV_ASZ + BSZ;
    extern __shared__ char sm[];
    const uint32_t sb = smem_u32(sm);
    __shared__ float sbias[COUT_TILE];

    int t = threadIdx.x, warp = t >> 5, lane = t & 31;
    int img = blockIdx.z / NT, ntile = blockIdx.z % NT;
    int cobase = ntile * COUT_TILE;
    int x0 = blockIdx.x * 16, y0 = blockIdx.y * 8;

    if (t < COUT_TILE) sbias[t] = bias[cobase + t];

    int lpy = t >> 4, lpx = t & 15;          // A: 1 thread per pixel
    bool bok = t < COUT_TILE;

    constexpr int NF = COUT_TILE / 16;       // 8 or 6 (even)
    int wm = warp & 1, nw = warp >> 1;
    int nbase = nw * (COUT_TILE / 2);

    float acc[4][NF][4];
    #pragma unroll
    for (int i = 0; i < 4; i++)
        #pragma unroll
        for (int j = 0; j < NF; j++)
            #pragma unroll
            for (int q = 0; q < 4; q++) acc[i][j][q] = 0.f;

    const __half* imgh = inh + (size_t)img * H * W * CIN;
    const __half* imgl = inl + (size_t)img * H * W * CIN;
    const int KCH = K9 / 32;

    auto issue = [&](int kc, int buf) {
        int kbase = kc * 32;
        int tap = kbase / CIN;
        int dy = tap / 3 - 1, dx = tap % 3 - 1;
        int gy = y0 + lpy + dy, gx = x0 + lpx + dx;
        bool aok = (gy >= 0 && gy < H && gx >= 0 && gx < W);
        int cy = min(max(gy, 0), H - 1), cx = min(max(gx, 0), W - 1);
        size_t ab = ((size_t)cy * W + cx) * CIN + (kbase % CIN);
        uint32_t AhiO = sb + buf * BUFSZ;
        uint32_t AloO = AhiO + CONV_ASZ;
        uint32_t BO   = AhiO + 2 * CONV_ASZ;
        uint32_t arow = t * 80;
        #pragma unroll
        for (int j = 0; j < 4; j++) {
            cpa16(AhiO + arow + j * 16, imgh + ab + j * 8, aok);
            cpa16(AloO + arow + j * 16, imgl + ab + j * 8, aok);
        }
        if (bok) {
            size_t bb = (size_t)(cobase + t) * K9 + kbase;
            #pragma unroll
            for (int j = 0; j < 4; j++)
                cpa16(BO + arow + j * 16, wt + bb + j * 8, true);
        }
        cp_commit();
    };

    issue(0, 0);

    for (int kc = 0; kc < KCH; kc++) {
        int buf = kc & 1;
        if (kc + 1 < KCH) { issue(kc + 1, buf ^ 1); cp_wait<1>(); }
        else              { cp_wait<0>(); }
        __syncthreads();

        uint32_t AhiO = sb + buf * BUFSZ;
        uint32_t AloO = AhiO + CONV_ASZ;
        uint32_t BO   = AhiO + 2 * CONV_ASZ;

        #pragma unroll
        for (int k16 = 0; k16 < 2; k16++) {
            uint32_t ah[4][4], al[4][4];
            #pragma unroll
            for (int mi = 0; mi < 4; mi++) {
                uint32_t rowb = (uint32_t)((wm * 64 + mi * 16 + (lane & 15)) * 80
                                           + (k16 * 16 + (lane >> 4) * 8) * 2);
                ldsm_x4(ah[mi], AhiO + rowb);
                ldsm_x4(al[mi], AloO + rowb);
            }
            uint32_t bh[NF][2];
            #pragma unroll
            for (int p = 0; p < NF / 2; p++) {
                uint32_t addr = (uint32_t)((nbase + p * 16 + ((lane >> 4) << 3) + (lane & 7)) * 80
                                           + (k16 * 16 + ((lane >> 3) & 1) * 8) * 2);
                uint32_t r4[4];
                ldsm_x4(r4, BO + addr);
                bh[2 * p][0] = r4[0]; bh[2 * p][1] = r4[1];
                bh[2 * p + 1][0] = r4[2]; bh[2 * p + 1][1] = r4[3];
            }
            #pragma unroll
            for (int mi = 0; mi < 4; mi++)
                #pragma unroll
                for (int ni = 0; ni < NF; ni++) {
                    mma_f16(acc[mi][ni], ah[mi], bh[ni]);
                    mma_f16(acc[mi][ni], al[mi], bh[ni]);
                }
        }
        __syncthreads();
    }

    // ---- epilogue: bias + relu; write fp32 or fp16 limbs ----
    #pragma unroll
    for (int mi = 0; mi < 4; mi++) {
        int p0 = wm * 64 + mi * 16 + (lane >> 2);
        #pragma unroll
        for (int half_ = 0; half_ < 2; half_++) {
            int p = p0 + half_ * 8;
            int gy = y0 + (p >> 4), gx = x0 + (p & 15);
            size_t pixoff = ((size_t)img * H * W + (size_t)gy * W + gx) * COUT + cobase;
            #pragma unroll
            for (int ni = 0; ni < NF; ni++) {
                int cl = nbase + ni * 8 + (lane & 3) * 2;
                float r0 = acc[mi][ni][half_ * 2 + 0] + sbias[cl];
                float r1 = acc[mi][ni][half_ * 2 + 1] + sbias[cl + 1];
                r0 = fmaxf(r0, 0.f); r1 = fmaxf(r1, 0.f);
                if (OUT_SPLIT) {
                    __half h0, h1, l0, l1;
                    hsplit(r0, h0, l0); hsplit(r1, h1, l1);
                    __half2 hh = __halves2half2(h0, h1);
                    __half2 ll = __halves2half2(l0, l1);
                    *(uint32_t*)(outh + pixoff + cl) = *(uint32_t*)&hh;
                    *(uint32_t*)(outl + pixoff + cl) = *(uint32_t*)&ll;
                } else {
                    *(float2*)(outf + pixoff + cl) = make_float2(r0, r1);
                }
            }
        }
    }
}

// ---------------------------------------------------------------------------
// Classification head
// ---------------------------------------------------------------------------
__global__ void cls_kernel(const float* __restrict__ feat5,
                           const float* __restrict__ fc1_w, const float* __restrict__ fc1_b,
                           const float* __restrict__ fc2_w, const float* __restrict__ fc2_b,
                           const float* __restrict__ fc3_w, const float* __restrict__ fc3_b,
                           float* __restrict__ out_predcls, int* __restrict__ cls) {
    int b = blockIdx.x;
    int t = threadIdx.x;
    __shared__ float g0[256], g1[256], lg[3];
    const float* f = feat5 + (size_t)b * 16 * 16 * 256;
    float s = 0.f;
    #pragma unroll 4
    for (int p = 0; p < 256; p++) s += f[p * 256 + t];
    g0[t] = s * (1.0f / 256.0f);
    __syncthreads();
    float a = fc1_b[t];
    #pragma unroll 4
    for (int k = 0; k < 256; k++) a = fmaf(g0[k], fc1_w[k * 256 + t], a);
    g1[t] = fmaxf(a, 0.f);
    __syncthreads();
    a = fc2_b[t];
    #pragma unroll 4
    for (int k = 0; k < 256; k++) a = fmaf(g1[k], fc2_w[k * 256 + t], a);
    g0[t] = fmaxf(a, 0.f);
    __syncthreads();
    if (t < 3) {
        a = fc3_b[t];
        for (int k = 0; k < 256; k++) a = fmaf(g0[k], fc3_w[k * 3 + t], a);
        lg[t] = a;
    }
    __syncthreads();
    if (t == 0) {
        float m = fmaxf(lg[0], fmaxf(lg[1], lg[2]));
        float e0 = expf(lg[0] - m), e1 = expf(lg[1] - m), e2 = expf(lg[2] - m);
        float inv = 1.f / (e0 + e1 + e2);
        out_predcls[b * 3 + 0] = e0 * inv;
        out_predcls[b * 3 + 1] = e1 * inv;
        out_predcls[b * 3 + 2] = e2 * inv;
        int c = 0;
        if (lg[1] > lg[0]) c = 1;
        if (lg[2] > lg[c]) c = 2;
        cls[b] = c;
    }
}

// ---------------------------------------------------------------------------
// Fused reg/wt conv with class selection (5 channels, fp32)
// ---------------------------------------------------------------------------
__global__ void regsel_kernel(const float* __restrict__ x,
                              const float* __restrict__ reg_w, const float* __restrict__ reg_b,
                              const float* __restrict__ wt_w,  const float* __restrict__ wt_b,
                              const int* __restrict__ cls, float* __restrict__ out) {
    int b = blockIdx.z;
    int c = cls[b];
    __shared__ __align__(16) float ws[9 * 256 * 5];
    int t = threadIdx.x;
    for (int i = t; i < 9 * 256; i += 256) {
        const float* rp = reg_w + (size_t)i * 12 + 4 * c;
        float* wp = ws + i * 5;
        wp[0] = rp[0]; wp[1] = rp[1]; wp[2] = rp[2]; wp[3] = rp[3];
        wp[4] = wt_w[(size_t)i * 3 + c];
    }
    __syncthreads();
    int px = blockIdx.x * 16 + (t & 15);
    int py = blockIdx.y * 16 + (t >> 4);
    float a0 = reg_b[4 * c], a1 = reg_b[4 * c + 1], a2 = reg_b[4 * c + 2],
          a3 = reg_b[4 * c + 3], a4 = wt_b[c];
    const float* xi = x + (size_t)b * 256 * 256 * 256;
    for (int tap = 0; tap < 9; tap++) {
        int yy = py + tap / 3 - 1, xx = px + tap % 3 - 1;
        if (yy < 0 || yy >= 256 || xx < 0 || xx >= 256) continue;
        const float* ip = xi + ((size_t)yy * 256 + xx) * 256;
        const float* wp = ws + tap * 256 * 5;
        #pragma unroll 2
        for (int ci = 0; ci < 256; ci += 4) {
            float4 v = *(const float4*)(ip + ci);
            float wl[20];
            const float4* w4 = (const float4*)(wp + ci * 5);
            #pragma unroll
            for (int q = 0; q < 5; q++) ((float4*)wl)[q] = w4[q];
            a0 = fmaf(v.x, wl[0], a0);  a1 = fmaf(v.x, wl[1], a1);
            a2 = fmaf(v.x, wl[2], a2);  a3 = fmaf(v.x, wl[3], a3);  a4 = fmaf(v.x, wl[4], a4);
            a0 = fmaf(v.y, wl[5], a0);  a1 = fmaf(v.y, wl[6], a1);
            a2 = fmaf(v.y, wl[7], a2);  a3 = fmaf(v.y, wl[8], a3);  a4 = fmaf(v.y, wl[9], a4);
            a0 = fmaf(v.z, wl[10], a0); a1 = fmaf(v.z, wl[11], a1);
            a2 = fmaf(v.z, wl[12], a2); a3 = fmaf(v.z, wl[13], a3); a4 = fmaf(v.z, wl[14], a4);
            a0 = fmaf(v.w, wl[15], a0); a1 = fmaf(v.w, wl[16], a1);
            a2 = fmaf(v.w, wl[17], a2); a3 = fmaf(v.w, wl[18], a3); a4 = fmaf(v.w, wl[19], a4);
        }
    }
    size_t pix = ((size_t)b * 256 + py) * 256 + px;
    out[OFF_OFFSETS + pix * 2 + 0] = a0;
    out[OFF_OFFSETS + pix * 2 + 1] = a1;
    out[OFF_SIZES   + pix * 2 + 0] = a2;
    out[OFF_SIZES   + pix * 2 + 1] = a3;
    out[OFF_WEIGHTS + pix] = a4;
}

// ---------------------------------------------------------------------------
// Bilinear crop -> fp16 limbs
// ---------------------------------------------------------------------------
__global__ void crop_kernel(const float* __restrict__ feat0,
                            const float* __restrict__ boxes,
                            __half* __restrict__ ch, __half* __restrict__ cl) {
    int n = blockIdx.x;
    int b = n >> 6;
    const int H = 512, W = 512, C = 64;
    __shared__ int sy0[32], sx0[32];
    __shared__ float swy[32], swx[32];
    const float* bx = boxes + (size_t)n * 4;
    float y1 = bx[0], x1 = bx[1], y2 = bx[2], x2 = bx[3];
    int t = threadIdx.x;
    if (t < 32) {
        float tt = (float)t / 31.0f;
        float ys = y1 * (H - 1) + tt * (y2 - y1) * (H - 1);
        int yy0 = (int)floorf(ys);
        yy0 = min(max(yy0, 0), H - 2);
        sy0[t] = yy0; swy[t] = ys - (float)yy0;
    } else if (t < 64) {
        int i = t - 32;
        float tt = (float)i / 31.0f;
        float xs = x1 * (W - 1) + tt * (x2 - x1) * (W - 1);
        int xx0 = (int)floorf(xs);
        xx0 = min(max(xx0, 0), W - 2);
        sx0[i] = xx0; swx[i] = xs - (float)xx0;
    }
    __syncthreads();
    const float* f = feat0 + (size_t)b * H * W * C;
    size_t obase = (size_t)n * 32 * 32 * C;
    for (int idx = t; idx < 32 * 32 * C; idx += blockDim.x) {
        int c  = idx & 63;
        int ix = (idx >> 6) & 31;
        int iy = idx >> 11;
        int yy0 = sy0[iy], xx0 = sx0[ix];
        float wy = swy[iy], wx = swx[ix];
        const float* p00 = f + ((size_t)yy0 * W + xx0) * C + c;
        float v00 = p00[0], v01 = p00[C], v10 = p00[(size_t)W * C], v11 = p00[(size_t)W * C + C];
        float top = v00 * (1.f - wx) + v01 * wx;
        float bot = v10 * (1.f - wx) + v11 * wx;
        float v = top * (1.f - wy) + bot * wy;
        __half hb, lb;
        hsplit(v, hb, lb);
        ch[obase + idx] = hb;
        cl[obase + idx] = lb;
    }
}

// ---------------------------------------------------------------------------
// so conv with class selection (1 channel, fp32)
// ---------------------------------------------------------------------------
__global__ void sosel_kernel(const float* __restrict__ s2,
                             const float* __restrict__ so_w, const float* __restrict__ so_b,
                             const int* __restrict__ cls, float* __restrict__ out) {
    int n = blockIdx.x;
    int c = cls[n >> 6];
    __shared__ __align__(16) float ws[9 * 96];
    int t = threadIdx.x;
    for (int i = t; i < 864; i += 256) ws[i] = so_w[(size_t)i * 3 + c];
    __syncthreads();
    float bias = so_b[c];
    const float* sp = s2 + (size_t)n * 32 * 32 * 96;
    for (int pix = t; pix < 1024; pix += 256) {
        int py = pix >> 5, px = pix & 31;
        float acc = bias;
        for (int tap = 0; tap < 9; tap++) {
            int yy = py + tap / 3 - 1, xx = px + tap % 3 - 1;
            if (yy < 0 || yy >= 32 || xx < 0 || xx >= 32) continue;
            const float* ip = sp + ((size_t)yy * 32 + xx) * 96;
            const float* wp = ws + tap * 96;
            #pragma unroll 4
            for (int ci = 0; ci < 96; ci += 4) {
                float4 v = *(const float4*)(ip + ci);
                float4 w = *(const float4*)(wp + ci);
                acc = fmaf(v.x, w.x, acc);
                acc = fmaf(v.y, w.y, acc);
                acc = fmaf(v.z, w.z, acc);
                acc = fmaf(v.w, w.w, acc);
            }
        }
        out[OFF_SEG + (size_t)n * 1024 + pix] = acc;
    }
}

// ---------------------------------------------------------------------------
// Score head
// ---------------------------------------------------------------------------
__global__ void score_kernel(const float* __restrict__ s2,
                             const float* __restrict__ sd1_w, const float* __restrict__ sd1_b,
                             const float* __restrict__ sd2_w, const float* __restrict__ sd2_b,
                             const float* __restrict__ sd3_w, const float* __restrict__ sd3_b,
                             const int* __restrict__ cls, float* __restrict__ out) {
    int n = blockIdx.x;
    int t = threadIdx.x;
    __shared__ float pooled[6144];
    __shared__ float h1[256], h2[256];
    const float* sp = s2 + (size_t)n * 32 * 32 * 96;
    for (int o = t; o < 6144; o += 256) {
        int c  = o % 96;
        int px = (o / 96) & 7;
        int py = o / 768;
        float s = 0.f;
        #pragma unroll
        for (int i = 0; i < 4; i++)
            #pragma unroll
            for (int j = 0; j < 4; j++)
                s += sp[(((size_t)(py * 4 + i)) * 32 + (px * 4 + j)) * 96 + c];
        pooled[o] = s * (1.f / 16.f);
    }
    __syncthreads();
    float a = sd1_b[t];
    #pragma unroll 4
    for (int k = 0; k < 6144; k++) a = fmaf(pooled[k], sd1_w[(size_t)k * 256 + t], a);
    h1[t] = fmaxf(a, 0.f);
    __syncthreads();
    a = sd2_b[t];
    #pragma unroll 4
    for (int k = 0; k < 256; k++) a = fmaf(h1[k], sd2_w[k * 256 + t], a);
    h2[t] = fmaxf(a, 0.f);
    __syncthreads();
    if (t == 0) {
        int c = cls[n >> 6];
        float acc = sd3_b[c];
        for (int k = 0; k < 256; k++) acc = fmaf(h2[k], sd3_w[k * 3 + c], acc);
        out[OFF_SCORE + n] = acc;
    }
}

// ---------------------------------------------------------------------------
extern "C" void kernel_launch(void* const* d_in, const int* in_sizes, int n_in,
                              void* d_out, int out_size) {
    (void)in_sizes; (void)n_in; (void)out_size;
    const float* feat0 = (const float*)d_in[0];
    const float* feat1 = (const float*)d_in[1];
    const float* feat5 = (const float*)d_in[2];
    const float* boxes = (const float*)d_in[3];
    const float* cb1_w = (const float*)d_in[4];
    const float* cb1_b = (const float*)d_in[5];
    const float* cb2_w = (const float*)d_in[6];
    const float* cb2_b = (const float*)d_in[7];
    const float* reg_w = (const float*)d_in[8];
    const float* reg_b = (const float*)d_in[9];
    const float* wt_w  = (const float*)d_in[10];
    const float* wt_b  = (const float*)d_in[11];
    const float* fc1_w = (const float*)d_in[12];
    const float* fc1_b = (const float*)d_in[13];
    const float* fc2_w = (const float*)d_in[14];
    const float* fc2_b = (const float*)d_in[15];
    const float* fc3_w = (const float*)d_in[16];
    const float* fc3_b = (const float*)d_in[17];
    const float* sc1_w = (const float*)d_in[18];
    const float* sc1_b = (const float*)d_in[19];
    const float* sc2_w = (const float*)d_in[20];
    const float* sc2_b = (const float*)d_in[21];
    const float* so_w  = (const float*)d_in[22];
    const float* so_b  = (const float*)d_in[23];
    const float* sd1_w = (const float*)d_in[24];
    const float* sd1_b = (const float*)d_in[25];
    const float* sd2_w = (const float*)d_in[26];
    const float* sd2_b = (const float*)d_in[27];
    const float* sd3_w = (const float*)d_in[28];
    const float* sd3_b = (const float*)d_in[29];
    float* out = (float*)d_out;

    // resolve device globals
    void* p;
    cudaGetSymbolAddress(&p, g_f1h); __half* f1h = (__half*)p;
    cudaGetSymbolAddress(&p, g_f1l); __half* f1l = (__half*)p;
    cudaGetSymbolAddress(&p, g_x1h); __half* x1h = (__half*)p;
    cudaGetSymbolAddress(&p, g_x1l); __half* x1l = (__half*)p;
    cudaGetSymbolAddress(&p, g_x2);  float* x2 = (float*)p;
    cudaGetSymbolAddress(&p, g_cph); __half* cph = (__half*)p;
    cudaGetSymbolAddress(&p, g_cpl); __half* cpl = (__half*)p;
    cudaGetSymbolAddress(&p, g_s1h); __half* s1h = (__half*)p;
    cudaGetSymbolAddress(&p, g_s1l); __half* s1l = (__half*)p;
    cudaGetSymbolAddress(&p, g_s2);  float* s2 = (float*)p;
    cudaGetSymbolAddress(&p, g_w1);  __half* w1 = (__half*)p;
    cudaGetSymbolAddress(&p, g_w2);  __half* w2 = (__half*)p;
    cudaGetSymbolAddress(&p, g_w3);  __half* w3 = (__half*)p;
    cudaGetSymbolAddress(&p, g_w4);  __half* w4 = (__half*)p;
    cudaGetSymbolAddress(&p, g_cls); int* cls = (int*)p;

    constexpr int DYN128 = 2 * (2 * CONV_ASZ + 128 * 80);   // 61440
    constexpr int DYN96  = 2 * (2 * CONV_ASZ + 96 * 80);    // 56320
    cudaFuncSetAttribute(conv3x3_h<128, 128, true,  2>,
                         cudaFuncAttributeMaxDynamicSharedMemorySize, DYN128);
    cudaFuncSetAttribute(conv3x3_h<256, 128, false, 2>,
                         cudaFuncAttributeMaxDynamicSharedMemorySize, DYN128);
    cudaFuncSetAttribute(conv3x3_h<64, 96, true,  3>,
                         cudaFuncAttributeMaxDynamicSharedMemorySize, DYN96);
    cudaFuncSetAttribute(conv3x3_h<96, 96, false, 3>,
                         cudaFuncAttributeMaxDynamicSharedMemorySize, DYN96);

    // classification first (selection depends on cls)
    cls_kernel<<<4, 256>>>(feat5, fc1_w, fc1_b, fc2_w, fc2_b, fc3_w, fc3_b,
                           out + OFF_PREDCLS, cls);

    // operand prep
    wprep16_kernel<<<(294912 + 255) / 256, 256>>>(cb1_w, w1, 1152, 256);
    wprep16_kernel<<<(589824 + 255) / 256, 256>>>(cb2_w, w2, 2304, 256);
    wprep16_kernel<<<(55296 + 255) / 256, 256>>>(sc1_w, w3, 576, 96);
    wprep16_kernel<<<(82944 + 255) / 256, 256>>>(sc2_w, w4, 864, 96);
    fsplit16_kernel<<<(33554432 / 4 + 255) / 256, 256>>>(feat1, f1h, f1l, 33554432);

    // crop + segmentation branch
    crop_kernel<<<256, 256>>>(feat0, boxes, cph, cpl);
    conv3x3_h<64, 96, true, 3><<<dim3(2, 4, 256), 128, DYN96>>>(
        cph, cpl, w3, sc1_b, nullptr, s1h, s1l, 32, 32, 96, 1);
    conv3x3_h<96, 96, false, 3><<<dim3(2, 4, 256), 128, DYN96>>>(
        s1h, s1l, w4, sc2_b, s2, nullptr, nullptr, 32, 32, 96, 1);
    sosel_kernel<<<256, 256>>>(s2, so_w, so_b, cls, out);
    score_kernel<<<256, 256>>>(s2, sd1_w, sd1_b, sd2_w, sd2_b, sd3_w, sd3_b, cls, out);

    // regression branch
    conv3x3_h<128, 128, true, 2><<<dim3(16, 32, 8), 128, DYN128>>>(
        f1h, f1l, w1, cb1_b, nullptr, x1h, x1l, 256, 256, 256, 2);
    conv3x3_h<256, 128, false, 2><<<dim3(16, 32, 8), 128, DYN128>>>(
        x1h, x1l, w2, cb2_b, x2, nullptr, nullptr, 256, 256, 256, 2);
    regsel_kernel<<<dim3(16, 16, 4), 256>>>(x2, reg_w, reg_b, wt_w, wt_b, cls, out);
}

// round 9
// speedup vs baseline: 2.8685x; 1.4197x over previous
#include <cuda_runtime.h>
#include <cuda_fp16.h>
#include <math.h>
#include <stdint.h>

typedef unsigned long long u64;

// ---------------------------------------------------------------------------
// Output layout (tuple flattened in order)
// ---------------------------------------------------------------------------
#define OFF_OFFSETS 0
#define OFF_SIZES   524288
#define OFF_WEIGHTS 1048576
#define OFF_PREDCLS 1310720
#define OFF_SEG     1310732
#define OFF_SCORE   1572876

// Scratch (device globals; no allocation allowed)
__device__ __half g_f1[33554432];     // feat1 fp16
__device__ __half g_x1[67108864];     // conv1 out fp16
__device__ float  g_x2[67108864];     // conv2 out fp32
__device__ __half g_cp[16777216];     // crops fp16
__device__ __half g_s1[25165824];     // sc1 out fp16
__device__ float  g_s2[25165824];     // sc2 out fp32
// transposed fp16 weights [cout][k9]
__device__ __half g_w1[294912];
__device__ __half g_w2[589824];
__device__ __half g_w3[55296];
__device__ __half g_w4[82944];
__device__ int g_cls[4];

// ---------------------------------------------------------------------------
// PTX helpers (arch-generic sm_80+)
// ---------------------------------------------------------------------------
__device__ __forceinline__ uint32_t smem_u32(const void* p) {
    uint32_t a;
    asm("{ .reg .u64 t; cvta.to.shared.u64 t, %1; cvt.u32.u64 %0, t; }"
        : "=r"(a) : "l"(p));
    return a;
}
__device__ __forceinline__ void ldsm_x4(uint32_t* r, uint32_t a) {
    asm volatile("ldmatrix.sync.aligned.m8n8.x4.shared.b16 {%0,%1,%2,%3}, [%4];"
                 : "=r"(r[0]), "=r"(r[1]), "=r"(r[2]), "=r"(r[3]) : "r"(a));
}
__device__ __forceinline__ void mma_f16(float* d, const uint32_t* a, const uint32_t* b) {
    asm volatile("mma.sync.aligned.m16n8k16.row.col.f32.f16.f16.f32 "
                 "{%0,%1,%2,%3}, {%4,%5,%6,%7}, {%8,%9}, {%0,%1,%2,%3};"
                 : "+f"(d[0]), "+f"(d[1]), "+f"(d[2]), "+f"(d[3])
                 : "r"(a[0]), "r"(a[1]), "r"(a[2]), "r"(a[3]),
                   "r"(b[0]), "r"(b[1]));
}
__device__ __forceinline__ void cpa16(uint32_t dst, const void* src, bool ok) {
    int sz = ok ? 16 : 0;
    asm volatile("cp.async.cg.shared.global [%0], [%1], 16, %2;"
                 :: "r"(dst), "l"(src), "r"(sz) : "memory");
}
__device__ __forceinline__ void cp_commit() {
    asm volatile("cp.async.commit_group;" ::: "memory");
}
template <int N>
__device__ __forceinline__ void cp_wait() {
    asm volatile("cp.async.wait_group %0;" :: "n"(N) : "memory");
}

// ---------------------------------------------------------------------------
// Operand preparation kernels
// ---------------------------------------------------------------------------
// fp32 -> fp16 (elementwise, 4-wide)
__global__ void fcvt16_kernel(const float* __restrict__ src,
                              __half* __restrict__ o, int n) {
    int i = blockIdx.x * blockDim.x + threadIdx.x;
    if (i * 4 >= n) return;
    float4 v = *(const float4*)(src + i * 4);
    __half2 a = __halves2half2(__float2half_rn(v.x), __float2half_rn(v.y));
    __half2 b = __halves2half2(__float2half_rn(v.z), __float2half_rn(v.w));
    *(uint2*)(o + i * 4) = make_uint2(*(uint32_t*)&a, *(uint32_t*)&b);
}

// weights [K9][COUT] fp32 -> [cout][k9] fp16
__global__ void wprep16_kernel(const float* __restrict__ w,
                               __half* __restrict__ o, int K9, int COUT) {
    int i = blockIdx.x * blockDim.x + threadIdx.x;
    if (i >= K9 * COUT) return;
    int k = i / COUT, c = i % COUT;
    o[(size_t)c * K9 + k] = __float2half_rn(w[i]);
}

// ---------------------------------------------------------------------------
// FP16 tensor-core 3x3 SAME conv: A fp16, W fp16, fp32 accumulate.
// CTA: 128 thr (2M x 2N warps). Tile M=128px (8y x 16x) x N=COUT_TILE.
// Warp tile 64 x COUT_TILE/2. K chunks of 32 channels. Double-buffered cp.async.
// grid: (W/16, H/8, nimg * NT)
// ---------------------------------------------------------------------------
#define CONV_ASZ 10240   // 128 rows * 80B

template <int CIN, int COUT_TILE, bool OUT_HALF, int MAXB>
__global__ __launch_bounds__(128, MAXB)
void conv3x3_h(const __half* __restrict__ in,
               const __half* __restrict__ wt,
               const float* __restrict__ bias,
               float* __restrict__ outf, __half* __restrict__ outh,
               int H, int W, int COUT, int NT) {
    constexpr int K9 = 9 * CIN;
    constexpr int BSZ = COUT_TILE * 80;
    constexpr int BUFSZ = CONV_ASZ + BSZ;
    extern __shared__ char sm[];
    const uint32_t sb = smem_u32(sm);
    __shared__ float sbias[COUT_TILE];

    int t = threadIdx.x, warp = t >> 5, lane = t & 31;
    int img = blockIdx.z / NT, ntile = blockIdx.z % NT;
    int cobase = ntile * COUT_TILE;
    int x0 = blockIdx.x * 16, y0 = blockIdx.y * 8;

    if (t < COUT_TILE) sbias[t] = bias[cobase + t];

    int lpy = t >> 4, lpx = t & 15;          // A: 1 thread per pixel
    bool bok = t < COUT_TILE;

    constexpr int NF = COUT_TILE / 16;       // 8 or 6 (even)
    int wm = warp & 1, nw = warp >> 1;
    int nbase = nw * (COUT_TILE / 2);

    float acc[4][NF][4];
    #pragma unroll
    for (int i = 0; i < 4; i++)
        #pragma unroll
        for (int j = 0; j < NF; j++)
            #pragma unroll
            for (int q = 0; q < 4; q++) acc[i][j][q] = 0.f;

    const __half* img0 = in + (size_t)img * H * W * CIN;
    const int KCH = K9 / 32;

    auto issue = [&](int kc, int buf) {
        int kbase = kc * 32;
        int tap = kbase / CIN;
        int dy = tap / 3 - 1, dx = tap % 3 - 1;
        int gy = y0 + lpy + dy, gx = x0 + lpx + dx;
        bool aok = (gy >= 0 && gy < H && gx >= 0 && gx < W);
        int cy = min(max(gy, 0), H - 1), cx = min(max(gx, 0), W - 1);
        size_t ab = ((size_t)cy * W + cx) * CIN + (kbase % CIN);
        uint32_t AO = sb + buf * BUFSZ;
        uint32_t BO = AO + CONV_ASZ;
        uint32_t arow = t * 80;
        #pragma unroll
        for (int j = 0; j < 4; j++)
            cpa16(AO + arow + j * 16, img0 + ab + j * 8, aok);
        if (bok) {
            size_t bb = (size_t)(cobase + t) * K9 + kbase;
            #pragma unroll
            for (int j = 0; j < 4; j++)
                cpa16(BO + arow + j * 16, wt + bb + j * 8, true);
        }
        cp_commit();
    };

    issue(0, 0);

    for (int kc = 0; kc < KCH; kc++) {
        int buf = kc & 1;
        if (kc + 1 < KCH) { issue(kc + 1, buf ^ 1); cp_wait<1>(); }
        else              { cp_wait<0>(); }
        __syncthreads();

        uint32_t AO = sb + buf * BUFSZ;
        uint32_t BO = AO + CONV_ASZ;

        #pragma unroll
        for (int k16 = 0; k16 < 2; k16++) {
            uint32_t ah[4][4];
            #pragma unroll
            for (int mi = 0; mi < 4; mi++) {
                uint32_t rowb = (uint32_t)((wm * 64 + mi * 16 + (lane & 15)) * 80
                                           + (k16 * 16 + (lane >> 4) * 8) * 2);
                ldsm_x4(ah[mi], AO + rowb);
            }
            uint32_t bh[NF][2];
            #pragma unroll
            for (int p = 0; p < NF / 2; p++) {
                uint32_t addr = (uint32_t)((nbase + p * 16 + ((lane >> 4) << 3) + (lane & 7)) * 80
                                           + (k16 * 16 + ((lane >> 3) & 1) * 8) * 2);
                uint32_t r4[4];
                ldsm_x4(r4, BO + addr);
                bh[2 * p][0] = r4[0]; bh[2 * p][1] = r4[1];
                bh[2 * p + 1][0] = r4[2]; bh[2 * p + 1][1] = r4[3];
            }
            #pragma unroll
            for (int mi = 0; mi < 4; mi++)
                #pragma unroll
                for (int ni = 0; ni < NF; ni++)
                    mma_f16(acc[mi][ni], ah[mi], bh[ni]);
        }
        __syncthreads();
    }

    // ---- epilogue: bias + relu; write fp16 or fp32 ----
    #pragma unroll
    for (int mi = 0; mi < 4; mi++) {
        int p0 = wm * 64 + mi * 16 + (lane >> 2);
        #pragma unroll
        for (int half_ = 0; half_ < 2; half_++) {
            int p = p0 + half_ * 8;
            int gy = y0 + (p >> 4), gx = x0 + (p & 15);
            size_t pixoff = ((size_t)img * H * W + (size_t)gy * W + gx) * COUT + cobase;
            #pragma unroll
            for (int ni = 0; ni < NF; ni++) {
                int cl = nbase + ni * 8 + (lane & 3) * 2;
                float r0 = acc[mi][ni][half_ * 2 + 0] + sbias[cl];
                float r1 = acc[mi][ni][half_ * 2 + 1] + sbias[cl + 1];
                r0 = fmaxf(r0, 0.f); r1 = fmaxf(r1, 0.f);
                if (OUT_HALF) {
                    __half2 hh = __halves2half2(__float2half_rn(r0), __float2half_rn(r1));
                    *(uint32_t*)(outh + pixoff + cl) = *(uint32_t*)&hh;
                } else {
                    *(float2*)(outf + pixoff + cl) = make_float2(r0, r1);
                }
            }
        }
    }
}

// ---------------------------------------------------------------------------
// Classification head
// ---------------------------------------------------------------------------
__global__ void cls_kernel(const float* __restrict__ feat5,
                           const float* __restrict__ fc1_w, const float* __restrict__ fc1_b,
                           const float* __restrict__ fc2_w, const float* __restrict__ fc2_b,
                           const float* __restrict__ fc3_w, const float* __restrict__ fc3_b,
                           float* __restrict__ out_predcls, int* __restrict__ cls) {
    int b = blockIdx.x;
    int t = threadIdx.x;
    __shared__ float g0[256], g1[256], lg[3];
    const float* f = feat5 + (size_t)b * 16 * 16 * 256;
    float s = 0.f;
    #pragma unroll 4
    for (int p = 0; p < 256; p++) s += f[p * 256 + t];
    g0[t] = s * (1.0f / 256.0f);
    __syncthreads();
    float a = fc1_b[t];
    #pragma unroll 4
    for (int k = 0; k < 256; k++) a = fmaf(g0[k], fc1_w[k * 256 + t], a);
    g1[t] = fmaxf(a, 0.f);
    __syncthreads();
    a = fc2_b[t];
    #pragma unroll 4
    for (int k = 0; k < 256; k++) a = fmaf(g1[k], fc2_w[k * 256 + t], a);
    g0[t] = fmaxf(a, 0.f);
    __syncthreads();
    if (t < 3) {
        a = fc3_b[t];
        for (int k = 0; k < 256; k++) a = fmaf(g0[k], fc3_w[k * 3 + t], a);
        lg[t] = a;
    }
    __syncthreads();
    if (t == 0) {
        float m = fmaxf(lg[0], fmaxf(lg[1], lg[2]));
        float e0 = expf(lg[0] - m), e1 = expf(lg[1] - m), e2 = expf(lg[2] - m);
        float inv = 1.f / (e0 + e1 + e2);
        out_predcls[b * 3 + 0] = e0 * inv;
        out_predcls[b * 3 + 1] = e1 * inv;
        out_predcls[b * 3 + 2] = e2 * inv;
        int c = 0;
        if (lg[1] > lg[0]) c = 1;
        if (lg[2] > lg[c]) c = 2;
        cls[b] = c;
    }
}

// ---------------------------------------------------------------------------
// Fused reg/wt conv with class selection (5 channels, fp32)
// ---------------------------------------------------------------------------
__global__ void regsel_kernel(const float* __restrict__ x,
                              const float* __restrict__ reg_w, const float* __restrict__ reg_b,
                              const float* __restrict__ wt_w,  const float* __restrict__ wt_b,
                              const int* __restrict__ cls, float* __restrict__ out) {
    int b = blockIdx.z;
    int c = cls[b];
    __shared__ __align__(16) float ws[9 * 256 * 5];
    int t = threadIdx.x;
    for (int i = t; i < 9 * 256; i += 256) {
        const float* rp = reg_w + (size_t)i * 12 + 4 * c;
        float* wp = ws + i * 5;
        wp[0] = rp[0]; wp[1] = rp[1]; wp[2] = rp[2]; wp[3] = rp[3];
        wp[4] = wt_w[(size_t)i * 3 + c];
    }
    __syncthreads();
    int px = blockIdx.x * 16 + (t & 15);
    int py = blockIdx.y * 16 + (t >> 4);
    float a0 = reg_b[4 * c], a1 = reg_b[4 * c + 1], a2 = reg_b[4 * c + 2],
          a3 = reg_b[4 * c + 3], a4 = wt_b[c];
    const float* xi = x + (size_t)b * 256 * 256 * 256;
    for (int tap = 0; tap < 9; tap++) {
        int yy = py + tap / 3 - 1, xx = px + tap % 3 - 1;
        if (yy < 0 || yy >= 256 || xx < 0 || xx >= 256) continue;
        const float* ip = xi + ((size_t)yy * 256 + xx) * 256;
        const float* wp = ws + tap * 256 * 5;
        #pragma unroll 2
        for (int ci = 0; ci < 256; ci += 4) {
            float4 v = *(const float4*)(ip + ci);
            float wl[20];
            const float4* w4 = (const float4*)(wp + ci * 5);
            #pragma unroll
            for (int q = 0; q < 5; q++) ((float4*)wl)[q] = w4[q];
            a0 = fmaf(v.x, wl[0], a0);  a1 = fmaf(v.x, wl[1], a1);
            a2 = fmaf(v.x, wl[2], a2);  a3 = fmaf(v.x, wl[3], a3);  a4 = fmaf(v.x, wl[4], a4);
            a0 = fmaf(v.y, wl[5], a0);  a1 = fmaf(v.y, wl[6], a1);
            a2 = fmaf(v.y, wl[7], a2);  a3 = fmaf(v.y, wl[8], a3);  a4 = fmaf(v.y, wl[9], a4);
            a0 = fmaf(v.z, wl[10], a0); a1 = fmaf(v.z, wl[11], a1);
            a2 = fmaf(v.z, wl[12], a2); a3 = fmaf(v.z, wl[13], a3); a4 = fmaf(v.z, wl[14], a4);
            a0 = fmaf(v.w, wl[15], a0); a1 = fmaf(v.w, wl[16], a1);
            a2 = fmaf(v.w, wl[17], a2); a3 = fmaf(v.w, wl[18], a3); a4 = fmaf(v.w, wl[19], a4);
        }
    }
    size_t pix = ((size_t)b * 256 + py) * 256 + px;
    out[OFF_OFFSETS + pix * 2 + 0] = a0;
    out[OFF_OFFSETS + pix * 2 + 1] = a1;
    out[OFF_SIZES   + pix * 2 + 0] = a2;
    out[OFF_SIZES   + pix * 2 + 1] = a3;
    out[OFF_WEIGHTS + pix] = a4;
}

// ---------------------------------------------------------------------------
// Bilinear crop -> fp16
// ---------------------------------------------------------------------------
__global__ void crop_kernel(const float* __restrict__ feat0,
                            const float* __restrict__ boxes,
                            __half* __restrict__ cp) {
    int n = blockIdx.x;
    int b = n >> 6;
    const int H = 512, W = 512, C = 64;
    __shared__ int sy0[32], sx0[32];
    __shared__ float swy[32], swx[32];
    const float* bx = boxes + (size_t)n * 4;
    float y1 = bx[0], x1 = bx[1], y2 = bx[2], x2 = bx[3];
    int t = threadIdx.x;
    if (t < 32) {
        float tt = (float)t / 31.0f;
        float ys = y1 * (H - 1) + tt * (y2 - y1) * (H - 1);
        int yy0 = (int)floorf(ys);
        yy0 = min(max(yy0, 0), H - 2);
        sy0[t] = yy0; swy[t] = ys - (float)yy0;
    } else if (t < 64) {
        int i = t - 32;
        float tt = (float)i / 31.0f;
        float xs = x1 * (W - 1) + tt * (x2 - x1) * (W - 1);
        int xx0 = (int)floorf(xs);
        xx0 = min(max(xx0, 0), W - 2);
        sx0[i] = xx0; swx[i] = xs - (float)xx0;
    }
    __syncthreads();
    const float* f = feat0 + (size_t)b * H * W * C;
    size_t obase = (size_t)n * 32 * 32 * C;
    for (int idx = t; idx < 32 * 32 * C; idx += blockDim.x) {
        int c  = idx & 63;
        int ix = (idx >> 6) & 31;
        int iy = idx >> 11;
        int yy0 = sy0[iy], xx0 = sx0[ix];
        float wy = swy[iy], wx = swx[ix];
        const float* p00 = f + ((size_t)yy0 * W + xx0) * C + c;
        float v00 = p00[0], v01 = p00[C], v10 = p00[(size_t)W * C], v11 = p00[(size_t)W * C + C];
        float top = v00 * (1.f - wx) + v01 * wx;
        float bot = v10 * (1.f - wx) + v11 * wx;
        float v = top * (1.f - wy) + bot * wy;
        cp[obase + idx] = __float2half_rn(v);
    }
}

// ---------------------------------------------------------------------------
// so conv with class selection (1 channel, fp32)
// ---------------------------------------------------------------------------
__global__ void sosel_kernel(const float* __restrict__ s2,
                             const float* __restrict__ so_w, const float* __restrict__ so_b,
                             const int* __restrict__ cls, float* __restrict__ out) {
    int n = blockIdx.x;
    int c = cls[n >> 6];
    __shared__ __align__(16) float ws[9 * 96];
    int t = threadIdx.x;
    for (int i = t; i < 864; i += 256) ws[i] = so_w[(size_t)i * 3 + c];
    __syncthreads();
    float bias = so_b[c];
    const float* sp = s2 + (size_t)n * 32 * 32 * 96;
    for (int pix = t; pix < 1024; pix += 256) {
        int py = pix >> 5, px = pix & 31;
        float acc = bias;
        for (int tap = 0; tap < 9; tap++) {
            int yy = py + tap / 3 - 1, xx = px + tap % 3 - 1;
            if (yy < 0 || yy >= 32 || xx < 0 || xx >= 32) continue;
            const float* ip = sp + ((size_t)yy * 32 + xx) * 96;
            const float* wp = ws + tap * 96;
            #pragma unroll 4
            for (int ci = 0; ci < 96; ci += 4) {
                float4 v = *(const float4*)(ip + ci);
                float4 w = *(const float4*)(wp + ci);
                acc = fmaf(v.x, w.x, acc);
                acc = fmaf(v.y, w.y, acc);
                acc = fmaf(v.z, w.z, acc);
                acc = fmaf(v.w, w.w, acc);
            }
        }
        out[OFF_SEG + (size_t)n * 1024 + pix] = acc;
    }
}

// ---------------------------------------------------------------------------
// Score head
// ---------------------------------------------------------------------------
__global__ void score_kernel(const float* __restrict__ s2,
                             const float* __restrict__ sd1_w, const float* __restrict__ sd1_b,
                             const float* __restrict__ sd2_w, const float* __restrict__ sd2_b,
                             const float* __restrict__ sd3_w, const float* __restrict__ sd3_b,
                             const int* __restrict__ cls, float* __restrict__ out) {
    int n = blockIdx.x;
    int t = threadIdx.x;
    __shared__ float pooled[6144];
    __shared__ float h1[256], h2[256];
    const float* sp = s2 + (size_t)n * 32 * 32 * 96;
    for (int o = t; o < 6144; o += 256) {
        int c  = o % 96;
        int px = (o / 96) & 7;
        int py = o / 768;
        float s = 0.f;
        #pragma unroll
        for (int i = 0; i < 4; i++)
            #pragma unroll
            for (int j = 0; j < 4; j++)
                s += sp[(((size_t)(py * 4 + i)) * 32 + (px * 4 + j)) * 96 + c];
        pooled[o] = s * (1.f / 16.f);
    }
    __syncthreads();
    float a = sd1_b[t];
    #pragma unroll 4
    for (int k = 0; k < 6144; k++) a = fmaf(pooled[k], sd1_w[(size_t)k * 256 + t], a);
    h1[t] = fmaxf(a, 0.f);
    __syncthreads();
    a = sd2_b[t];
    #pragma unroll 4
    for (int k = 0; k < 256; k++) a = fmaf(h1[k], sd2_w[k * 256 + t], a);
    h2[t] = fmaxf(a, 0.f);
    __syncthreads();
    if (t == 0) {
        int c = cls[n >> 6];
        float acc = sd3_b[c];
        for (int k = 0; k < 256; k++) acc = fmaf(h2[k], sd3_w[k * 3 + c], acc);
        out[OFF_SCORE + n] = acc;
    }
}

// ---------------------------------------------------------------------------
extern "C" void kernel_launch(void* const* d_in, const int* in_sizes, int n_in,
                              void* d_out, int out_size) {
    (void)in_sizes; (void)n_in; (void)out_size;
    const float* feat0 = (const float*)d_in[0];
    const float* feat1 = (const float*)d_in[1];
    const float* feat5 = (const float*)d_in[2];
    const float* boxes = (const float*)d_in[3];
    const float* cb1_w = (const float*)d_in[4];
    const float* cb1_b = (const float*)d_in[5];
    const float* cb2_w = (const float*)d_in[6];
    const float* cb2_b = (const float*)d_in[7];
    const float* reg_w = (const float*)d_in[8];
    const float* reg_b = (const float*)d_in[9];
    const float* wt_w  = (const float*)d_in[10];
    const float* wt_b  = (const float*)d_in[11];
    const float* fc1_w = (const float*)d_in[12];
    const float* fc1_b = (const float*)d_in[13];
    const float* fc2_w = (const float*)d_in[14];
    const float* fc2_b = (const float*)d_in[15];
    const float* fc3_w = (const float*)d_in[16];
    const float* fc3_b = (const float*)d_in[17];
    const float* sc1_w = (const float*)d_in[18];
    const float* sc1_b = (const float*)d_in[19];
    const float* sc2_w = (const float*)d_in[20];
    const float* sc2_b = (const float*)d_in[21];
    const float* so_w  = (const float*)d_in[22];
    const float* so_b  = (const float*)d_in[23];
    const float* sd1_w = (const float*)d_in[24];
    const float* sd1_b = (const float*)d_in[25];
    const float* sd2_w = (const float*)d_in[26];
    const float* sd2_b = (const float*)d_in[27];
    const float* sd3_w = (const float*)d_in[28];
    const float* sd3_b = (const float*)d_in[29];
    float* out = (float*)d_out;

    // resolve device globals
    void* p;
    cudaGetSymbolAddress(&p, g_f1);  __half* f1 = (__half*)p;
    cudaGetSymbolAddress(&p, g_x1);  __half* x1 = (__half*)p;
    cudaGetSymbolAddress(&p, g_x2);  float* x2 = (float*)p;
    cudaGetSymbolAddress(&p, g_cp);  __half* cp = (__half*)p;
    cudaGetSymbolAddress(&p, g_s1);  __half* s1 = (__half*)p;
    cudaGetSymbolAddress(&p, g_s2);  float* s2 = (float*)p;
    cudaGetSymbolAddress(&p, g_w1);  __half* w1 = (__half*)p;
    cudaGetSymbolAddress(&p, g_w2);  __half* w2 = (__half*)p;
    cudaGetSymbolAddress(&p, g_w3);  __half* w3 = (__half*)p;
    cudaGetSymbolAddress(&p, g_w4);  __half* w4 = (__half*)p;
    cudaGetSymbolAddress(&p, g_cls); int* cls = (int*)p;

    constexpr int DYN128 = 2 * (CONV_ASZ + 128 * 80);   // 40960
    constexpr int DYN96  = 2 * (CONV_ASZ + 96 * 80);    // 35840
    cudaFuncSetAttribute(conv3x3_h<128, 128, true,  2>,
                         cudaFuncAttributeMaxDynamicSharedMemorySize, DYN128);
    cudaFuncSetAttribute(conv3x3_h<256, 128, false, 2>,
                         cudaFuncAttributeMaxDynamicSharedMemorySize, DYN128);
    cudaFuncSetAttribute(conv3x3_h<64, 96, true,  3>,
                         cudaFuncAttributeMaxDynamicSharedMemorySize, DYN96);
    cudaFuncSetAttribute(conv3x3_h<96, 96, false, 3>,
                         cudaFuncAttributeMaxDynamicSharedMemorySize, DYN96);

    // classification first (selection depends on cls)
    cls_kernel<<<4, 256>>>(feat5, fc1_w, fc1_b, fc2_w, fc2_b, fc3_w, fc3_b,
                           out + OFF_PREDCLS, cls);

    // operand prep
    wprep16_kernel<<<(294912 + 255) / 256, 256>>>(cb1_w, w1, 1152, 256);
    wprep16_kernel<<<(589824 + 255) / 256, 256>>>(cb2_w, w2, 2304, 256);
    wprep16_kernel<<<(55296 + 255) / 256, 256>>>(sc1_w, w3, 576, 96);
    wprep16_kernel<<<(82944 + 255) / 256, 256>>>(sc2_w, w4, 864, 96);
    fcvt16_kernel<<<(33554432 / 4 + 255) / 256, 256>>>(feat1, f1, 33554432);

    // crop + segmentation branch
    crop_kernel<<<256, 256>>>(feat0, boxes, cp);
    conv3x3_h<64, 96, true, 3><<<dim3(2, 4, 256), 128, DYN96>>>(
        cp, w3, sc1_b, nullptr, s1, 32, 32, 96, 1);
    conv3x3_h<96, 96, false, 3><<<dim3(2, 4, 256), 128, DYN96>>>(
        s1, w4, sc2_b, s2, nullptr, 32, 32, 96, 1);
    sosel_kernel<<<256, 256>>>(s2, so_w, so_b, cls, out);
    score_kernel<<<256, 256>>>(s2, sd1_w, sd1_b, sd2_w, sd2_b, sd3_w, sd3_b, cls, out);

    // regression branch
    conv3x3_h<128, 128, true, 2><<<dim3(16, 32, 8), 128, DYN128>>>(
        f1, w1, cb1_b, nullptr, x1, 256, 256, 256, 2);
    conv3x3_h<256, 128, false, 2><<<dim3(16, 32, 8), 128, DYN128>>>(
        x1, w2, cb2_b, x2, nullptr, 256, 256, 256, 2);
    regsel_kernel<<<dim3(16, 16, 4), 256>>>(x2, reg_w, reg_b, wt_w, wt_b, cls, out);
}

// round 12
// speedup vs baseline: 3.1044x; 1.0822x over previous
#include <cuda_runtime.h>
#include <cuda_fp16.h>
#include <math.h>
#include <stdint.h>

typedef unsigned long long u64;

// ---------------------------------------------------------------------------
// Output layout (tuple flattened in order)
// ---------------------------------------------------------------------------
#define OFF_OFFSETS 0
#define OFF_SIZES   524288
#define OFF_WEIGHTS 1048576
#define OFF_PREDCLS 1310720
#define OFF_SEG     1310732
#define OFF_SCORE   1572876

// Scratch (device globals; no allocation allowed)
__device__ __half g_f1[33554432];     // feat1 fp16
__device__ __half g_x1[67108864];     // conv1 out fp16
__device__ float  g_x2[67108864];     // conv2 out fp32
__device__ __half g_cp[16777216];     // crops fp16
__device__ __half g_s1[25165824];     // sc1 out fp16
__device__ float  g_s2[25165824];     // sc2 out fp32
// fragment-order fp16 weights (b32-packed)
__device__ __align__(16) __half g_w1[294912];
__device__ __align__(16) __half g_w2[589824];
__device__ __align__(16) __half g_w3[55296];
__device__ __align__(16) __half g_w4[82944];
__device__ int g_cls[4];

// ---------------------------------------------------------------------------
// PTX helpers (arch-generic sm_80+)
// ---------------------------------------------------------------------------
__device__ __forceinline__ uint32_t smem_u32(const void* p) {
    uint32_t a;
    asm("{ .reg .u64 t; cvta.to.shared.u64 t, %1; cvt.u32.u64 %0, t; }"
        : "=r"(a) : "l"(p));
    return a;
}
__device__ __forceinline__ void ldsm_x4(uint32_t* r, uint32_t a) {
    asm volatile("ldmatrix.sync.aligned.m8n8.x4.shared.b16 {%0,%1,%2,%3}, [%4];"
                 : "=r"(r[0]), "=r"(r[1]), "=r"(r[2]), "=r"(r[3]) : "r"(a));
}
__device__ __forceinline__ void mma_f16(float* d, const uint32_t* a, const uint32_t* b) {
    asm volatile("mma.sync.aligned.m16n8k16.row.col.f32.f16.f16.f32 "
                 "{%0,%1,%2,%3}, {%4,%5,%6,%7}, {%8,%9}, {%0,%1,%2,%3};"
                 : "+f"(d[0]), "+f"(d[1]), "+f"(d[2]), "+f"(d[3])
                 : "r"(a[0]), "r"(a[1]), "r"(a[2]), "r"(a[3]),
                   "r"(b[0]), "r"(b[1]));
}
__device__ __forceinline__ void cpa16(uint32_t dst, const void* src, bool ok) {
    int sz = ok ? 16 : 0;
    asm volatile("cp.async.cg.shared.global [%0], [%1], 16, %2;"
                 :: "r"(dst), "l"(src), "r"(sz) : "memory");
}
__device__ __forceinline__ void cp_commit() {
    asm volatile("cp.async.commit_group;" ::: "memory");
}
template <int N>
__device__ __forceinline__ void cp_wait() {
    asm volatile("cp.async.wait_group %0;" :: "n"(N) : "memory");
}

// ---------------------------------------------------------------------------
// Operand preparation kernels
// ---------------------------------------------------------------------------
// fp32 -> fp16 (elementwise, 4-wide)
__global__ void fcvt16_kernel(const float* __restrict__ src,
                              __half* __restrict__ o, int n) {
    int i = blockIdx.x * blockDim.x + threadIdx.x;
    if (i * 4 >= n) return;
    float4 v = *(const float4*)(src + i * 4);
    __half2 a = __halves2half2(__float2half_rn(v.x), __float2half_rn(v.y));
    __half2 b = __halves2half2(__float2half_rn(v.z), __float2half_rn(v.w));
    *(uint2*)(o + i * 4) = make_uint2(*(uint32_t*)&a, *(uint32_t*)&b);
}

// weights [K9][COUT] fp32 -> mma B-fragment order, b32-packed:
//   idx = ((((nt*KH + kh)*2 + nw)*32 + lane)*NF + ni)*2 + r
//   b32 = half2( W[k][co], W[k+1][co] )
//   k = kh*16 + r*8 + (lane&3)*2;  co = nt*CT + nw*(CT/2) + ni*8 + (lane>>2)
__global__ void wfrag_kernel(const float* __restrict__ w,
                             uint32_t* __restrict__ o,
                             int K9, int COUT, int CT, int NF, int KH, int total) {
    int i = blockIdx.x * blockDim.x + threadIdx.x;
    if (i >= total) return;
    int r  = i & 1;
    int ni = (i >> 1) % NF;
    int l  = (i >> 1) / NF % 32;
    int nw = (i >> 1) / NF / 32 & 1;
    int kh = (i >> 1) / NF / 64 % KH;
    int nt = (i >> 1) / NF / 64 / KH;
    int k  = kh * 16 + r * 8 + (l & 3) * 2;
    int co = nt * CT + nw * (CT / 2) + ni * 8 + (l >> 2);
    __half2 v = __halves2half2(__float2half_rn(w[(size_t)k * COUT + co]),
                               __float2half_rn(w[(size_t)(k + 1) * COUT + co]));
    o[i] = *(uint32_t*)&v;
}

// ---------------------------------------------------------------------------
// FP16 tensor-core 3x3 SAME conv: A fp16 via cp.async+ldmatrix,
// W fp16 preloaded in fragment order via direct LDG (128b when NF%4==0,
// else 64b — alignment-safe for NF=6), fp32 accumulate.
// CTA: 128 thr (2M x 2N warps). Tile M=128px (8y x 16x) x N=COUT_TILE.
// Warp tile 64 x COUT_TILE/2. K chunks of 32 channels. Double-buffered A smem.
// grid: (W/16, H/8, nimg * NT)
// ---------------------------------------------------------------------------
#define CONV_ASZ 10240   // 128 rows * 80B

template <int CIN, int COUT_TILE, bool OUT_HALF, int MAXB>
__global__ __launch_bounds__(128, MAXB)
void conv3x3_h(const __half* __restrict__ in,
               const uint32_t* __restrict__ wfrag,
               const float* __restrict__ bias,
               float* __restrict__ outf, __half* __restrict__ outh,
               int H, int W, int COUT, int NT) {
    constexpr int K9 = 9 * CIN;
    constexpr int KCH = K9 / 32;
    constexpr int KH = K9 / 16;
    constexpr int NF = COUT_TILE / 16;       // 8 or 6 (even)
    extern __shared__ char sm[];
    const uint32_t sb = smem_u32(sm);
    __shared__ float sbias[COUT_TILE];

    int t = threadIdx.x, warp = t >> 5, lane = t & 31;
    int img = blockIdx.z / NT, ntile = blockIdx.z % NT;
    int cobase = ntile * COUT_TILE;
    int x0 = blockIdx.x * 16, y0 = blockIdx.y * 8;

    if (t < COUT_TILE) sbias[t] = bias[cobase + t];

    int lpy = t >> 4, lpx = t & 15;          // A: 1 thread per pixel
    int wm = warp & 1, nw = warp >> 1;
    int nbase = nw * (COUT_TILE / 2);

    // per-lane B fragment base (in b32 units):
    //   idx = ((((nt*KH + kh)*2 + nw)*32 + lane) * (2*NF)) + ni*2 + r
    const uint32_t* wbase = wfrag
        + ((size_t)((ntile * KH) * 2 + nw) * 32 + lane) * (2 * NF);
    const size_t whstep = (size_t)128 * NF;  // per-kh step: 2*32*2*NF b32

    float acc[4][NF][4];
    #pragma unroll
    for (int i = 0; i < 4; i++)
        #pragma unroll
        for (int j = 0; j < NF; j++)
            #pragma unroll
            for (int q = 0; q < 4; q++) acc[i][j][q] = 0.f;

    const __half* img0 = in + (size_t)img * H * W * CIN;

    auto issue = [&](int kc, int buf) {
        int kbase = kc * 32;
        int tap = kbase / CIN;
        int dy = tap / 3 - 1, dx = tap % 3 - 1;
        int gy = y0 + lpy + dy, gx = x0 + lpx + dx;
        bool aok = (gy >= 0 && gy < H && gx >= 0 && gx < W);
        int cy = min(max(gy, 0), H - 1), cx = min(max(gx, 0), W - 1);
        size_t ab = ((size_t)cy * W + cx) * CIN + (kbase % CIN);
        uint32_t AO = sb + buf * CONV_ASZ;
        uint32_t arow = t * 80;
        #pragma unroll
        for (int j = 0; j < 4; j++)
            cpa16(AO + arow + j * 16, img0 + ab + j * 8, aok);
        cp_commit();
    };

    issue(0, 0);

    for (int kc = 0; kc < KCH; kc++) {
        int buf = kc & 1;
        if (kc + 1 < KCH) { issue(kc + 1, buf ^ 1); cp_wait<1>(); }
        else              { cp_wait<0>(); }
        __syncthreads();

        uint32_t AO = sb + buf * CONV_ASZ;

        #pragma unroll
        for (int k16 = 0; k16 < 2; k16++) {
            // B frags via direct global loads (weights are L2-resident)
            const uint32_t* wp = wbase + (size_t)(kc * 2 + k16) * whstep;
            uint32_t bh[NF][2];
            if constexpr (NF % 4 == 0) {
                #pragma unroll
                for (int j = 0; j < NF / 2; j++) {
                    uint4 v = ((const uint4*)wp)[j];
                    bh[2 * j][0] = v.x;     bh[2 * j][1] = v.y;
                    bh[2 * j + 1][0] = v.z; bh[2 * j + 1][1] = v.w;
                }
            } else {
                #pragma unroll
                for (int j = 0; j < NF; j++) {
                    uint2 v = ((const uint2*)wp)[j];
                    bh[j][0] = v.x; bh[j][1] = v.y;
                }
            }
            uint32_t ah[4][4];
            #pragma unroll
            for (int mi = 0; mi < 4; mi++) {
                uint32_t rowb = (uint32_t)((wm * 64 + mi * 16 + (lane & 15)) * 80
                                           + (k16 * 16 + (lane >> 4) * 8) * 2);
                ldsm_x4(ah[mi], AO + rowb);
            }
            #pragma unroll
            for (int mi = 0; mi < 4; mi++)
                #pragma unroll
                for (int ni = 0; ni < NF; ni++)
                    mma_f16(acc[mi][ni], ah[mi], bh[ni]);
        }
        __syncthreads();
    }

    // ---- epilogue: bias + relu; write fp16 or fp32 ----
    #pragma unroll
    for (int mi = 0; mi < 4; mi++) {
        int p0 = wm * 64 + mi * 16 + (lane >> 2);
        #pragma unroll
        for (int half_ = 0; half_ < 2; half_++) {
            int p = p0 + half_ * 8;
            int gy = y0 + (p >> 4), gx = x0 + (p & 15);
            size_t pixoff = ((size_t)img * H * W + (size_t)gy * W + gx) * COUT + cobase;
            #pragma unroll
            for (int ni = 0; ni < NF; ni++) {
                int cl = nbase + ni * 8 + (lane & 3) * 2;
                float r0 = acc[mi][ni][half_ * 2 + 0] + sbias[cl];
                float r1 = acc[mi][ni][half_ * 2 + 1] + sbias[cl + 1];
                r0 = fmaxf(r0, 0.f); r1 = fmaxf(r1, 0.f);
                if (OUT_HALF) {
                    __half2 hh = __halves2half2(__float2half_rn(r0), __float2half_rn(r1));
                    *(uint32_t*)(outh + pixoff + cl) = *(uint32_t*)&hh;
                } else {
                    *(float2*)(outf + pixoff + cl) = make_float2(r0, r1);
                }
            }
        }
    }
}

// ---------------------------------------------------------------------------
// Classification head
// ---------------------------------------------------------------------------
__global__ void cls_kernel(const float* __restrict__ feat5,
                           const float* __restrict__ fc1_w, const float* __restrict__ fc1_b,
                           const float* __restrict__ fc2_w, const float* __restrict__ fc2_b,
                           const float* __restrict__ fc3_w, const float* __restrict__ fc3_b,
                           float* __restrict__ out_predcls, int* __restrict__ cls) {
    int b = blockIdx.x;
    int t = threadIdx.x;
    __shared__ float g0[256], g1[256], lg[3];
    const float* f = feat5 + (size_t)b * 16 * 16 * 256;
    float s = 0.f;
    #pragma unroll 4
    for (int p = 0; p < 256; p++) s += f[p * 256 + t];
    g0[t] = s * (1.0f / 256.0f);
    __syncthreads();
    float a = fc1_b[t];
    #pragma unroll 4
    for (int k = 0; k < 256; k++) a = fmaf(g0[k], fc1_w[k * 256 + t], a);
    g1[t] = fmaxf(a, 0.f);
    __syncthreads();
    a = fc2_b[t];
    #pragma unroll 4
    for (int k = 0; k < 256; k++) a = fmaf(g1[k], fc2_w[k * 256 + t], a);
    g0[t] = fmaxf(a, 0.f);
    __syncthreads();
    if (t < 3) {
        a = fc3_b[t];
        for (int k = 0; k < 256; k++) a = fmaf(g0[k], fc3_w[k * 3 + t], a);
        lg[t] = a;
    }
    __syncthreads();
    if (t == 0) {
        float m = fmaxf(lg[0], fmaxf(lg[1], lg[2]));
        float e0 = expf(lg[0] - m), e1 = expf(lg[1] - m), e2 = expf(lg[2] - m);
        float inv = 1.f / (e0 + e1 + e2);
        out_predcls[b * 3 + 0] = e0 * inv;
        out_predcls[b * 3 + 1] = e1 * inv;
        out_predcls[b * 3 + 2] = e2 * inv;
        int c = 0;
        if (lg[1] > lg[0]) c = 1;
        if (lg[2] > lg[c]) c = 2;
        cls[b] = c;
    }
}

// ---------------------------------------------------------------------------
// Fused reg/wt conv with class selection (5 channels, fp32)
// ---------------------------------------------------------------------------
__global__ void regsel_kernel(const float* __restrict__ x,
                              const float* __restrict__ reg_w, const float* __restrict__ reg_b,
                              const float* __restrict__ wt_w,  const float* __restrict__ wt_b,
                              const int* __restrict__ cls, float* __restrict__ out) {
    int b = blockIdx.z;
    int c = cls[b];
    __shared__ __align__(16) float ws[9 * 256 * 5];
    int t = threadIdx.x;
    for (int i = t; i < 9 * 256; i += 256) {
        const float* rp = reg_w + (size_t)i * 12 + 4 * c;
        float* wp = ws + i * 5;
        wp[0] = rp[0]; wp[1] = rp[1]; wp[2] = rp[2]; wp[3] = rp[3];
        wp[4] = wt_w[(size_t)i * 3 + c];
    }
    __syncthreads();
    int px = blockIdx.x * 16 + (t & 15);
    int py = blockIdx.y * 16 + (t >> 4);
    float a0 = reg_b[4 * c], a1 = reg_b[4 * c + 1], a2 = reg_b[4 * c + 2],
          a3 = reg_b[4 * c + 3], a4 = wt_b[c];
    const float* xi = x + (size_t)b * 256 * 256 * 256;
    for (int tap = 0; tap < 9; tap++) {
        int yy = py + tap / 3 - 1, xx = px + tap % 3 - 1;
        if (yy < 0 || yy >= 256 || xx < 0 || xx >= 256) continue;
        const float* ip = xi + ((size_t)yy * 256 + xx) * 256;
        const float* wp = ws + tap * 256 * 5;
        #pragma unroll 2
        for (int ci = 0; ci < 256; ci += 4) {
            float4 v = *(const float4*)(ip + ci);
            float wl[20];
            const float4* w4 = (const float4*)(wp + ci * 5);
            #pragma unroll
            for (int q = 0; q < 5; q++) ((float4*)wl)[q] = w4[q];
            a0 = fmaf(v.x, wl[0], a0);  a1 = fmaf(v.x, wl[1], a1);
            a2 = fmaf(v.x, wl[2], a2);  a3 = fmaf(v.x, wl[3], a3);  a4 = fmaf(v.x, wl[4], a4);
            a0 = fmaf(v.y, wl[5], a0);  a1 = fmaf(v.y, wl[6], a1);
            a2 = fmaf(v.y, wl[7], a2);  a3 = fmaf(v.y, wl[8], a3);  a4 = fmaf(v.y, wl[9], a4);
            a0 = fmaf(v.z, wl[10], a0); a1 = fmaf(v.z, wl[11], a1);
            a2 = fmaf(v.z, wl[12], a2); a3 = fmaf(v.z, wl[13], a3); a4 = fmaf(v.z, wl[14], a4);
            a0 = fmaf(v.w, wl[15], a0); a1 = fmaf(v.w, wl[16], a1);
            a2 = fmaf(v.w, wl[17], a2); a3 = fmaf(v.w, wl[18], a3); a4 = fmaf(v.w, wl[19], a4);
        }
    }
    size_t pix = ((size_t)b * 256 + py) * 256 + px;
    out[OFF_OFFSETS + pix * 2 + 0] = a0;
    out[OFF_OFFSETS + pix * 2 + 1] = a1;
    out[OFF_SIZES   + pix * 2 + 0] = a2;
    out[OFF_SIZES   + pix * 2 + 1] = a3;
    out[OFF_WEIGHTS + pix] = a4;
}

// ---------------------------------------------------------------------------
// Bilinear crop -> fp16
// ---------------------------------------------------------------------------
__global__ void crop_kernel(const float* __restrict__ feat0,
                            const float* __restrict__ boxes,
                            __half* __restrict__ cp) {
    int n = blockIdx.x;
    int b = n >> 6;
    const int H = 512, W = 512, C = 64;
    __shared__ int sy0[32], sx0[32];
    __shared__ float swy[32], swx[32];
    const float* bx = boxes + (size_t)n * 4;
    float y1 = bx[0], x1 = bx[1], y2 = bx[2], x2 = bx[3];
    int t = threadIdx.x;
    if (t < 32) {
        float tt = (float)t / 31.0f;
        float ys = y1 * (H - 1) + tt * (y2 - y1) * (H - 1);
        int yy0 = (int)floorf(ys);
        yy0 = min(max(yy0, 0), H - 2);
        sy0[t] = yy0; swy[t] = ys - (float)yy0;
    } else if (t < 64) {
        int i = t - 32;
        float tt = (float)i / 31.0f;
        float xs = x1 * (W - 1) + tt * (x2 - x1) * (W - 1);
        int xx0 = (int)floorf(xs);
        xx0 = min(max(xx0, 0), W - 2);
        sx0[i] = xx0; swx[i] = xs - (float)xx0;
    }
    __syncthreads();
    const float* f = feat0 + (size_t)b * H * W * C;
    size_t obase = (size_t)n * 32 * 32 * C;
    for (int idx = t; idx < 32 * 32 * C; idx += blockDim.x) {
        int c  = idx & 63;
        int ix = (idx >> 6) & 31;
        int iy = idx >> 11;
        int yy0 = sy0[iy], xx0 = sx0[ix];
        float wy = swy[iy], wx = swx[ix];
        const float* p00 = f + ((size_t)yy0 * W + xx0) * C + c;
        float v00 = p00[0], v01 = p00[C], v10 = p00[(size_t)W * C], v11 = p00[(size_t)W * C + C];
        float top = v00 * (1.f - wx) + v01 * wx;
        float bot = v10 * (1.f - wx) + v11 * wx;
        float v = top * (1.f - wy) + bot * wy;
        cp[obase + idx] = __float2half_rn(v);
    }
}

// ---------------------------------------------------------------------------
// so conv with class selection (1 channel, fp32)
// ---------------------------------------------------------------------------
__global__ void sosel_kernel(const float* __restrict__ s2,
                             const float* __restrict__ so_w, const float* __restrict__ so_b,
                             const int* __restrict__ cls, float* __restrict__ out) {
    int n = blockIdx.x;
    int c = cls[n >> 6];
    __shared__ __align__(16) float ws[9 * 96];
    int t = threadIdx.x;
    for (int i = t; i < 864; i += 256) ws[i] = so_w[(size_t)i * 3 + c];
    __syncthreads();
    float bias = so_b[c];
    const float* sp = s2 + (size_t)n * 32 * 32 * 96;
    for (int pix = t; pix < 1024; pix += 256) {
        int py = pix >> 5, px = pix & 31;
        float acc = bias;
        for (int tap = 0; tap < 9; tap++) {
            int yy = py + tap / 3 - 1, xx = px + tap % 3 - 1;
            if (yy < 0 || yy >= 32 || xx < 0 || xx >= 32) continue;
            const float* ip = sp + ((size_t)yy * 32 + xx) * 96;
            const float* wp = ws + tap * 96;
            #pragma unroll 4
            for (int ci = 0; ci < 96; ci += 4) {
                float4 v = *(const float4*)(ip + ci);
                float4 w = *(const float4*)(wp + ci);
                acc = fmaf(v.x, w.x, acc);
                acc = fmaf(v.y, w.y, acc);
                acc = fmaf(v.z, w.z, acc);
                acc = fmaf(v.w, w.w, acc);
            }
        }
        out[OFF_SEG + (size_t)n * 1024 + pix] = acc;
    }
}

// ---------------------------------------------------------------------------
// Score head
// ---------------------------------------------------------------------------
__global__ void score_kernel(const float* __restrict__ s2,
                             const float* __restrict__ sd1_w, const float* __restrict__ sd1_b,
                             const float* __restrict__ sd2_w, const float* __restrict__ sd2_b,
                             const float* __restrict__ sd3_w, const float* __restrict__ sd3_b,
                             const int* __restrict__ cls, float* __restrict__ out) {
    int n = blockIdx.x;
    int t = threadIdx.x;
    __shared__ float pooled[6144];
    __shared__ float h1[256], h2[256];
    const float* sp = s2 + (size_t)n * 32 * 32 * 96;
    for (int o = t; o < 6144; o += 256) {
        int c  = o % 96;
        int px = (o / 96) & 7;
        int py = o / 768;
        float s = 0.f;
        #pragma unroll
        for (int i = 0; i < 4; i++)
            #pragma unroll
            for (int j = 0; j < 4; j++)
                s += sp[(((size_t)(py * 4 + i)) * 32 + (px * 4 + j)) * 96 + c];
        pooled[o] = s * (1.f / 16.f);
    }
    __syncthreads();
    float a = sd1_b[t];
    #pragma unroll 4
    for (int k = 0; k < 6144; k++) a = fmaf(pooled[k], sd1_w[(size_t)k * 256 + t], a);
    h1[t] = fmaxf(a, 0.f);
    __syncthreads();
    a = sd2_b[t];
    #pragma unroll 4
    for (int k = 0; k < 256; k++) a = fmaf(h1[k], sd2_w[k * 256 + t], a);
    h2[t] = fmaxf(a, 0.f);
    __syncthreads();
    if (t == 0) {
        int c = cls[n >> 6];
        float acc = sd3_b[c];
        for (int k = 0; k < 256; k++) acc = fmaf(h2[k], sd3_w[k * 3 + c], acc);
        out[OFF_SCORE + n] = acc;
    }
}

// ---------------------------------------------------------------------------
extern "C" void kernel_launch(void* const* d_in, const int* in_sizes, int n_in,
                              void* d_out, int out_size) {
    (void)in_sizes; (void)n_in; (void)out_size;
    const float* feat0 = (const float*)d_in[0];
    const float* feat1 = (const float*)d_in[1];
    const float* feat5 = (const float*)d_in[2];
    const float* boxes = (const float*)d_in[3];
    const float* cb1_w = (const float*)d_in[4];
    const float* cb1_b = (const float*)d_in[5];
    const float* cb2_w = (const float*)d_in[6];
    const float* cb2_b = (const float*)d_in[7];
    const float* reg_w = (const float*)d_in[8];
    const float* reg_b = (const float*)d_in[9];
    const float* wt_w  = (const float*)d_in[10];
    const float* wt_b  = (const float*)d_in[11];
    const float* fc1_w = (const float*)d_in[12];
    const float* fc1_b = (const float*)d_in[13];
    const float* fc2_w = (const float*)d_in[14];
    const float* fc2_b = (const float*)d_in[15];
    const float* fc3_w = (const float*)d_in[16];
    const float* fc3_b = (const float*)d_in[17];
    const float* sc1_w = (const float*)d_in[18];
    const float* sc1_b = (const float*)d_in[19];
    const float* sc2_w = (const float*)d_in[20];
    const float* sc2_b = (const float*)d_in[21];
    const float* so_w  = (const float*)d_in[22];
    const float* so_b  = (const float*)d_in[23];
    const float* sd1_w = (const float*)d_in[24];
    const float* sd1_b = (const float*)d_in[25];
    const float* sd2_w = (const float*)d_in[26];
    const float* sd2_b = (const float*)d_in[27];
    const float* sd3_w = (const float*)d_in[28];
    const float* sd3_b = (const float*)d_in[29];
    float* out = (float*)d_out;

    // resolve device globals
    void* p;
    cudaGetSymbolAddress(&p, g_f1);  __half* f1 = (__half*)p;
    cudaGetSymbolAddress(&p, g_x1);  __half* x1 = (__half*)p;
    cudaGetSymbolAddress(&p, g_x2);  float* x2 = (float*)p;
    cudaGetSymbolAddress(&p, g_cp);  __half* cp = (__half*)p;
    cudaGetSymbolAddress(&p, g_s1);  __half* s1 = (__half*)p;
    cudaGetSymbolAddress(&p, g_s2);  float* s2 = (float*)p;
    cudaGetSymbolAddress(&p, g_w1);  uint32_t* w1 = (uint32_t*)p;
    cudaGetSymbolAddress(&p, g_w2);  uint32_t* w2 = (uint32_t*)p;
    cudaGetSymbolAddress(&p, g_w3);  uint32_t* w3 = (uint32_t*)p;
    cudaGetSymbolAddress(&p, g_w4);  uint32_t* w4 = (uint32_t*)p;
    cudaGetSymbolAddress(&p, g_cls); int* cls = (int*)p;

    constexpr int DYN = 2 * CONV_ASZ;   // 20480 (A only, double-buffered)

    // classification first (selection depends on cls)
    cls_kernel<<<4, 256>>>(feat5, fc1_w, fc1_b, fc2_w, fc2_b, fc3_w, fc3_b,
                           out + OFF_PREDCLS, cls);

    // operand prep: weights into fragment order; feat1 -> fp16
    // totals (b32): cb1: 2*72*64*8*2=147456; cb2: 2*144*64*8*2=294912
    //               sc1: 1*36*64*6*2=27648;  sc2: 1*54*64*6*2=41472
    wfrag_kernel<<<(147456 + 255) / 256, 256>>>(cb1_w, w1, 1152, 256, 128, 8, 72, 147456);
    wfrag_kernel<<<(294912 + 255) / 256, 256>>>(cb2_w, w2, 2304, 256, 128, 8, 144, 294912);
    wfrag_kernel<<<(27648 + 255) / 256, 256>>>(sc1_w, w3, 576, 96, 96, 6, 36, 27648);
    wfrag_kernel<<<(41472 + 255) / 256, 256>>>(sc2_w, w4, 864, 96, 96, 6, 54, 41472);
    fcvt16_kernel<<<(33554432 / 4 + 255) / 256, 256>>>(feat1, f1, 33554432);

    // crop + segmentation branch
    crop_kernel<<<256, 256>>>(feat0, boxes, cp);
    conv3x3_h<64, 96, true, 3><<<dim3(2, 4, 256), 128, DYN>>>(
        cp, w3, sc1_b, nullptr, s1, 32, 32, 96, 1);
    conv3x3_h<96, 96, false, 3><<<dim3(2, 4, 256), 128, DYN>>>(
        s1, w4, sc2_b, s2, nullptr, 32, 32, 96, 1);
    sosel_kernel<<<256, 256>>>(s2, so_w, so_b, cls, out);
    score_kernel<<<256, 256>>>(s2, sd1_w, sd1_b, sd2_w, sd2_b, sd3_w, sd3_b, cls, out);

    // regression branch
    conv3x3_h<128, 128, true, 2><<<dim3(16, 32, 8), 128, DYN>>>(
        f1, w1, cb1_b, nullptr, x1, 256, 256, 256, 2);
    conv3x3_h<256, 128, false, 2><<<dim3(16, 32, 8), 128, DYN>>>(
        x1, w2, cb2_b, x2, nullptr, 256, 256, 256, 2);
    regsel_kernel<<<dim3(16, 16, 4), 256>>>(x2, reg_w, reg_b, wt_w, wt_b, cls, out);
}

// round 13
// speedup vs baseline: 3.6950x; 1.1903x over previous
#include <cuda_runtime.h>
#include <cuda_fp16.h>
#include <math.h>
#include <stdint.h>

typedef unsigned long long u64;

// ---------------------------------------------------------------------------
// Output layout (tuple flattened in order)
// ---------------------------------------------------------------------------
#define OFF_OFFSETS 0
#define OFF_SIZES   524288
#define OFF_WEIGHTS 1048576
#define OFF_PREDCLS 1310720
#define OFF_SEG     1310732
#define OFF_SCORE   1572876

// Scratch (device globals; no allocation allowed)
__device__ __half g_f1[33554432];     // feat1 fp16
__device__ __half g_x1[67108864];     // conv1 out fp16
__device__ float  g_x2[67108864];     // conv2 out fp32
__device__ __half g_cp[16777216];     // crops fp16
__device__ __half g_s1[25165824];     // sc1 out fp16
__device__ float  g_s2[25165824];     // sc2 out fp32
// fragment-order fp16 weights (b32-packed)
__device__ __align__(16) __half g_w1[294912];
__device__ __align__(16) __half g_w2[589824];
__device__ __align__(16) __half g_w3[55296];
__device__ __align__(16) __half g_w4[82944];
__device__ int g_cls[4];

// ---------------------------------------------------------------------------
// PTX helpers (arch-generic sm_80+)
// ---------------------------------------------------------------------------
__device__ __forceinline__ uint32_t smem_u32(const void* p) {
    uint32_t a;
    asm("{ .reg .u64 t; cvta.to.shared.u64 t, %1; cvt.u32.u64 %0, t; }"
        : "=r"(a) : "l"(p));
    return a;
}
__device__ __forceinline__ void ldsm_x4(uint32_t* r, uint32_t a) {
    asm volatile("ldmatrix.sync.aligned.m8n8.x4.shared.b16 {%0,%1,%2,%3}, [%4];"
                 : "=r"(r[0]), "=r"(r[1]), "=r"(r[2]), "=r"(r[3]) : "r"(a));
}
__device__ __forceinline__ void mma_f16(float* d, const uint32_t* a, const uint32_t* b) {
    asm volatile("mma.sync.aligned.m16n8k16.row.col.f32.f16.f16.f32 "
                 "{%0,%1,%2,%3}, {%4,%5,%6,%7}, {%8,%9}, {%0,%1,%2,%3};"
                 : "+f"(d[0]), "+f"(d[1]), "+f"(d[2]), "+f"(d[3])
                 : "r"(a[0]), "r"(a[1]), "r"(a[2]), "r"(a[3]),
                   "r"(b[0]), "r"(b[1]));
}
__device__ __forceinline__ void cpa16(uint32_t dst, const void* src, bool ok) {
    int sz = ok ? 16 : 0;
    asm volatile("cp.async.cg.shared.global [%0], [%1], 16, %2;"
                 :: "r"(dst), "l"(src), "r"(sz) : "memory");
}
__device__ __forceinline__ void cp_commit() {
    asm volatile("cp.async.commit_group;" ::: "memory");
}
template <int N>
__device__ __forceinline__ void cp_wait() {
    asm volatile("cp.async.wait_group %0;" :: "n"(N) : "memory");
}

// ---------------------------------------------------------------------------
// Operand preparation kernels
// ---------------------------------------------------------------------------
// fp32 -> fp16 (elementwise, 4-wide)
__global__ void fcvt16_kernel(const float* __restrict__ src,
                              __half* __restrict__ o, int n) {
    int i = blockIdx.x * blockDim.x + threadIdx.x;
    if (i * 4 >= n) return;
    float4 v = *(const float4*)(src + i * 4);
    __half2 a = __halves2half2(__float2half_rn(v.x), __float2half_rn(v.y));
    __half2 b = __halves2half2(__float2half_rn(v.z), __float2half_rn(v.w));
    *(uint2*)(o + i * 4) = make_uint2(*(uint32_t*)&a, *(uint32_t*)&b);
}

// weights [K9][COUT] fp32 -> mma B-fragment order, b32-packed:
//   idx = ((((nt*KH + kh)*2 + nw)*32 + lane)*NF + ni)*2 + r
//   b32 = half2( W[k][co], W[k+1][co] )
//   k = kh*16 + r*8 + (lane&3)*2;  co = nt*CT + nw*(CT/2) + ni*8 + (lane>>2)
__global__ void wfrag_kernel(const float* __restrict__ w,
                             uint32_t* __restrict__ o,
                             int K9, int COUT, int CT, int NF, int KH, int total) {
    int i = blockIdx.x * blockDim.x + threadIdx.x;
    if (i >= total) return;
    int r  = i & 1;
    int ni = (i >> 1) % NF;
    int l  = (i >> 1) / NF % 32;
    int nw = (i >> 1) / NF / 32 & 1;
    int kh = (i >> 1) / NF / 64 % KH;
    int nt = (i >> 1) / NF / 64 / KH;
    int k  = kh * 16 + r * 8 + (l & 3) * 2;
    int co = nt * CT + nw * (CT / 2) + ni * 8 + (l >> 2);
    __half2 v = __halves2half2(__float2half_rn(w[(size_t)k * COUT + co]),
                               __float2half_rn(w[(size_t)(k + 1) * COUT + co]));
    o[i] = *(uint32_t*)&v;
}

// ---------------------------------------------------------------------------
// FP16 tensor-core 3x3 SAME conv, HALO-TILED A staging:
// per 32-channel cin-chunk, load the (8+2)x(16+2)=180-pixel halo window once
// (80B pitch, conflict-free), then run all 9 taps x 2 k16 from shifted smem
// addresses. W fp16 in fragment order via direct LDG. fp32 accumulate.
// CTA: 128 thr (2M x 2N warps). Tile M=128px (8y x 16x) x N=COUT_TILE.
// grid: (W/16, H/8, nimg * NT)
// ---------------------------------------------------------------------------
#define HALO_SZ (180 * 80)   // 14400 B per buffer

template <int CIN, int COUT_TILE, bool OUT_HALF, int MAXB>
__global__ __launch_bounds__(128, MAXB)
void conv3x3_halo(const __half* __restrict__ in,
                  const uint32_t* __restrict__ wfrag,
                  const float* __restrict__ bias,
                  float* __restrict__ outf, __half* __restrict__ outh,
                  int H, int W, int COUT, int NT) {
    constexpr int CC = CIN / 32;             // cin chunks
    constexpr int KH = 9 * CIN / 16;
    constexpr int NF = COUT_TILE / 16;       // 8 or 6 (even)
    extern __shared__ char sm[];
    const uint32_t sb = smem_u32(sm);
    __shared__ float sbias[COUT_TILE];

    int t = threadIdx.x, warp = t >> 5, lane = t & 31;
    int img = blockIdx.z / NT, ntile = blockIdx.z % NT;
    int cobase = ntile * COUT_TILE;
    int x0 = blockIdx.x * 16, y0 = blockIdx.y * 8;

    if (t < COUT_TILE) sbias[t] = bias[cobase + t];

    int wm = warp & 1, nw = warp >> 1;
    int nbase = nw * (COUT_TILE / 2);

    // per-lane B fragment base (b32): ((((nt*KH+kh)*2+nw)*32+lane)*(2*NF))
    const uint32_t* wbase = wfrag
        + ((size_t)((ntile * KH) * 2 + nw) * 32 + lane) * (2 * NF);
    const size_t whstep = (size_t)128 * NF;  // per-kh step in b32

    float acc[4][NF][4];
    #pragma unroll
    for (int i = 0; i < 4; i++)
        #pragma unroll
        for (int j = 0; j < NF; j++)
            #pragma unroll
            for (int q = 0; q < 4; q++) acc[i][j][q] = 0.f;

    const __half* img0 = in + (size_t)img * H * W * CIN;

    // load one cin-chunk's halo window (180 pixels x 32 ch) into buffer
    auto issue = [&](int cc, int buf) {
        uint32_t AO = sb + buf * HALO_SZ;
        for (int p = t; p < 180; p += 128) {
            int hy = p / 18, hx = p % 18;
            int gy = y0 - 1 + hy, gx = x0 - 1 + hx;
            bool aok = (gy >= 0 && gy < H && gx >= 0 && gx < W);
            int cy = min(max(gy, 0), H - 1), cx = min(max(gx, 0), W - 1);
            const __half* src = img0 + ((size_t)cy * W + cx) * CIN + cc * 32;
            uint32_t dst = AO + (uint32_t)p * 80;
            #pragma unroll
            for (int j = 0; j < 4; j++)
                cpa16(dst + j * 16, src + j * 8, aok);
        }
        cp_commit();
    };

    issue(0, 0);

    for (int cc = 0; cc < CC; cc++) {
        int buf = cc & 1;
        if (cc + 1 < CC) { issue(cc + 1, buf ^ 1); cp_wait<1>(); }
        else             { cp_wait<0>(); }
        __syncthreads();

        uint32_t AO = sb + buf * HALO_SZ;

        for (int tap = 0; tap < 9; tap++) {
            int dy = tap / 3 - 1, dx = tap % 3 - 1;
            #pragma unroll
            for (int k16 = 0; k16 < 2; k16++) {
                int kh = tap * (CIN / 16) + cc * 2 + k16;
                const uint32_t* wp = wbase + (size_t)kh * whstep;
                uint32_t bh[NF][2];
                if constexpr (NF % 4 == 0) {
                    #pragma unroll
                    for (int j = 0; j < NF / 2; j++) {
                        uint4 v = ((const uint4*)wp)[j];
                        bh[2 * j][0] = v.x;     bh[2 * j][1] = v.y;
                        bh[2 * j + 1][0] = v.z; bh[2 * j + 1][1] = v.w;
                    }
                } else {
                    #pragma unroll
                    for (int j = 0; j < NF; j++) {
                        uint2 v = ((const uint2*)wp)[j];
                        bh[j][0] = v.x; bh[j][1] = v.y;
                    }
                }
                uint32_t ah[4][4];
                #pragma unroll
                for (int mi = 0; mi < 4; mi++) {
                    int p = wm * 64 + mi * 16 + (lane & 15);
                    int py = p >> 4, px = p & 15;
                    int hidx = (py + 1 + dy) * 18 + (px + 1 + dx);
                    uint32_t rowb = (uint32_t)(hidx * 80 + k16 * 32 + (lane >> 4) * 16);
                    ldsm_x4(ah[mi], AO + rowb);
                }
                #pragma unroll
                for (int mi = 0; mi < 4; mi++)
                    #pragma unroll
                    for (int ni = 0; ni < NF; ni++)
                        mma_f16(acc[mi][ni], ah[mi], bh[ni]);
            }
        }
        __syncthreads();
    }

    // ---- epilogue: bias + relu; write fp16 or fp32 ----
    #pragma unroll
    for (int mi = 0; mi < 4; mi++) {
        int p0 = wm * 64 + mi * 16 + (lane >> 2);
        #pragma unroll
        for (int half_ = 0; half_ < 2; half_++) {
            int p = p0 + half_ * 8;
            int gy = y0 + (p >> 4), gx = x0 + (p & 15);
            size_t pixoff = ((size_t)img * H * W + (size_t)gy * W + gx) * COUT + cobase;
            #pragma unroll
            for (int ni = 0; ni < NF; ni++) {
                int cl = nbase + ni * 8 + (lane & 3) * 2;
                float r0 = acc[mi][ni][half_ * 2 + 0] + sbias[cl];
                float r1 = acc[mi][ni][half_ * 2 + 1] + sbias[cl + 1];
                r0 = fmaxf(r0, 0.f); r1 = fmaxf(r1, 0.f);
                if (OUT_HALF) {
                    __half2 hh = __halves2half2(__float2half_rn(r0), __float2half_rn(r1));
                    *(uint32_t*)(outh + pixoff + cl) = *(uint32_t*)&hh;
                } else {
                    *(float2*)(outf + pixoff + cl) = make_float2(r0, r1);
                }
            }
        }
    }
}

// ---------------------------------------------------------------------------
// Classification head
// ---------------------------------------------------------------------------
__global__ void cls_kernel(const float* __restrict__ feat5,
                           const float* __restrict__ fc1_w, const float* __restrict__ fc1_b,
                           const float* __restrict__ fc2_w, const float* __restrict__ fc2_b,
                           const float* __restrict__ fc3_w, const float* __restrict__ fc3_b,
                           float* __restrict__ out_predcls, int* __restrict__ cls) {
    int b = blockIdx.x;
    int t = threadIdx.x;
    __shared__ float g0[256], g1[256], lg[3];
    const float* f = feat5 + (size_t)b * 16 * 16 * 256;
    float s = 0.f;
    #pragma unroll 4
    for (int p = 0; p < 256; p++) s += f[p * 256 + t];
    g0[t] = s * (1.0f / 256.0f);
    __syncthreads();
    float a = fc1_b[t];
    #pragma unroll 4
    for (int k = 0; k < 256; k++) a = fmaf(g0[k], fc1_w[k * 256 + t], a);
    g1[t] = fmaxf(a, 0.f);
    __syncthreads();
    a = fc2_b[t];
    #pragma unroll 4
    for (int k = 0; k < 256; k++) a = fmaf(g1[k], fc2_w[k * 256 + t], a);
    g0[t] = fmaxf(a, 0.f);
    __syncthreads();
    if (t < 3) {
        a = fc3_b[t];
        for (int k = 0; k < 256; k++) a = fmaf(g0[k], fc3_w[k * 3 + t], a);
        lg[t] = a;
    }
    __syncthreads();
    if (t == 0) {
        float m = fmaxf(lg[0], fmaxf(lg[1], lg[2]));
        float e0 = expf(lg[0] - m), e1 = expf(lg[1] - m), e2 = expf(lg[2] - m);
        float inv = 1.f / (e0 + e1 + e2);
        out_predcls[b * 3 + 0] = e0 * inv;
        out_predcls[b * 3 + 1] = e1 * inv;
        out_predcls[b * 3 + 2] = e2 * inv;
        int c = 0;
        if (lg[1] > lg[0]) c = 1;
        if (lg[2] > lg[c]) c = 2;
        cls[b] = c;
    }
}

// ---------------------------------------------------------------------------
// Fused reg/wt conv with class selection (5 channels, fp32)
// ---------------------------------------------------------------------------
__global__ void regsel_kernel(const float* __restrict__ x,
                              const float* __restrict__ reg_w, const float* __restrict__ reg_b,
                              const float* __restrict__ wt_w,  const float* __restrict__ wt_b,
                              const int* __restrict__ cls, float* __restrict__ out) {
    int b = blockIdx.z;
    int c = cls[b];
    __shared__ __align__(16) float ws[9 * 256 * 5];
    int t = threadIdx.x;
    for (int i = t; i < 9 * 256; i += 256) {
        const float* rp = reg_w + (size_t)i * 12 + 4 * c;
        float* wp = ws + i * 5;
        wp[0] = rp[0]; wp[1] = rp[1]; wp[2] = rp[2]; wp[3] = rp[3];
        wp[4] = wt_w[(size_t)i * 3 + c];
    }
    __syncthreads();
    int px = blockIdx.x * 16 + (t & 15);
    int py = blockIdx.y * 16 + (t >> 4);
    float a0 = reg_b[4 * c], a1 = reg_b[4 * c + 1], a2 = reg_b[4 * c + 2],
          a3 = reg_b[4 * c + 3], a4 = wt_b[c];
    const float* xi = x + (size_t)b * 256 * 256 * 256;
    for (int tap = 0; tap < 9; tap++) {
        int yy = py + tap / 3 - 1, xx = px + tap % 3 - 1;
        if (yy < 0 || yy >= 256 || xx < 0 || xx >= 256) continue;
        const float* ip = xi + ((size_t)yy * 256 + xx) * 256;
        const float* wp = ws + tap * 256 * 5;
        #pragma unroll 2
        for (int ci = 0; ci < 256; ci += 4) {
            float4 v = *(const float4*)(ip + ci);
            float wl[20];
            const float4* w4 = (const float4*)(wp + ci * 5);
            #pragma unroll
            for (int q = 0; q < 5; q++) ((float4*)wl)[q] = w4[q];
            a0 = fmaf(v.x, wl[0], a0);  a1 = fmaf(v.x, wl[1], a1);
            a2 = fmaf(v.x, wl[2], a2);  a3 = fmaf(v.x, wl[3], a3);  a4 = fmaf(v.x, wl[4], a4);
            a0 = fmaf(v.y, wl[5], a0);  a1 = fmaf(v.y, wl[6], a1);
            a2 = fmaf(v.y, wl[7], a2);  a3 = fmaf(v.y, wl[8], a3);  a4 = fmaf(v.y, wl[9], a4);
            a0 = fmaf(v.z, wl[10], a0); a1 = fmaf(v.z, wl[11], a1);
            a2 = fmaf(v.z, wl[12], a2); a3 = fmaf(v.z, wl[13], a3); a4 = fmaf(v.z, wl[14], a4);
            a0 = fmaf(v.w, wl[15], a0); a1 = fmaf(v.w, wl[16], a1);
            a2 = fmaf(v.w, wl[17], a2); a3 = fmaf(v.w, wl[18], a3); a4 = fmaf(v.w, wl[19], a4);
        }
    }
    size_t pix = ((size_t)b * 256 + py) * 256 + px;
    out[OFF_OFFSETS + pix * 2 + 0] = a0;
    out[OFF_OFFSETS + pix * 2 + 1] = a1;
    out[OFF_SIZES   + pix * 2 + 0] = a2;
    out[OFF_SIZES   + pix * 2 + 1] = a3;
    out[OFF_WEIGHTS + pix] = a4;
}

// ---------------------------------------------------------------------------
// Bilinear crop -> fp16
// ---------------------------------------------------------------------------
__global__ void crop_kernel(const float* __restrict__ feat0,
                            const float* __restrict__ boxes,
                            __half* __restrict__ cp) {
    int n = blockIdx.x;
    int b = n >> 6;
    const int H = 512, W = 512, C = 64;
    __shared__ int sy0[32], sx0[32];
    __shared__ float swy[32], swx[32];
    const float* bx = boxes + (size_t)n * 4;
    float y1 = bx[0], x1 = bx[1], y2 = bx[2], x2 = bx[3];
    int t = threadIdx.x;
    if (t < 32) {
        float tt = (float)t / 31.0f;
        float ys = y1 * (H - 1) + tt * (y2 - y1) * (H - 1);
        int yy0 = (int)floorf(ys);
        yy0 = min(max(yy0, 0), H - 2);
        sy0[t] = yy0; swy[t] = ys - (float)yy0;
    } else if (t < 64) {
        int i = t - 32;
        float tt = (float)i / 31.0f;
        float xs = x1 * (W - 1) + tt * (x2 - x1) * (W - 1);
        int xx0 = (int)floorf(xs);
        xx0 = min(max(xx0, 0), W - 2);
        sx0[i] = xx0; swx[i] = xs - (float)xx0;
    }
    __syncthreads();
    const float* f = feat0 + (size_t)b * H * W * C;
    size_t obase = (size_t)n * 32 * 32 * C;
    for (int idx = t; idx < 32 * 32 * C; idx += blockDim.x) {
        int c  = idx & 63;
        int ix = (idx >> 6) & 31;
        int iy = idx >> 11;
        int yy0 = sy0[iy], xx0 = sx0[ix];
        float wy = swy[iy], wx = swx[ix];
        const float* p00 = f + ((size_t)yy0 * W + xx0) * C + c;
        float v00 = p00[0], v01 = p00[C], v10 = p00[(size_t)W * C], v11 = p00[(size_t)W * C + C];
        float top = v00 * (1.f - wx) + v01 * wx;
        float bot = v10 * (1.f - wx) + v11 * wx;
        float v = top * (1.f - wy) + bot * wy;
        cp[obase + idx] = __float2half_rn(v);
    }
}

// ---------------------------------------------------------------------------
// so conv with class selection (1 channel, fp32)
// ---------------------------------------------------------------------------
__global__ void sosel_kernel(const float* __restrict__ s2,
                             const float* __restrict__ so_w, const float* __restrict__ so_b,
                             const int* __restrict__ cls, float* __restrict__ out) {
    int n = blockIdx.x;
    int c = cls[n >> 6];
    __shared__ __align__(16) float ws[9 * 96];
    int t = threadIdx.x;
    for (int i = t; i < 864; i += 256) ws[i] = so_w[(size_t)i * 3 + c];
    __syncthreads();
    float bias = so_b[c];
    const float* sp = s2 + (size_t)n * 32 * 32 * 96;
    for (int pix = t; pix < 1024; pix += 256) {
        int py = pix >> 5, px = pix & 31;
        float acc = bias;
        for (int tap = 0; tap < 9; tap++) {
            int yy = py + tap / 3 - 1, xx = px + tap % 3 - 1;
            if (yy < 0 || yy >= 32 || xx < 0 || xx >= 32) continue;
            const float* ip = sp + ((size_t)yy * 32 + xx) * 96;
            const float* wp = ws + tap * 96;
            #pragma unroll 4
            for (int ci = 0; ci < 96; ci += 4) {
                float4 v = *(const float4*)(ip + ci);
                float4 w = *(const float4*)(wp + ci);
                acc = fmaf(v.x, w.x, acc);
                acc = fmaf(v.y, w.y, acc);
                acc = fmaf(v.z, w.z, acc);
                acc = fmaf(v.w, w.w, acc);
            }
        }
        out[OFF_SEG + (size_t)n * 1024 + pix] = acc;
    }
}

// ---------------------------------------------------------------------------
// Score head
// ---------------------------------------------------------------------------
__global__ void score_kernel(const float* __restrict__ s2,
                             const float* __restrict__ sd1_w, const float* __restrict__ sd1_b,
                             const float* __restrict__ sd2_w, const float* __restrict__ sd2_b,
                             const float* __restrict__ sd3_w, const float* __restrict__ sd3_b,
                             const int* __restrict__ cls, float* __restrict__ out) {
    int n = blockIdx.x;
    int t = threadIdx.x;
    __shared__ float pooled[6144];
    __shared__ float h1[256], h2[256];
    const float* sp = s2 + (size_t)n * 32 * 32 * 96;
    for (int o = t; o < 6144; o += 256) {
        int c  = o % 96;
        int px = (o / 96) & 7;
        int py = o / 768;
        float s = 0.f;
        #pragma unroll
        for (int i = 0; i < 4; i++)
            #pragma unroll
            for (int j = 0; j < 4; j++)
                s += sp[(((size_t)(py * 4 + i)) * 32 + (px * 4 + j)) * 96 + c];
        pooled[o] = s * (1.f / 16.f);
    }
    __syncthreads();
    float a = sd1_b[t];
    #pragma unroll 4
    for (int k = 0; k < 6144; k++) a = fmaf(pooled[k], sd1_w[(size_t)k * 256 + t], a);
    h1[t] = fmaxf(a, 0.f);
    __syncthreads();
    a = sd2_b[t];
    #pragma unroll 4
    for (int k = 0; k < 256; k++) a = fmaf(h1[k], sd2_w[k * 256 + t], a);
    h2[t] = fmaxf(a, 0.f);
    __syncthreads();
    if (t == 0) {
        int c = cls[n >> 6];
        float acc = sd3_b[c];
        for (int k = 0; k < 256; k++) acc = fmaf(h2[k], sd3_w[k * 3 + c], acc);
        out[OFF_SCORE + n] = acc;
    }
}

// ---------------------------------------------------------------------------
extern "C" void kernel_launch(void* const* d_in, const int* in_sizes, int n_in,
                              void* d_out, int out_size) {
    (void)in_sizes; (void)n_in; (void)out_size;
    const float* feat0 = (const float*)d_in[0];
    const float* feat1 = (const float*)d_in[1];
    const float* feat5 = (const float*)d_in[2];
    const float* boxes = (const float*)d_in[3];
    const float* cb1_w = (const float*)d_in[4];
    const float* cb1_b = (const float*)d_in[5];
    const float* cb2_w = (const float*)d_in[6];
    const float* cb2_b = (const float*)d_in[7];
    const float* reg_w = (const float*)d_in[8];
    const float* reg_b = (const float*)d_in[9];
    const float* wt_w  = (const float*)d_in[10];
    const float* wt_b  = (const float*)d_in[11];
    const float* fc1_w = (const float*)d_in[12];
    const float* fc1_b = (const float*)d_in[13];
    const float* fc2_w = (const float*)d_in[14];
    const float* fc2_b = (const float*)d_in[15];
    const float* fc3_w = (const float*)d_in[16];
    const float* fc3_b = (const float*)d_in[17];
    const float* sc1_w = (const float*)d_in[18];
    const float* sc1_b = (const float*)d_in[19];
    const float* sc2_w = (const float*)d_in[20];
    const float* sc2_b = (const float*)d_in[21];
    const float* so_w  = (const float*)d_in[22];
    const float* so_b  = (const float*)d_in[23];
    const float* sd1_w = (const float*)d_in[24];
    const float* sd1_b = (const float*)d_in[25];
    const float* sd2_w = (const float*)d_in[26];
    const float* sd2_b = (const float*)d_in[27];
    const float* sd3_w = (const float*)d_in[28];
    const float* sd3_b = (const float*)d_in[29];
    float* out = (float*)d_out;

    // resolve device globals
    void* p;
    cudaGetSymbolAddress(&p, g_f1);  __half* f1 = (__half*)p;
    cudaGetSymbolAddress(&p, g_x1);  __half* x1 = (__half*)p;
    cudaGetSymbolAddress(&p, g_x2);  float* x2 = (float*)p;
    cudaGetSymbolAddress(&p, g_cp);  __half* cp = (__half*)p;
    cudaGetSymbolAddress(&p, g_s1);  __half* s1 = (__half*)p;
    cudaGetSymbolAddress(&p, g_s2);  float* s2 = (float*)p;
    cudaGetSymbolAddress(&p, g_w1);  uint32_t* w1 = (uint32_t*)p;
    cudaGetSymbolAddress(&p, g_w2);  uint32_t* w2 = (uint32_t*)p;
    cudaGetSymbolAddress(&p, g_w3);  uint32_t* w3 = (uint32_t*)p;
    cudaGetSymbolAddress(&p, g_w4);  uint32_t* w4 = (uint32_t*)p;
    cudaGetSymbolAddress(&p, g_cls); int* cls = (int*)p;

    constexpr int DYN = 2 * HALO_SZ;   // 28800 (halo A, double-buffered)

    // classification first (selection depends on cls)
    cls_kernel<<<4, 256>>>(feat5, fc1_w, fc1_b, fc2_w, fc2_b, fc3_w, fc3_b,
                           out + OFF_PREDCLS, cls);

    // operand prep: weights into fragment order; feat1 -> fp16
    wfrag_kernel<<<(147456 + 255) / 256, 256>>>(cb1_w, w1, 1152, 256, 128, 8, 72, 147456);
    wfrag_kernel<<<(294912 + 255) / 256, 256>>>(cb2_w, w2, 2304, 256, 128, 8, 144, 294912);
    wfrag_kernel<<<(27648 + 255) / 256, 256>>>(sc1_w, w3, 576, 96, 96, 6, 36, 27648);
    wfrag_kernel<<<(41472 + 255) / 256, 256>>>(sc2_w, w4, 864, 96, 96, 6, 54, 41472);
    fcvt16_kernel<<<(33554432 / 4 + 255) / 256, 256>>>(feat1, f1, 33554432);

    // crop + segmentation branch
    crop_kernel<<<256, 256>>>(feat0, boxes, cp);
    conv3x3_halo<64, 96, true, 3><<<dim3(2, 4, 256), 128, DYN>>>(
        cp, w3, sc1_b, nullptr, s1, 32, 32, 96, 1);
    conv3x3_halo<96, 96, false, 3><<<dim3(2, 4, 256), 128, DYN>>>(
        s1, w4, sc2_b, s2, nullptr, 32, 32, 96, 1);
    sosel_kernel<<<256, 256>>>(s2, so_w, so_b, cls, out);
    score_kernel<<<256, 256>>>(s2, sd1_w, sd1_b, sd2_w, sd2_b, sd3_w, sd3_b, cls, out);

    // regression branch
    conv3x3_halo<128, 128, true, 2><<<dim3(16, 32, 8), 128, DYN>>>(
        f1, w1, cb1_b, nullptr, x1, 256, 256, 256, 2);
    conv3x3_halo<256, 128, false, 2><<<dim3(16, 32, 8), 128, DYN>>>(
        x1, w2, cb2_b, x2, nullptr, 256, 256, 256, 2);
    regsel_kernel<<<dim3(16, 16, 4), 256>>>(x2, reg_w, reg_b, wt_w, wt_b, cls, out);
}

// round 14
// speedup vs baseline: 4.3719x; 1.1832x over previous
#include <cuda_runtime.h>
#include <cuda_fp16.h>
#include <math.h>
#include <stdint.h>

typedef unsigned long long u64;

// ---------------------------------------------------------------------------
// Output layout (tuple flattened in order)
// ---------------------------------------------------------------------------
#define OFF_OFFSETS 0
#define OFF_SIZES   524288
#define OFF_WEIGHTS 1048576
#define OFF_PREDCLS 1310720
#define OFF_SEG     1310732
#define OFF_SCORE   1572876

// Scratch (device globals; no allocation allowed)
__device__ __half g_f1[33554432];     // feat1 fp16
__device__ __half g_x1[67108864];     // conv1 out fp16
__device__ __half g_x2[67108864];     // conv2 out fp16
__device__ __half g_cp[16777216];     // crops fp16
__device__ __half g_s1[25165824];     // sc1 out fp16
__device__ __half g_s2[25165824];     // sc2 out fp16
// fragment-order fp16 weights (b32-packed)
__device__ __align__(16) __half g_w1[294912];
__device__ __align__(16) __half g_w2[589824];
__device__ __align__(16) __half g_w3[55296];
__device__ __align__(16) __half g_w4[82944];
__device__ int g_cls[4];

// ---------------------------------------------------------------------------
// PTX helpers (arch-generic sm_80+)
// ---------------------------------------------------------------------------
__device__ __forceinline__ uint32_t smem_u32(const void* p) {
    uint32_t a;
    asm("{ .reg .u64 t; cvta.to.shared.u64 t, %1; cvt.u32.u64 %0, t; }"
        : "=r"(a) : "l"(p));
    return a;
}
__device__ __forceinline__ void ldsm_x4(uint32_t* r, uint32_t a) {
    asm volatile("ldmatrix.sync.aligned.m8n8.x4.shared.b16 {%0,%1,%2,%3}, [%4];"
                 : "=r"(r[0]), "=r"(r[1]), "=r"(r[2]), "=r"(r[3]) : "r"(a));
}
__device__ __forceinline__ void mma_f16(float* d, const uint32_t* a, const uint32_t* b) {
    asm volatile("mma.sync.aligned.m16n8k16.row.col.f32.f16.f16.f32 "
                 "{%0,%1,%2,%3}, {%4,%5,%6,%7}, {%8,%9}, {%0,%1,%2,%3};"
                 : "+f"(d[0]), "+f"(d[1]), "+f"(d[2]), "+f"(d[3])
                 : "r"(a[0]), "r"(a[1]), "r"(a[2]), "r"(a[3]),
                   "r"(b[0]), "r"(b[1]));
}
__device__ __forceinline__ void cpa16(uint32_t dst, const void* src, bool ok) {
    int sz = ok ? 16 : 0;
    asm volatile("cp.async.cg.shared.global [%0], [%1], 16, %2;"
                 :: "r"(dst), "l"(src), "r"(sz) : "memory");
}
__device__ __forceinline__ void cp_commit() {
    asm volatile("cp.async.commit_group;" ::: "memory");
}
template <int N>
__device__ __forceinline__ void cp_wait() {
    asm volatile("cp.async.wait_group %0;" :: "n"(N) : "memory");
}

// ---------------------------------------------------------------------------
// Operand preparation kernels
// ---------------------------------------------------------------------------
// fp32 -> fp16 (elementwise, 4-wide)
__global__ void fcvt16_kernel(const float* __restrict__ src,
                              __half* __restrict__ o, int n) {
    int i = blockIdx.x * blockDim.x + threadIdx.x;
    if (i * 4 >= n) return;
    float4 v = *(const float4*)(src + i * 4);
    __half2 a = __halves2half2(__float2half_rn(v.x), __float2half_rn(v.y));
    __half2 b = __halves2half2(__float2half_rn(v.z), __float2half_rn(v.w));
    *(uint2*)(o + i * 4) = make_uint2(*(uint32_t*)&a, *(uint32_t*)&b);
}

// weights [K9][COUT] fp32 -> mma B-fragment order, b32-packed
__global__ void wfrag_kernel(const float* __restrict__ w,
                             uint32_t* __restrict__ o,
                             int K9, int COUT, int CT, int NF, int KH, int total) {
    int i = blockIdx.x * blockDim.x + threadIdx.x;
    if (i >= total) return;
    int r  = i & 1;
    int ni = (i >> 1) % NF;
    int l  = (i >> 1) / NF % 32;
    int nw = (i >> 1) / NF / 32 & 1;
    int kh = (i >> 1) / NF / 64 % KH;
    int nt = (i >> 1) / NF / 64 / KH;
    int k  = kh * 16 + r * 8 + (l & 3) * 2;
    int co = nt * CT + nw * (CT / 2) + ni * 8 + (l >> 2);
    __half2 v = __halves2half2(__float2half_rn(w[(size_t)k * COUT + co]),
                               __float2half_rn(w[(size_t)(k + 1) * COUT + co]));
    o[i] = *(uint32_t*)&v;
}

// ---------------------------------------------------------------------------
// FP16 tensor-core 3x3 SAME conv, HALO-TILED A staging, 3-stage cp.async
// pipeline (1 sync per cin-chunk). W fp16 fragment-order via direct LDG.
// CTA: 128 thr (2M x 2N warps). Tile M=128px (8y x 16x) x N=COUT_TILE.
// grid: (W/16, H/8, nimg * NT)
// ---------------------------------------------------------------------------
#define HALO_SZ (180 * 80)   // 14400 B per buffer

template <int CIN, int COUT_TILE, bool OUT_HALF, int MAXB>
__global__ __launch_bounds__(128, MAXB)
void conv3x3_halo(const __half* __restrict__ in,
                  const uint32_t* __restrict__ wfrag,
                  const float* __restrict__ bias,
                  float* __restrict__ outf, __half* __restrict__ outh,
                  int H, int W, int COUT, int NT) {
    constexpr int CC = CIN / 32;             // cin chunks
    constexpr int KH = 9 * CIN / 16;
    constexpr int NF = COUT_TILE / 16;       // 8 or 6 (even)
    extern __shared__ char sm[];
    const uint32_t sb = smem_u32(sm);
    __shared__ float sbias[COUT_TILE];

    int t = threadIdx.x, warp = t >> 5, lane = t & 31;
    int img = blockIdx.z / NT, ntile = blockIdx.z % NT;
    int cobase = ntile * COUT_TILE;
    int x0 = blockIdx.x * 16, y0 = blockIdx.y * 8;

    if (t < COUT_TILE) sbias[t] = bias[cobase + t];

    int wm = warp & 1, nw = warp >> 1;
    int nbase = nw * (COUT_TILE / 2);

    const uint32_t* wbase = wfrag
        + ((size_t)((ntile * KH) * 2 + nw) * 32 + lane) * (2 * NF);
    const size_t whstep = (size_t)128 * NF;  // per-kh step in b32

    float acc[4][NF][4];
    #pragma unroll
    for (int i = 0; i < 4; i++)
        #pragma unroll
        for (int j = 0; j < NF; j++)
            #pragma unroll
            for (int q = 0; q < 4; q++) acc[i][j][q] = 0.f;

    const __half* img0 = in + (size_t)img * H * W * CIN;

    // load one cin-chunk's halo window (180 px x 32 ch) into buffer
    auto issue = [&](int cc, int buf) {
        uint32_t AO = sb + buf * HALO_SZ;
        for (int p = t; p < 180; p += 128) {
            int hy = p / 18, hx = p % 18;
            int gy = y0 - 1 + hy, gx = x0 - 1 + hx;
            bool aok = (gy >= 0 && gy < H && gx >= 0 && gx < W);
            int cy = min(max(gy, 0), H - 1), cx = min(max(gx, 0), W - 1);
            const __half* src = img0 + ((size_t)cy * W + cx) * CIN + cc * 32;
            uint32_t dst = AO + (uint32_t)p * 80;
            #pragma unroll
            for (int j = 0; j < 4; j++)
                cpa16(dst + j * 16, src + j * 8, aok);
        }
        cp_commit();
    };

    issue(0, 0);
    if (CC > 1) issue(1, 1);

    for (int cc = 0; cc < CC; cc++) {
        if (cc + 1 < CC) cp_wait<1>();
        else             cp_wait<0>();
        __syncthreads();
        if (cc + 2 < CC) issue(cc + 2, (cc + 2) % 3);

        uint32_t AO = sb + (cc % 3) * HALO_SZ;

        for (int tap = 0; tap < 9; tap++) {
            int dy = tap / 3 - 1, dx = tap % 3 - 1;
            #pragma unroll
            for (int k16 = 0; k16 < 2; k16++) {
                int kh = tap * (CIN / 16) + cc * 2 + k16;
                const uint32_t* wp = wbase + (size_t)kh * whstep;
                uint32_t bh[NF][2];
                if constexpr (NF % 4 == 0) {
                    #pragma unroll
                    for (int j = 0; j < NF / 2; j++) {
                        uint4 v = ((const uint4*)wp)[j];
                        bh[2 * j][0] = v.x;     bh[2 * j][1] = v.y;
                        bh[2 * j + 1][0] = v.z; bh[2 * j + 1][1] = v.w;
                    }
                } else {
                    #pragma unroll
                    for (int j = 0; j < NF; j++) {
                        uint2 v = ((const uint2*)wp)[j];
                        bh[j][0] = v.x; bh[j][1] = v.y;
                    }
                }
                uint32_t ah[4][4];
                #pragma unroll
                for (int mi = 0; mi < 4; mi++) {
                    int p = wm * 64 + mi * 16 + (lane & 15);
                    int py = p >> 4, px = p & 15;
                    int hidx = (py + 1 + dy) * 18 + (px + 1 + dx);
                    uint32_t rowb = (uint32_t)(hidx * 80 + k16 * 32 + (lane >> 4) * 16);
                    ldsm_x4(ah[mi], AO + rowb);
                }
                #pragma unroll
                for (int mi = 0; mi < 4; mi++)
                    #pragma unroll
                    for (int ni = 0; ni < NF; ni++)
                        mma_f16(acc[mi][ni], ah[mi], bh[ni]);
            }
        }
    }

    // ---- epilogue: bias + relu; write fp16 or fp32 ----
    #pragma unroll
    for (int mi = 0; mi < 4; mi++) {
        int p0 = wm * 64 + mi * 16 + (lane >> 2);
        #pragma unroll
        for (int half_ = 0; half_ < 2; half_++) {
            int p = p0 + half_ * 8;
            int gy = y0 + (p >> 4), gx = x0 + (p & 15);
            size_t pixoff = ((size_t)img * H * W + (size_t)gy * W + gx) * COUT + cobase;
            #pragma unroll
            for (int ni = 0; ni < NF; ni++) {
                int cl = nbase + ni * 8 + (lane & 3) * 2;
                float r0 = acc[mi][ni][half_ * 2 + 0] + sbias[cl];
                float r1 = acc[mi][ni][half_ * 2 + 1] + sbias[cl + 1];
                r0 = fmaxf(r0, 0.f); r1 = fmaxf(r1, 0.f);
                if (OUT_HALF) {
                    __half2 hh = __halves2half2(__float2half_rn(r0), __float2half_rn(r1));
                    *(uint32_t*)(outh + pixoff + cl) = *(uint32_t*)&hh;
                } else {
                    *(float2*)(outf + pixoff + cl) = make_float2(r0, r1);
                }
            }
        }
    }
}

// ---------------------------------------------------------------------------
// Classification head
// ---------------------------------------------------------------------------
__global__ void cls_kernel(const float* __restrict__ feat5,
                           const float* __restrict__ fc1_w, const float* __restrict__ fc1_b,
                           const float* __restrict__ fc2_w, const float* __restrict__ fc2_b,
                           const float* __restrict__ fc3_w, const float* __restrict__ fc3_b,
                           float* __restrict__ out_predcls, int* __restrict__ cls) {
    int b = blockIdx.x;
    int t = threadIdx.x;
    __shared__ float g0[256], g1[256], lg[3];
    const float* f = feat5 + (size_t)b * 16 * 16 * 256;
    float s = 0.f;
    #pragma unroll 4
    for (int p = 0; p < 256; p++) s += f[p * 256 + t];
    g0[t] = s * (1.0f / 256.0f);
    __syncthreads();
    float a = fc1_b[t];
    #pragma unroll 4
    for (int k = 0; k < 256; k++) a = fmaf(g0[k], fc1_w[k * 256 + t], a);
    g1[t] = fmaxf(a, 0.f);
    __syncthreads();
    a = fc2_b[t];
    #pragma unroll 4
    for (int k = 0; k < 256; k++) a = fmaf(g1[k], fc2_w[k * 256 + t], a);
    g0[t] = fmaxf(a, 0.f);
    __syncthreads();
    if (t < 3) {
        a = fc3_b[t];
        for (int k = 0; k < 256; k++) a = fmaf(g0[k], fc3_w[k * 3 + t], a);
        lg[t] = a;
    }
    __syncthreads();
    if (t == 0) {
        float m = fmaxf(lg[0], fmaxf(lg[1], lg[2]));
        float e0 = expf(lg[0] - m), e1 = expf(lg[1] - m), e2 = expf(lg[2] - m);
        float inv = 1.f / (e0 + e1 + e2);
        out_predcls[b * 3 + 0] = e0 * inv;
        out_predcls[b * 3 + 1] = e1 * inv;
        out_predcls[b * 3 + 2] = e2 * inv;
        int c = 0;
        if (lg[1] > lg[0]) c = 1;
        if (lg[2] > lg[c]) c = 2;
        cls[b] = c;
    }
}

// ---------------------------------------------------------------------------
// Fused reg/wt conv with class selection (5 channels; x2 is fp16)
// ---------------------------------------------------------------------------
__global__ void regsel_kernel(const __half* __restrict__ x,
                              const float* __restrict__ reg_w, const float* __restrict__ reg_b,
                              const float* __restrict__ wt_w,  const float* __restrict__ wt_b,
                              const int* __restrict__ cls, float* __restrict__ out) {
    int b = blockIdx.z;
    int c = cls[b];
    __shared__ __align__(16) float ws[9 * 256 * 5];
    int t = threadIdx.x;
    for (int i = t; i < 9 * 256; i += 256) {
        const float* rp = reg_w + (size_t)i * 12 + 4 * c;
        float* wp = ws + i * 5;
        wp[0] = rp[0]; wp[1] = rp[1]; wp[2] = rp[2]; wp[3] = rp[3];
        wp[4] = wt_w[(size_t)i * 3 + c];
    }
    __syncthreads();
    int px = blockIdx.x * 16 + (t & 15);
    int py = blockIdx.y * 16 + (t >> 4);
    float a0 = reg_b[4 * c], a1 = reg_b[4 * c + 1], a2 = reg_b[4 * c + 2],
          a3 = reg_b[4 * c + 3], a4 = wt_b[c];
    const __half* xi = x + (size_t)b * 256 * 256 * 256;
    for (int tap = 0; tap < 9; tap++) {
        int yy = py + tap / 3 - 1, xx = px + tap % 3 - 1;
        if (yy < 0 || yy >= 256 || xx < 0 || xx >= 256) continue;
        const __half* ip = xi + ((size_t)yy * 256 + xx) * 256;
        const float* wp = ws + tap * 256 * 5;
        for (int ci = 0; ci < 256; ci += 8) {
            uint4 hv = *(const uint4*)(ip + ci);
            __half2 h0 = *(__half2*)&hv.x, h1 = *(__half2*)&hv.y;
            __half2 h2 = *(__half2*)&hv.z, h3 = *(__half2*)&hv.w;
            float v[8];
            float2 f0 = __half22float2(h0), f1 = __half22float2(h1);
            float2 f2 = __half22float2(h2), f3 = __half22float2(h3);
            v[0] = f0.x; v[1] = f0.y; v[2] = f1.x; v[3] = f1.y;
            v[4] = f2.x; v[5] = f2.y; v[6] = f3.x; v[7] = f3.y;
            const float* wl = wp + ci * 5;
            #pragma unroll
            for (int q = 0; q < 8; q++) {
                a0 = fmaf(v[q], wl[q * 5 + 0], a0);
                a1 = fmaf(v[q], wl[q * 5 + 1], a1);
                a2 = fmaf(v[q], wl[q * 5 + 2], a2);
                a3 = fmaf(v[q], wl[q * 5 + 3], a3);
                a4 = fmaf(v[q], wl[q * 5 + 4], a4);
            }
        }
    }
    size_t pix = ((size_t)b * 256 + py) * 256 + px;
    out[OFF_OFFSETS + pix * 2 + 0] = a0;
    out[OFF_OFFSETS + pix * 2 + 1] = a1;
    out[OFF_SIZES   + pix * 2 + 0] = a2;
    out[OFF_SIZES   + pix * 2 + 1] = a3;
    out[OFF_WEIGHTS + pix] = a4;
}

// ---------------------------------------------------------------------------
// Bilinear crop -> fp16
// ---------------------------------------------------------------------------
__global__ void crop_kernel(const float* __restrict__ feat0,
                            const float* __restrict__ boxes,
                            __half* __restrict__ cp) {
    int n = blockIdx.x;
    int b = n >> 6;
    const int H = 512, W = 512, C = 64;
    __shared__ int sy0[32], sx0[32];
    __shared__ float swy[32], swx[32];
    const float* bx = boxes + (size_t)n * 4;
    float y1 = bx[0], x1 = bx[1], y2 = bx[2], x2 = bx[3];
    int t = threadIdx.x;
    if (t < 32) {
        float tt = (float)t / 31.0f;
        float ys = y1 * (H - 1) + tt * (y2 - y1) * (H - 1);
        int yy0 = (int)floorf(ys);
        yy0 = min(max(yy0, 0), H - 2);
        sy0[t] = yy0; swy[t] = ys - (float)yy0;
    } else if (t < 64) {
        int i = t - 32;
        float tt = (float)i / 31.0f;
        float xs = x1 * (W - 1) + tt * (x2 - x1) * (W - 1);
        int xx0 = (int)floorf(xs);
        xx0 = min(max(xx0, 0), W - 2);
        sx0[i] = xx0; swx[i] = xs - (float)xx0;
    }
    __syncthreads();
    const float* f = feat0 + (size_t)b * H * W * C;
    size_t obase = (size_t)n * 32 * 32 * C;
    for (int idx = t; idx < 32 * 32 * C; idx += blockDim.x) {
        int c  = idx & 63;
        int ix = (idx >> 6) & 31;
        int iy = idx >> 11;
        int yy0 = sy0[iy], xx0 = sx0[ix];
        float wy = swy[iy], wx = swx[ix];
        const float* p00 = f + ((size_t)yy0 * W + xx0) * C + c;
        float v00 = p00[0], v01 = p00[C], v10 = p00[(size_t)W * C], v11 = p00[(size_t)W * C + C];
        float top = v00 * (1.f - wx) + v01 * wx;
        float bot = v10 * (1.f - wx) + v11 * wx;
        float v = top * (1.f - wy) + bot * wy;
        cp[obase + idx] = __float2half_rn(v);
    }
}

// ---------------------------------------------------------------------------
// so conv with class selection (1 channel; s2 is fp16)
// ---------------------------------------------------------------------------
__global__ void sosel_kernel(const __half* __restrict__ s2,
                             const float* __restrict__ so_w, const float* __restrict__ so_b,
                             const int* __restrict__ cls, float* __restrict__ out) {
    int n = blockIdx.x;
    int c = cls[n >> 6];
    __shared__ __align__(16) float ws[9 * 96];
    int t = threadIdx.x;
    for (int i = t; i < 864; i += 256) ws[i] = so_w[(size_t)i * 3 + c];
    __syncthreads();
    float bias = so_b[c];
    const __half* sp = s2 + (size_t)n * 32 * 32 * 96;
    for (int pix = t; pix < 1024; pix += 256) {
        int py = pix >> 5, px = pix & 31;
        float acc = bias;
        for (int tap = 0; tap < 9; tap++) {
            int yy = py + tap / 3 - 1, xx = px + tap % 3 - 1;
            if (yy < 0 || yy >= 32 || xx < 0 || xx >= 32) continue;
            const __half* ip = sp + ((size_t)yy * 32 + xx) * 96;
            const float* wp = ws + tap * 96;
            for (int ci = 0; ci < 96; ci += 8) {
                uint4 hv = *(const uint4*)(ip + ci);
                float2 f0 = __half22float2(*(__half2*)&hv.x);
                float2 f1 = __half22float2(*(__half2*)&hv.y);
                float2 f2 = __half22float2(*(__half2*)&hv.z);
                float2 f3 = __half22float2(*(__half2*)&hv.w);
                acc = fmaf(f0.x, wp[ci + 0], acc);
                acc = fmaf(f0.y, wp[ci + 1], acc);
                acc = fmaf(f1.x, wp[ci + 2], acc);
                acc = fmaf(f1.y, wp[ci + 3], acc);
                acc = fmaf(f2.x, wp[ci + 4], acc);
                acc = fmaf(f2.y, wp[ci + 5], acc);
                acc = fmaf(f3.x, wp[ci + 6], acc);
                acc = fmaf(f3.y, wp[ci + 7], acc);
            }
        }
        out[OFF_SEG + (size_t)n * 1024 + pix] = acc;
    }
}

// ---------------------------------------------------------------------------
// Score head (s2 is fp16)
// ---------------------------------------------------------------------------
__global__ void score_kernel(const __half* __restrict__ s2,
                             const float* __restrict__ sd1_w, const float* __restrict__ sd1_b,
                             const float* __restrict__ sd2_w, const float* __restrict__ sd2_b,
                             const float* __restrict__ sd3_w, const float* __restrict__ sd3_b,
                             const int* __restrict__ cls, float* __restrict__ out) {
    int n = blockIdx.x;
    int t = threadIdx.x;
    __shared__ float pooled[6144];
    __shared__ float h1[256], h2[256];
    const __half* sp = s2 + (size_t)n * 32 * 32 * 96;
    for (int o = t; o < 6144; o += 256) {
        int c  = o % 96;
        int px = (o / 96) & 7;
        int py = o / 768;
        float s = 0.f;
        #pragma unroll
        for (int i = 0; i < 4; i++)
            #pragma unroll
            for (int j = 0; j < 4; j++)
                s += __half2float(sp[(((size_t)(py * 4 + i)) * 32 + (px * 4 + j)) * 96 + c]);
        pooled[o] = s * (1.f / 16.f);
    }
    __syncthreads();
    float a = sd1_b[t];
    #pragma unroll 4
    for (int k = 0; k < 6144; k++) a = fmaf(pooled[k], sd1_w[(size_t)k * 256 + t], a);
    h1[t] = fmaxf(a, 0.f);
    __syncthreads();
    a = sd2_b[t];
    #pragma unroll 4
    for (int k = 0; k < 256; k++) a = fmaf(h1[k], sd2_w[k * 256 + t], a);
    h2[t] = fmaxf(a, 0.f);
    __syncthreads();
    if (t == 0) {
        int c = cls[n >> 6];
        float acc = sd3_b[c];
        for (int k = 0; k < 256; k++) acc = fmaf(h2[k], sd3_w[k * 3 + c], acc);
        out[OFF_SCORE + n] = acc;
    }
}

// ---------------------------------------------------------------------------
extern "C" void kernel_launch(void* const* d_in, const int* in_sizes, int n_in,
                              void* d_out, int out_size) {
    (void)in_sizes; (void)n_in; (void)out_size;
    const float* feat0 = (const float*)d_in[0];
    const float* feat1 = (const float*)d_in[1];
    const float* feat5 = (const float*)d_in[2];
    const float* boxes = (const float*)d_in[3];
    const float* cb1_w = (const float*)d_in[4];
    const float* cb1_b = (const float*)d_in[5];
    const float* cb2_w = (const float*)d_in[6];
    const float* cb2_b = (const float*)d_in[7];
    const float* reg_w = (const float*)d_in[8];
    const float* reg_b = (const float*)d_in[9];
    const float* wt_w  = (const float*)d_in[10];
    const float* wt_b  = (const float*)d_in[11];
    const float* fc1_w = (const float*)d_in[12];
    const float* fc1_b = (const float*)d_in[13];
    const float* fc2_w = (const float*)d_in[14];
    const float* fc2_b = (const float*)d_in[15];
    const float* fc3_w = (const float*)d_in[16];
    const float* fc3_b = (const float*)d_in[17];
    const float* sc1_w = (const float*)d_in[18];
    const float* sc1_b = (const float*)d_in[19];
    const float* sc2_w = (const float*)d_in[20];
    const float* sc2_b = (const float*)d_in[21];
    const float* so_w  = (const float*)d_in[22];
    const float* so_b  = (const float*)d_in[23];
    const float* sd1_w = (const float*)d_in[24];
    const float* sd1_b = (const float*)d_in[25];
    const float* sd2_w = (const float*)d_in[26];
    const float* sd2_b = (const float*)d_in[27];
    const float* sd3_w = (const float*)d_in[28];
    const float* sd3_b = (const float*)d_in[29];
    float* out = (float*)d_out;

    // resolve device globals
    void* p;
    cudaGetSymbolAddress(&p, g_f1);  __half* f1 = (__half*)p;
    cudaGetSymbolAddress(&p, g_x1);  __half* x1 = (__half*)p;
    cudaGetSymbolAddress(&p, g_x2);  __half* x2 = (__half*)p;
    cudaGetSymbolAddress(&p, g_cp);  __half* cp = (__half*)p;
    cudaGetSymbolAddress(&p, g_s1);  __half* s1 = (__half*)p;
    cudaGetSymbolAddress(&p, g_s2);  __half* s2 = (__half*)p;
    cudaGetSymbolAddress(&p, g_w1);  uint32_t* w1 = (uint32_t*)p;
    cudaGetSymbolAddress(&p, g_w2);  uint32_t* w2 = (uint32_t*)p;
    cudaGetSymbolAddress(&p, g_w3);  uint32_t* w3 = (uint32_t*)p;
    cudaGetSymbolAddress(&p, g_w4);  uint32_t* w4 = (uint32_t*)p;
    cudaGetSymbolAddress(&p, g_cls); int* cls = (int*)p;

    constexpr int DYN = 3 * HALO_SZ;   // 43200 (halo A, triple-buffered)
    cudaFuncSetAttribute(conv3x3_halo<128, 128, true, 2>,
                         cudaFuncAttributeMaxDynamicSharedMemorySize, DYN);
    cudaFuncSetAttribute(conv3x3_halo<256, 128, true, 2>,
                         cudaFuncAttributeMaxDynamicSharedMemorySize, DYN);
    cudaFuncSetAttribute(conv3x3_halo<64, 96, true, 3>,
                         cudaFuncAttributeMaxDynamicSharedMemorySize, DYN);
    cudaFuncSetAttribute(conv3x3_halo<96, 96, true, 3>,
                         cudaFuncAttributeMaxDynamicSharedMemorySize, DYN);

    // classification first (selection depends on cls)
    cls_kernel<<<4, 256>>>(feat5, fc1_w, fc1_b, fc2_w, fc2_b, fc3_w, fc3_b,
                           out + OFF_PREDCLS, cls);

    // operand prep: weights into fragment order; feat1 -> fp16
    wfrag_kernel<<<(147456 + 255) / 256, 256>>>(cb1_w, w1, 1152, 256, 128, 8, 72, 147456);
    wfrag_kernel<<<(294912 + 255) / 256, 256>>>(cb2_w, w2, 2304, 256, 128, 8, 144, 294912);
    wfrag_kernel<<<(27648 + 255) / 256, 256>>>(sc1_w, w3, 576, 96, 96, 6, 36, 27648);
    wfrag_kernel<<<(41472 + 255) / 256, 256>>>(sc2_w, w4, 864, 96, 96, 6, 54, 41472);
    fcvt16_kernel<<<(33554432 / 4 + 255) / 256, 256>>>(feat1, f1, 33554432);

    // crop + segmentation branch
    crop_kernel<<<256, 256>>>(feat0, boxes, cp);
    conv3x3_halo<64, 96, true, 3><<<dim3(2, 4, 256), 128, DYN>>>(
        cp, w3, sc1_b, nullptr, s1, 32, 32, 96, 1);
    conv3x3_halo<96, 96, true, 3><<<dim3(2, 4, 256), 128, DYN>>>(
        s1, w4, sc2_b, nullptr, s2, 32, 32, 96, 1);
    sosel_kernel<<<256, 256>>>(s2, so_w, so_b, cls, out);
    score_kernel<<<256, 256>>>(s2, sd1_w, sd1_b, sd2_w, sd2_b, sd3_w, sd3_b, cls, out);

    // regression branch
    conv3x3_halo<128, 128, true, 2><<<dim3(16, 32, 8), 128, DYN>>>(
        f1, w1, cb1_b, nullptr, x1, 256, 256, 256, 2);
    conv3x3_halo<256, 128, true, 2><<<dim3(16, 32, 8), 128, DYN>>>(
        x1, w2, cb2_b, nullptr, x2, 256, 256, 256, 2);
    regsel_kernel<<<dim3(16, 16, 4), 256>>>(x2, reg_w, reg_b, wt_w, wt_b, cls, out);
}

// round 15
// speedup vs baseline: 4.4463x; 1.0170x over previous
#include <cuda_runtime.h>
#include <cuda_fp16.h>
#include <math.h>
#include <stdint.h>

typedef unsigned long long u64;

// ---------------------------------------------------------------------------
// Output layout (tuple flattened in order)
// ---------------------------------------------------------------------------
#define OFF_OFFSETS 0
#define OFF_SIZES   524288
#define OFF_WEIGHTS 1048576
#define OFF_PREDCLS 1310720
#define OFF_SEG     1310732
#define OFF_SCORE   1572876

// Scratch (device globals; no allocation allowed)
__device__ __half g_f1[33554432];     // feat1 fp16
__device__ __half g_x1[67108864];     // conv1 out fp16
__device__ __half g_x2[67108864];     // conv2 out fp16
__device__ __half g_cp[16777216];     // crops fp16
__device__ __half g_s1[25165824];     // sc1 out fp16
__device__ __half g_s2[25165824];     // sc2 out fp16
// fragment-order fp16 weights (b32-packed)
__device__ __align__(16) __half g_w1[294912];
__device__ __align__(16) __half g_w2[589824];
__device__ __align__(16) __half g_w3[55296];
__device__ __align__(16) __half g_w4[82944];
__device__ int g_cls[4];

// ---------------------------------------------------------------------------
// PTX helpers (arch-generic sm_80+)
// ---------------------------------------------------------------------------
__device__ __forceinline__ uint32_t smem_u32(const void* p) {
    uint32_t a;
    asm("{ .reg .u64 t; cvta.to.shared.u64 t, %1; cvt.u32.u64 %0, t; }"
        : "=r"(a) : "l"(p));
    return a;
}
__device__ __forceinline__ void ldsm_x4(uint32_t* r, uint32_t a) {
    asm volatile("ldmatrix.sync.aligned.m8n8.x4.shared.b16 {%0,%1,%2,%3}, [%4];"
                 : "=r"(r[0]), "=r"(r[1]), "=r"(r[2]), "=r"(r[3]) : "r"(a));
}
__device__ __forceinline__ void mma_f16(float* d, const uint32_t* a, const uint32_t* b) {
    asm volatile("mma.sync.aligned.m16n8k16.row.col.f32.f16.f16.f32 "
                 "{%0,%1,%2,%3}, {%4,%5,%6,%7}, {%8,%9}, {%0,%1,%2,%3};"
                 : "+f"(d[0]), "+f"(d[1]), "+f"(d[2]), "+f"(d[3])
                 : "r"(a[0]), "r"(a[1]), "r"(a[2]), "r"(a[3]),
                   "r"(b[0]), "r"(b[1]));
}
__device__ __forceinline__ void cpa16(uint32_t dst, const void* src, bool ok) {
    int sz = ok ? 16 : 0;
    asm volatile("cp.async.cg.shared.global [%0], [%1], 16, %2;"
                 :: "r"(dst), "l"(src), "r"(sz) : "memory");
}
__device__ __forceinline__ void cp_commit() {
    asm volatile("cp.async.commit_group;" ::: "memory");
}
template <int N>
__device__ __forceinline__ void cp_wait() {
    asm volatile("cp.async.wait_group %0;" :: "n"(N) : "memory");
}

// ---------------------------------------------------------------------------
// Operand preparation kernels
// ---------------------------------------------------------------------------
__global__ void fcvt16_kernel(const float* __restrict__ src,
                              __half* __restrict__ o, int n) {
    int i = blockIdx.x * blockDim.x + threadIdx.x;
    if (i * 4 >= n) return;
    float4 v = *(const float4*)(src + i * 4);
    __half2 a = __halves2half2(__float2half_rn(v.x), __float2half_rn(v.y));
    __half2 b = __halves2half2(__float2half_rn(v.z), __float2half_rn(v.w));
    *(uint2*)(o + i * 4) = make_uint2(*(uint32_t*)&a, *(uint32_t*)&b);
}

// weights [K9][COUT] fp32 -> mma B-fragment order, b32-packed
__global__ void wfrag_kernel(const float* __restrict__ w,
                             uint32_t* __restrict__ o,
                             int K9, int COUT, int CT, int NF, int KH, int total) {
    int i = blockIdx.x * blockDim.x + threadIdx.x;
    if (i >= total) return;
    int r  = i & 1;
    int ni = (i >> 1) % NF;
    int l  = (i >> 1) / NF % 32;
    int nw = (i >> 1) / NF / 32 & 1;
    int kh = (i >> 1) / NF / 64 % KH;
    int nt = (i >> 1) / NF / 64 / KH;
    int k  = kh * 16 + r * 8 + (l & 3) * 2;
    int co = nt * CT + nw * (CT / 2) + ni * 8 + (l >> 2);
    __half2 v = __halves2half2(__float2half_rn(w[(size_t)k * COUT + co]),
                               __float2half_rn(w[(size_t)(k + 1) * COUT + co]));
    o[i] = *(uint32_t*)&v;
}

// ---------------------------------------------------------------------------
// FP16 tensor-core 3x3 SAME conv, HALO-TILED A staging, 3-stage cp.async
// pipeline. W fp16 fragment-order via direct LDG. (unchanged from R14)
// ---------------------------------------------------------------------------
#define HALO_SZ (180 * 80)   // 14400 B per buffer

template <int CIN, int COUT_TILE, bool OUT_HALF, int MAXB>
__global__ __launch_bounds__(128, MAXB)
void conv3x3_halo(const __half* __restrict__ in,
                  const uint32_t* __restrict__ wfrag,
                  const float* __restrict__ bias,
                  float* __restrict__ outf, __half* __restrict__ outh,
                  int H, int W, int COUT, int NT) {
    constexpr int CC = CIN / 32;
    constexpr int KH = 9 * CIN / 16;
    constexpr int NF = COUT_TILE / 16;
    extern __shared__ char sm[];
    const uint32_t sb = smem_u32(sm);
    __shared__ float sbias[COUT_TILE];

    int t = threadIdx.x, warp = t >> 5, lane = t & 31;
    int img = blockIdx.z / NT, ntile = blockIdx.z % NT;
    int cobase = ntile * COUT_TILE;
    int x0 = blockIdx.x * 16, y0 = blockIdx.y * 8;

    if (t < COUT_TILE) sbias[t] = bias[cobase + t];

    int wm = warp & 1, nw = warp >> 1;
    int nbase = nw * (COUT_TILE / 2);

    const uint32_t* wbase = wfrag
        + ((size_t)((ntile * KH) * 2 + nw) * 32 + lane) * (2 * NF);
    const size_t whstep = (size_t)128 * NF;

    float acc[4][NF][4];
    #pragma unroll
    for (int i = 0; i < 4; i++)
        #pragma unroll
        for (int j = 0; j < NF; j++)
            #pragma unroll
            for (int q = 0; q < 4; q++) acc[i][j][q] = 0.f;

    const __half* img0 = in + (size_t)img * H * W * CIN;

    auto issue = [&](int cc, int buf) {
        uint32_t AO = sb + buf * HALO_SZ;
        for (int p = t; p < 180; p += 128) {
            int hy = p / 18, hx = p % 18;
            int gy = y0 - 1 + hy, gx = x0 - 1 + hx;
            bool aok = (gy >= 0 && gy < H && gx >= 0 && gx < W);
            int cy = min(max(gy, 0), H - 1), cx = min(max(gx, 0), W - 1);
            const __half* src = img0 + ((size_t)cy * W + cx) * CIN + cc * 32;
            uint32_t dst = AO + (uint32_t)p * 80;
            #pragma unroll
            for (int j = 0; j < 4; j++)
                cpa16(dst + j * 16, src + j * 8, aok);
        }
        cp_commit();
    };

    issue(0, 0);
    if (CC > 1) issue(1, 1);

    for (int cc = 0; cc < CC; cc++) {
        if (cc + 1 < CC) cp_wait<1>();
        else             cp_wait<0>();
        __syncthreads();
        if (cc + 2 < CC) issue(cc + 2, (cc + 2) % 3);

        uint32_t AO = sb + (cc % 3) * HALO_SZ;

        for (int tap = 0; tap < 9; tap++) {
            int dy = tap / 3 - 1, dx = tap % 3 - 1;
            #pragma unroll
            for (int k16 = 0; k16 < 2; k16++) {
                int kh = tap * (CIN / 16) + cc * 2 + k16;
                const uint32_t* wp = wbase + (size_t)kh * whstep;
                uint32_t bh[NF][2];
                if constexpr (NF % 4 == 0) {
                    #pragma unroll
                    for (int j = 0; j < NF / 2; j++) {
                        uint4 v = ((const uint4*)wp)[j];
                        bh[2 * j][0] = v.x;     bh[2 * j][1] = v.y;
                        bh[2 * j + 1][0] = v.z; bh[2 * j + 1][1] = v.w;
                    }
                } else {
                    #pragma unroll
                    for (int j = 0; j < NF; j++) {
                        uint2 v = ((const uint2*)wp)[j];
                        bh[j][0] = v.x; bh[j][1] = v.y;
                    }
                }
                uint32_t ah[4][4];
                #pragma unroll
                for (int mi = 0; mi < 4; mi++) {
                    int p = wm * 64 + mi * 16 + (lane & 15);
                    int py = p >> 4, px = p & 15;
                    int hidx = (py + 1 + dy) * 18 + (px + 1 + dx);
                    uint32_t rowb = (uint32_t)(hidx * 80 + k16 * 32 + (lane >> 4) * 16);
                    ldsm_x4(ah[mi], AO + rowb);
                }
                #pragma unroll
                for (int mi = 0; mi < 4; mi++)
                    #pragma unroll
                    for (int ni = 0; ni < NF; ni++)
                        mma_f16(acc[mi][ni], ah[mi], bh[ni]);
            }
        }
    }

    #pragma unroll
    for (int mi = 0; mi < 4; mi++) {
        int p0 = wm * 64 + mi * 16 + (lane >> 2);
        #pragma unroll
        for (int half_ = 0; half_ < 2; half_++) {
            int p = p0 + half_ * 8;
            int gy = y0 + (p >> 4), gx = x0 + (p & 15);
            size_t pixoff = ((size_t)img * H * W + (size_t)gy * W + gx) * COUT + cobase;
            #pragma unroll
            for (int ni = 0; ni < NF; ni++) {
                int cl = nbase + ni * 8 + (lane & 3) * 2;
                float r0 = acc[mi][ni][half_ * 2 + 0] + sbias[cl];
                float r1 = acc[mi][ni][half_ * 2 + 1] + sbias[cl + 1];
                r0 = fmaxf(r0, 0.f); r1 = fmaxf(r1, 0.f);
                if (OUT_HALF) {
                    __half2 hh = __halves2half2(__float2half_rn(r0), __float2half_rn(r1));
                    *(uint32_t*)(outh + pixoff + cl) = *(uint32_t*)&hh;
                } else {
                    *(float2*)(outf + pixoff + cl) = make_float2(r0, r1);
                }
            }
        }
    }
}

// ---------------------------------------------------------------------------
// Classification head
// ---------------------------------------------------------------------------
__global__ void cls_kernel(const float* __restrict__ feat5,
                           const float* __restrict__ fc1_w, const float* __restrict__ fc1_b,
                           const float* __restrict__ fc2_w, const float* __restrict__ fc2_b,
                           const float* __restrict__ fc3_w, const float* __restrict__ fc3_b,
                           float* __restrict__ out_predcls, int* __restrict__ cls) {
    int b = blockIdx.x;
    int t = threadIdx.x;
    __shared__ float g0[256], g1[256], lg[3];
    const float* f = feat5 + (size_t)b * 16 * 16 * 256;
    float s = 0.f;
    #pragma unroll 4
    for (int p = 0; p < 256; p++) s += f[p * 256 + t];
    g0[t] = s * (1.0f / 256.0f);
    __syncthreads();
    float a = fc1_b[t];
    #pragma unroll 4
    for (int k = 0; k < 256; k++) a = fmaf(g0[k], fc1_w[k * 256 + t], a);
    g1[t] = fmaxf(a, 0.f);
    __syncthreads();
    a = fc2_b[t];
    #pragma unroll 4
    for (int k = 0; k < 256; k++) a = fmaf(g1[k], fc2_w[k * 256 + t], a);
    g0[t] = fmaxf(a, 0.f);
    __syncthreads();
    if (t < 3) {
        a = fc3_b[t];
        for (int k = 0; k < 256; k++) a = fmaf(g0[k], fc3_w[k * 3 + t], a);
        lg[t] = a;
    }
    __syncthreads();
    if (t == 0) {
        float m = fmaxf(lg[0], fmaxf(lg[1], lg[2]));
        float e0 = expf(lg[0] - m), e1 = expf(lg[1] - m), e2 = expf(lg[2] - m);
        float inv = 1.f / (e0 + e1 + e2);
        out_predcls[b * 3 + 0] = e0 * inv;
        out_predcls[b * 3 + 1] = e1 * inv;
        out_predcls[b * 3 + 2] = e2 * inv;
        int c = 0;
        if (lg[1] > lg[0]) c = 1;
        if (lg[2] > lg[c]) c = 2;
        cls[b] = c;
    }
}

// ---------------------------------------------------------------------------
// Fused reg/wt conv, halo-tiled smem staging of fp16 x2 (64-ch chunks).
// grid (16,16,4), block 256 (16x16 pixel tile). Dynamic smem: 324*72 halves.
// ---------------------------------------------------------------------------
#define REG_PITCH 72
#define REG_DSM   (324 * REG_PITCH * 2)   // 46656 B

__global__ __launch_bounds__(256)
void regsel_kernel(const __half* __restrict__ x,
                   const float* __restrict__ reg_w, const float* __restrict__ reg_b,
                   const float* __restrict__ wt_w,  const float* __restrict__ wt_b,
                   const int* __restrict__ cls, float* __restrict__ out) {
    int b = blockIdx.z;
    int c = cls[b];
    extern __shared__ __align__(16) char dsm[];
    __half* tile = (__half*)dsm;
    __shared__ __align__(16) float ws[9 * 256 * 5];
    int t = threadIdx.x;
    for (int i = t; i < 9 * 256; i += 256) {
        const float* rp = reg_w + (size_t)i * 12 + 4 * c;
        float* wp = ws + i * 5;
        wp[0] = rp[0]; wp[1] = rp[1]; wp[2] = rp[2]; wp[3] = rp[3];
        wp[4] = wt_w[(size_t)i * 3 + c];
    }
    int px = t & 15, py = t >> 4;
    int bx0 = blockIdx.x * 16, by0 = blockIdx.y * 16;
    float a0 = reg_b[4 * c], a1 = reg_b[4 * c + 1], a2 = reg_b[4 * c + 2],
          a3 = reg_b[4 * c + 3], a4 = wt_b[c];
    const __half* xi = x + (size_t)b * 256 * 256 * 256;

    for (int cc = 0; cc < 4; cc++) {
        __syncthreads();   // fences ws load (first iter) + previous chunk reads
        for (int p = t; p < 324; p += 256) {
            int hy = p / 18, hx = p % 18;
            int gy = by0 - 1 + hy, gx = bx0 - 1 + hx;
            bool ok = (gy >= 0 && gy < 256 && gx >= 0 && gx < 256);
            uint4 z = make_uint4(0, 0, 0, 0);
            const uint4* src = (const uint4*)(xi + ((size_t)gy * 256 + gx) * 256 + cc * 64);
            uint4* dst = (uint4*)(tile + p * REG_PITCH);
            #pragma unroll
            for (int j = 0; j < 8; j++) dst[j] = ok ? src[j] : z;
        }
        __syncthreads();
        #pragma unroll
        for (int tap = 0; tap < 9; tap++) {
            int dy = tap / 3 - 1, dx = tap % 3 - 1;
            const __half* ip = tile + ((py + 1 + dy) * 18 + (px + 1 + dx)) * REG_PITCH;
            const float* wp = ws + tap * 256 * 5 + cc * 64 * 5;
            for (int ci = 0; ci < 64; ci += 8) {
                uint4 hv = *(const uint4*)(ip + ci);
                float2 f0 = __half22float2(*(__half2*)&hv.x);
                float2 f1 = __half22float2(*(__half2*)&hv.y);
                float2 f2 = __half22float2(*(__half2*)&hv.z);
                float2 f3 = __half22float2(*(__half2*)&hv.w);
                float v[8] = {f0.x, f0.y, f1.x, f1.y, f2.x, f2.y, f3.x, f3.y};
                const float* wl = wp + ci * 5;
                #pragma unroll
                for (int q = 0; q < 8; q++) {
                    a0 = fmaf(v[q], wl[q * 5 + 0], a0);
                    a1 = fmaf(v[q], wl[q * 5 + 1], a1);
                    a2 = fmaf(v[q], wl[q * 5 + 2], a2);
                    a3 = fmaf(v[q], wl[q * 5 + 3], a3);
                    a4 = fmaf(v[q], wl[q * 5 + 4], a4);
                }
            }
        }
    }
    size_t pix = ((size_t)b * 256 + by0 + py) * 256 + bx0 + px;
    out[OFF_OFFSETS + pix * 2 + 0] = a0;
    out[OFF_OFFSETS + pix * 2 + 1] = a1;
    out[OFF_SIZES   + pix * 2 + 0] = a2;
    out[OFF_SIZES   + pix * 2 + 1] = a3;
    out[OFF_WEIGHTS + pix] = a4;
}

// ---------------------------------------------------------------------------
// Bilinear crop -> fp16
// ---------------------------------------------------------------------------
__global__ void crop_kernel(const float* __restrict__ feat0,
                            const float* __restrict__ boxes,
                            __half* __restrict__ cp) {
    int n = blockIdx.x;
    int b = n >> 6;
    const int H = 512, W = 512, C = 64;
    __shared__ int sy0[32], sx0[32];
    __shared__ float swy[32], swx[32];
    const float* bx = boxes + (size_t)n * 4;
    float y1 = bx[0], x1 = bx[1], y2 = bx[2], x2 = bx[3];
    int t = threadIdx.x;
    if (t < 32) {
        float tt = (float)t / 31.0f;
        float ys = y1 * (H - 1) + tt * (y2 - y1) * (H - 1);
        int yy0 = (int)floorf(ys);
        yy0 = min(max(yy0, 0), H - 2);
        sy0[t] = yy0; swy[t] = ys - (float)yy0;
    } else if (t < 64) {
        int i = t - 32;
        float tt = (float)i / 31.0f;
        float xs = x1 * (W - 1) + tt * (x2 - x1) * (W - 1);
        int xx0 = (int)floorf(xs);
        xx0 = min(max(xx0, 0), W - 2);
        sx0[i] = xx0; swx[i] = xs - (float)xx0;
    }
    __syncthreads();
    const float* f = feat0 + (size_t)b * H * W * C;
    size_t obase = (size_t)n * 32 * 32 * C;
    for (int idx = t; idx < 32 * 32 * C; idx += blockDim.x) {
        int c  = idx & 63;
        int ix = (idx >> 6) & 31;
        int iy = idx >> 11;
        int yy0 = sy0[iy], xx0 = sx0[ix];
        float wy = swy[iy], wx = swx[ix];
        const float* p00 = f + ((size_t)yy0 * W + xx0) * C + c;
        float v00 = p00[0], v01 = p00[C], v10 = p00[(size_t)W * C], v11 = p00[(size_t)W * C + C];
        float top = v00 * (1.f - wx) + v01 * wx;
        float bot = v10 * (1.f - wx) + v11 * wx;
        float v = top * (1.f - wy) + bot * wy;
        cp[obase + idx] = __float2half_rn(v);
    }
}

// ---------------------------------------------------------------------------
// so conv with class selection (1 channel; s2 is fp16)
// ---------------------------------------------------------------------------
__global__ void sosel_kernel(const __half* __restrict__ s2,
                             const float* __restrict__ so_w, const float* __restrict__ so_b,
                             const int* __restrict__ cls, float* __restrict__ out) {
    int n = blockIdx.x;
    int c = cls[n >> 6];
    __shared__ __align__(16) float ws[9 * 96];
    int t = threadIdx.x;
    for (int i = t; i < 864; i += 256) ws[i] = so_w[(size_t)i * 3 + c];
    __syncthreads();
    float bias = so_b[c];
    const __half* sp = s2 + (size_t)n * 32 * 32 * 96;
    for (int pix = t; pix < 1024; pix += 256) {
        int py = pix >> 5, px = pix & 31;
        float acc = bias;
        for (int tap = 0; tap < 9; tap++) {
            int yy = py + tap / 3 - 1, xx = px + tap % 3 - 1;
            if (yy < 0 || yy >= 32 || xx < 0 || xx >= 32) continue;
            const __half* ip = sp + ((size_t)yy * 32 + xx) * 96;
            const float* wp = ws + tap * 96;
            for (int ci = 0; ci < 96; ci += 8) {
                uint4 hv = *(const uint4*)(ip + ci);
                float2 f0 = __half22float2(*(__half2*)&hv.x);
                float2 f1 = __half22float2(*(__half2*)&hv.y);
                float2 f2 = __half22float2(*(__half2*)&hv.z);
                float2 f3 = __half22float2(*(__half2*)&hv.w);
                acc = fmaf(f0.x, wp[ci + 0], acc);
                acc = fmaf(f0.y, wp[ci + 1], acc);
                acc = fmaf(f1.x, wp[ci + 2], acc);
                acc = fmaf(f1.y, wp[ci + 3], acc);
                acc = fmaf(f2.x, wp[ci + 4], acc);
                acc = fmaf(f2.y, wp[ci + 5], acc);
                acc = fmaf(f3.x, wp[ci + 6], acc);
                acc = fmaf(f3.y, wp[ci + 7], acc);
            }
        }
        out[OFF_SEG + (size_t)n * 1024 + pix] = acc;
    }
}

// ---------------------------------------------------------------------------
// Score head: 4 crops per block (4x reuse of sd1_w). s2 is fp16.
// grid 64, block 256. Dynamic smem: pooled[4][6144] fp32 = 98304 B.
// ---------------------------------------------------------------------------
#define SCORE_DSM (4 * 6144 * 4)

__global__ __launch_bounds__(256)
void score_kernel(const __half* __restrict__ s2,
                  const float* __restrict__ sd1_w, const float* __restrict__ sd1_b,
                  const float* __restrict__ sd2_w, const float* __restrict__ sd2_b,
                  const float* __restrict__ sd3_w, const float* __restrict__ sd3_b,
                  const int* __restrict__ cls, float* __restrict__ out) {
    int n0 = blockIdx.x * 4;
    int t = threadIdx.x;
    extern __shared__ __align__(16) char dsm[];
    float* pooled = (float*)dsm;            // [4][6144]
    __shared__ float h1[4][256], h2[4][256];

    for (int o = t; o < 4 * 6144; o += 256) {
        int j  = o / 6144;
        int oo = o % 6144;
        int c  = oo % 96;
        int px = (oo / 96) & 7;
        int py = oo / 768;
        const __half* sp = s2 + (size_t)(n0 + j) * 32 * 32 * 96;
        float s = 0.f;
        #pragma unroll
        for (int i = 0; i < 4; i++)
            #pragma unroll
            for (int q = 0; q < 4; q++)
                s += __half2float(sp[(((size_t)(py * 4 + i)) * 32 + (px * 4 + q)) * 96 + c]);
        pooled[o] = s * (1.f / 16.f);
    }
    __syncthreads();
    {
        float a[4];
        #pragma unroll
        for (int j = 0; j < 4; j++) a[j] = sd1_b[t];
        for (int k = 0; k < 6144; k++) {
            float w = sd1_w[(size_t)k * 256 + t];
            #pragma unroll
            for (int j = 0; j < 4; j++) a[j] = fmaf(pooled[j * 6144 + k], w, a[j]);
        }
        #pragma unroll
        for (int j = 0; j < 4; j++) h1[j][t] = fmaxf(a[j], 0.f);
    }
    __syncthreads();
    {
        float a[4];
        #pragma unroll
        for (int j = 0; j < 4; j++) a[j] = sd2_b[t];
        for (int k = 0; k < 256; k++) {
            float w = sd2_w[k * 256 + t];
            #pragma unroll
            for (int j = 0; j < 4; j++) a[j] = fmaf(h1[j][k], w, a[j]);
        }
        #pragma unroll
        for (int j = 0; j < 4; j++) h2[j][t] = fmaxf(a[j], 0.f);
    }
    __syncthreads();
    if (t < 4) {
        int n = n0 + t;
        int c = cls[n >> 6];
        float acc = sd3_b[c];
        for (int k = 0; k < 256; k++) acc = fmaf(h2[t][k], sd3_w[k * 3 + c], acc);
        out[OFF_SCORE + n] = acc;
    }
}

// ---------------------------------------------------------------------------
extern "C" void kernel_launch(void* const* d_in, const int* in_sizes, int n_in,
                              void* d_out, int out_size) {
    (void)in_sizes; (void)n_in; (void)out_size;
    const float* feat0 = (const float*)d_in[0];
    const float* feat1 = (const float*)d_in[1];
    const float* feat5 = (const float*)d_in[2];
    const float* boxes = (const float*)d_in[3];
    const float* cb1_w = (const float*)d_in[4];
    const float* cb1_b = (const float*)d_in[5];
    const float* cb2_w = (const float*)d_in[6];
    const float* cb2_b = (const float*)d_in[7];
    const float* reg_w = (const float*)d_in[8];
    const float* reg_b = (const float*)d_in[9];
    const float* wt_w  = (const float*)d_in[10];
    const float* wt_b  = (const float*)d_in[11];
    const float* fc1_w = (const float*)d_in[12];
    const float* fc1_b = (const float*)d_in[13];
    const float* fc2_w = (const float*)d_in[14];
    const float* fc2_b = (const float*)d_in[15];
    const float* fc3_w = (const float*)d_in[16];
    const float* fc3_b = (const float*)d_in[17];
    const float* sc1_w = (const float*)d_in[18];
    const float* sc1_b = (const float*)d_in[19];
    const float* sc2_w = (const float*)d_in[20];
    const float* sc2_b = (const float*)d_in[21];
    const float* so_w  = (const float*)d_in[22];
    const float* so_b  = (const float*)d_in[23];
    const float* sd1_w = (const float*)d_in[24];
    const float* sd1_b = (const float*)d_in[25];
    const float* sd2_w = (const float*)d_in[26];
    const float* sd2_b = (const float*)d_in[27];
    const float* sd3_w = (const float*)d_in[28];
    const float* sd3_b = (const float*)d_in[29];
    float* out = (float*)d_out;

    // resolve device globals
    void* p;
    cudaGetSymbolAddress(&p, g_f1);  __half* f1 = (__half*)p;
    cudaGetSymbolAddress(&p, g_x1);  __half* x1 = (__half*)p;
    cudaGetSymbolAddress(&p, g_x2);  __half* x2 = (__half*)p;
    cudaGetSymbolAddress(&p, g_cp);  __half* cp = (__half*)p;
    cudaGetSymbolAddress(&p, g_s1);  __half* s1 = (__half*)p;
    cudaGetSymbolAddress(&p, g_s2);  __half* s2 = (__half*)p;
    cudaGetSymbolAddress(&p, g_w1);  uint32_t* w1 = (uint32_t*)p;
    cudaGetSymbolAddress(&p, g_w2);  uint32_t* w2 = (uint32_t*)p;
    cudaGetSymbolAddress(&p, g_w3);  uint32_t* w3 = (uint32_t*)p;
    cudaGetSymbolAddress(&p, g_w4);  uint32_t* w4 = (uint32_t*)p;
    cudaGetSymbolAddress(&p, g_cls); int* cls = (int*)p;

    constexpr int DYN = 3 * HALO_SZ;   // 43200 (halo A, triple-buffered)
    cudaFuncSetAttribute(conv3x3_halo<128, 128, true, 2>,
                         cudaFuncAttributeMaxDynamicSharedMemorySize, DYN);
    cudaFuncSetAttribute(conv3x3_halo<256, 128, true, 2>,
                         cudaFuncAttributeMaxDynamicSharedMemorySize, DYN);
    cudaFuncSetAttribute(conv3x3_halo<64, 96, true, 3>,
                         cudaFuncAttributeMaxDynamicSharedMemorySize, DYN);
    cudaFuncSetAttribute(conv3x3_halo<96, 96, true, 3>,
                         cudaFuncAttributeMaxDynamicSharedMemorySize, DYN);
    cudaFuncSetAttribute(regsel_kernel,
                         cudaFuncAttributeMaxDynamicSharedMemorySize, REG_DSM);
    cudaFuncSetAttribute(score_kernel,
                         cudaFuncAttributeMaxDynamicSharedMemorySize, SCORE_DSM);

    // classification first (selection depends on cls)
    cls_kernel<<<4, 256>>>(feat5, fc1_w, fc1_b, fc2_w, fc2_b, fc3_w, fc3_b,
                           out + OFF_PREDCLS, cls);

    // operand prep: weights into fragment order; feat1 -> fp16
    wfrag_kernel<<<(147456 + 255) / 256, 256>>>(cb1_w, w1, 1152, 256, 128, 8, 72, 147456);
    wfrag_kernel<<<(294912 + 255) / 256, 256>>>(cb2_w, w2, 2304, 256, 128, 8, 144, 294912);
    wfrag_kernel<<<(27648 + 255) / 256, 256>>>(sc1_w, w3, 576, 96, 96, 6, 36, 27648);
    wfrag_kernel<<<(41472 + 255) / 256, 256>>>(sc2_w, w4, 864, 96, 96, 6, 54, 41472);
    fcvt16_kernel<<<(33554432 / 4 + 255) / 256, 256>>>(feat1, f1, 33554432);

    // crop + segmentation branch
    crop_kernel<<<256, 256>>>(feat0, boxes, cp);
    conv3x3_halo<64, 96, true, 3><<<dim3(2, 4, 256), 128, DYN>>>(
        cp, w3, sc1_b, nullptr, s1, 32, 32, 96, 1);
    conv3x3_halo<96, 96, true, 3><<<dim3(2, 4, 256), 128, DYN>>>(
        s1, w4, sc2_b, nullptr, s2, 32, 32, 96, 1);
    sosel_kernel<<<256, 256>>>(s2, so_w, so_b, cls, out);
    score_kernel<<<64, 256, SCORE_DSM>>>(s2, sd1_w, sd1_b, sd2_w, sd2_b,
                                         sd3_w, sd3_b, cls, out);

    // regression branch
    conv3x3_halo<128, 128, true, 2><<<dim3(16, 32, 8), 128, DYN>>>(
        f1, w1, cb1_b, nullptr, x1, 256, 256, 256, 2);
    conv3x3_halo<256, 128, true, 2><<<dim3(16, 32, 8), 128, DYN>>>(
        x1, w2, cb2_b, nullptr, x2, 256, 256, 256, 2);
    regsel_kernel<<<dim3(16, 16, 4), 256, REG_DSM>>>(
        x2, reg_w, reg_b, wt_w, wt_b, cls, out);
}